// round 2
// baseline (speedup 1.0000x reference)
#include <cuda_runtime.h>

// Problem constants
#define BB   2
#define MM   2048
#define NN   2048
#define DMOD 1024
#define NH   16
#define DK   64

// Scratch (device globals: allocation-free rule)
__device__ float g_Qp[BB * MM * DMOD];
__device__ float g_Kp[BB * NN * DMOD];
__device__ float g_Vp[BB * NN * DMOD];
__device__ float g_ctx[BB * MM * DMOD];
__device__ unsigned char g_mask[BB * (size_t)MM * NN];
__device__ int g_mask_kind;   // 0=uint8, 1=int32, 2=float32

// ---------------------------------------------------------------------------
// Mask dtype detection: scan first 64K u32 words of the raw mask buffer.
// int32 0/1   -> every word in {0,1}
// float32 0/1 -> every word in {0, 0x3F800000}
// uint8 0/1   -> words are packed byte combos (e.g. 0x00010001) -> neither
// First 256KB is always in-bounds (min possible mask buffer = 8MB).
// ---------------------------------------------------------------------------
__global__ void detect_mask(const unsigned int* __restrict__ w) {
    __shared__ int s_not_int, s_not_float;
    if (threadIdx.x == 0) { s_not_int = 0; s_not_float = 0; }
    __syncthreads();
    int li = 0, lf = 0;
    for (int i = threadIdx.x; i < 65536; i += blockDim.x) {
        unsigned int x = w[i];
        if (x > 1u) li = 1;
        if (x != 0u && x != 0x3F800000u) lf = 1;
    }
    if (li) atomicOr(&s_not_int, 1);
    if (lf) atomicOr(&s_not_float, 1);
    __syncthreads();
    if (threadIdx.x == 0) {
        if (!s_not_int)        g_mask_kind = 1;
        else if (!s_not_float) g_mask_kind = 2;
        else                   g_mask_kind = 0;
    }
}

__global__ void convert_mask(const void* __restrict__ m) {
    size_t i = (size_t)blockIdx.x * blockDim.x + threadIdx.x;
    const size_t total = (size_t)BB * MM * NN;
    if (i >= total) return;
    int kind = g_mask_kind;
    unsigned char v;
    if (kind == 1)      v = (unsigned char)(((const int*)m)[i] != 0);
    else if (kind == 2) v = (unsigned char)(((const float*)m)[i] != 0.0f);
    else                v = ((const unsigned char*)m)[i] ? 1 : 0;
    g_mask[i] = v;
}

// ---------------------------------------------------------------------------
// proj64: out[r, n] = sum_k A[r,k] * W[n,k]    (A @ W^T)
// 64x64 output tile per CTA, BK=16, 256 threads, 4x4 micro-tile per thread.
// ---------------------------------------------------------------------------
__global__ void proj64(const float* __restrict__ A,
                       const float* __restrict__ W,
                       float* __restrict__ out) {
    __shared__ float At[16 * 68];
    __shared__ float Wt[16 * 68];

    const int t  = threadIdx.x;
    const int tx = t & 15;
    const int ty = t >> 4;
    const int m0 = blockIdx.y * 64;
    const int n0 = blockIdx.x * 64;

    const int lr = t >> 2;
    const int lk = (t & 3) * 4;

    float acc[4][4] = {};

    const float* Arow = A + (size_t)(m0 + lr) * DMOD + lk;
    const float* Wrow = W + (size_t)(n0 + lr) * DMOD + lk;

    for (int k0 = 0; k0 < DMOD; k0 += 16) {
        float4 av = *(const float4*)(Arow + k0);
        float4 wv = *(const float4*)(Wrow + k0);
        At[(lk + 0) * 68 + lr] = av.x;
        At[(lk + 1) * 68 + lr] = av.y;
        At[(lk + 2) * 68 + lr] = av.z;
        At[(lk + 3) * 68 + lr] = av.w;
        Wt[(lk + 0) * 68 + lr] = wv.x;
        Wt[(lk + 1) * 68 + lr] = wv.y;
        Wt[(lk + 2) * 68 + lr] = wv.z;
        Wt[(lk + 3) * 68 + lr] = wv.w;
        __syncthreads();

#pragma unroll
        for (int kk = 0; kk < 16; kk++) {
            float4 a4 = *(const float4*)&At[kk * 68 + ty * 4];
            float4 b4 = *(const float4*)&Wt[kk * 68 + tx * 4];
            float aa[4] = {a4.x, a4.y, a4.z, a4.w};
            float bb[4] = {b4.x, b4.y, b4.z, b4.w};
#pragma unroll
            for (int i = 0; i < 4; i++)
#pragma unroll
                for (int j = 0; j < 4; j++)
                    acc[i][j] += aa[i] * bb[j];
        }
        __syncthreads();
    }

#pragma unroll
    for (int i = 0; i < 4; i++) {
        float4 o = make_float4(acc[i][0], acc[i][1], acc[i][2], acc[i][3]);
        *(float4*)&out[(size_t)(m0 + ty * 4 + i) * DMOD + n0 + tx * 4] = o;
    }
}

// ---------------------------------------------------------------------------
// Fused attention (flash style), fp32.
// grid: (M/64, B*H). Each CTA: 64 query rows of one (b,h).
// Mask applied BEFORE the 1/sqrt(dk) scaling, matching the reference.
// ---------------------------------------------------------------------------
#define ATTN_SMEM ((4 * 64 * 68 + 3 * 64) * 4 + 64 * 64)   // 74496 bytes

__global__ void attn_kernel(const float* __restrict__ Qp,
                            const float* __restrict__ Kp,
                            const float* __restrict__ Vp,
                            const unsigned char* __restrict__ mask,
                            float* __restrict__ ctx) {
    extern __shared__ float sm[];
    float* Qt = sm;                       // [d][m]  64x68
    float* Kt = Qt + 64 * 68;             // [d][n]  64x68
    float* Vs = Kt + 64 * 68;             // [n][d]  64x68
    float* Ps = Vs + 64 * 68;             // [n][m]  64x68
    float* rowmax = Ps + 64 * 68;
    float* rowsum = rowmax + 64;
    float* corr   = rowsum + 64;
    unsigned char* msk = (unsigned char*)(corr + 64);   // 64x64 bytes

    const int t  = threadIdx.x;
    const int tx = t & 15;
    const int ty = t >> 4;
    const int bh = blockIdx.y;
    const int b = bh >> 4;
    const int h = bh & 15;
    const int m0 = blockIdx.x * 64;

    const int lr = t >> 2;
    const int lq = t & 3;

    {
        const float* qbase = Qp + ((size_t)(b * MM + m0 + lr)) * DMOD + h * DK;
#pragma unroll
        for (int it = 0; it < 4; it++) {
            int d0 = lq * 4 + it * 16;
            float4 v = *(const float4*)(qbase + d0);
            Qt[(d0 + 0) * 68 + lr] = v.x;
            Qt[(d0 + 1) * 68 + lr] = v.y;
            Qt[(d0 + 2) * 68 + lr] = v.z;
            Qt[(d0 + 3) * 68 + lr] = v.w;
        }
    }
    if (t < 64) { rowmax[t] = -1e30f; rowsum[t] = 0.0f; }

    float O[4][4] = {};

    for (int nt = 0; nt < NN / 64; nt++) {
        const int n0 = nt * 64;
        __syncthreads();

        {
            const float* kbase = Kp + ((size_t)(b * NN + n0 + lr)) * DMOD + h * DK;
            const float* vbase = Vp + ((size_t)(b * NN + n0 + lr)) * DMOD + h * DK;
#pragma unroll
            for (int it = 0; it < 4; it++) {
                int d0 = lq * 4 + it * 16;
                float4 kv = *(const float4*)(kbase + d0);
                Kt[(d0 + 0) * 68 + lr] = kv.x;
                Kt[(d0 + 1) * 68 + lr] = kv.y;
                Kt[(d0 + 2) * 68 + lr] = kv.z;
                Kt[(d0 + 3) * 68 + lr] = kv.w;
                float4 vv = *(const float4*)(vbase + d0);
                *(float4*)&Vs[lr * 68 + d0] = vv;
            }
            uint4 mv = *(const uint4*)(mask + ((size_t)(b * MM + m0 + lr)) * NN + n0 + lq * 16);
            *(uint4*)&msk[lr * 64 + lq * 16] = mv;
        }
        __syncthreads();

        // S = Q K^T
        float s[4][4] = {};
#pragma unroll 8
        for (int d = 0; d < 64; d++) {
            float4 qa = *(const float4*)&Qt[d * 68 + ty * 4];
            float4 kb = *(const float4*)&Kt[d * 68 + tx * 4];
            float aa[4] = {qa.x, qa.y, qa.z, qa.w};
            float bb[4] = {kb.x, kb.y, kb.z, kb.w};
#pragma unroll
            for (int i = 0; i < 4; i++)
#pragma unroll
                for (int j = 0; j < 4; j++)
                    s[i][j] += aa[i] * bb[j];
        }

#pragma unroll
        for (int i = 0; i < 4; i++)
#pragma unroll
            for (int j = 0; j < 4; j++) {
                float v = msk[(ty * 4 + i) * 64 + tx * 4 + j] ? -1e9f : s[i][j];
                Ps[(tx * 4 + j) * 68 + (ty * 4 + i)] = v * 0.125f;
            }
        __syncthreads();

        if (t < 64) {
            const int mr = t;
            float mxold = rowmax[mr];
            float tm = -1e30f;
#pragma unroll 8
            for (int n = 0; n < 64; n++) tm = fmaxf(tm, Ps[n * 68 + mr]);
            float nm = fmaxf(mxold, tm);
            float c = __expf(mxold - nm);
            float ps = 0.0f;
#pragma unroll 8
            for (int n = 0; n < 64; n++) {
                float p = __expf(Ps[n * 68 + mr] - nm);
                Ps[n * 68 + mr] = p;
                ps += p;
            }
            rowsum[mr] = rowsum[mr] * c + ps;
            rowmax[mr] = nm;
            corr[mr]   = c;
        }
        __syncthreads();

        float cr[4];
#pragma unroll
        for (int i = 0; i < 4; i++) cr[i] = corr[ty * 4 + i];
#pragma unroll
        for (int i = 0; i < 4; i++)
#pragma unroll
            for (int j = 0; j < 4; j++) O[i][j] *= cr[i];

#pragma unroll 8
        for (int n = 0; n < 64; n++) {
            float4 p4 = *(const float4*)&Ps[n * 68 + ty * 4];
            float4 v4 = *(const float4*)&Vs[n * 68 + tx * 4];
            float pp[4] = {p4.x, p4.y, p4.z, p4.w};
            float vv[4] = {v4.x, v4.y, v4.z, v4.w};
#pragma unroll
            for (int i = 0; i < 4; i++)
#pragma unroll
                for (int j = 0; j < 4; j++)
                    O[i][j] += pp[i] * vv[j];
        }
    }
    __syncthreads();

#pragma unroll
    for (int i = 0; i < 4; i++) {
        float inv = 1.0f / rowsum[ty * 4 + i];
        float4 o = make_float4(O[i][0] * inv, O[i][1] * inv, O[i][2] * inv, O[i][3] * inv);
        *(float4*)&ctx[((size_t)(b * MM + m0 + ty * 4 + i)) * DMOD + h * DK + tx * 4] = o;
    }
}

// ---------------------------------------------------------------------------
extern "C" void kernel_launch(void* const* d_in, const int* in_sizes, int n_in,
                              void* d_out, int out_size) {
    const float* q  = (const float*)d_in[0];
    const float* k  = (const float*)d_in[1];
    const float* v  = (const float*)d_in[2];
    const void*  mask_raw = d_in[3];
    const float* Wq = (const float*)d_in[4];
    const float* Wk = (const float*)d_in[5];
    const float* Wv = (const float*)d_in[6];
    const float* Wo = (const float*)d_in[7];
    float* out = (float*)d_out;

    void *Qp_, *Kp_, *Vp_, *ctx_, *mask_;
    cudaGetSymbolAddress(&Qp_,  g_Qp);
    cudaGetSymbolAddress(&Kp_,  g_Kp);
    cudaGetSymbolAddress(&Vp_,  g_Vp);
    cudaGetSymbolAddress(&ctx_, g_ctx);
    cudaGetSymbolAddress(&mask_, g_mask);
    float* Qp  = (float*)Qp_;
    float* Kp  = (float*)Kp_;
    float* Vp  = (float*)Vp_;
    float* ctx = (float*)ctx_;
    unsigned char* mask = (unsigned char*)mask_;

    cudaFuncSetAttribute(attn_kernel,
                         cudaFuncAttributeMaxDynamicSharedMemorySize, ATTN_SMEM);

    // Normalize mask dtype -> uint8
    detect_mask<<<1, 1024>>>((const unsigned int*)mask_raw);
    const size_t mtotal = (size_t)BB * MM * NN;
    convert_mask<<<(unsigned)((mtotal + 511) / 512), 512>>>(mask_raw);

    dim3 gridP(DMOD / 64, (BB * MM) / 64);
    proj64<<<gridP, 256>>>(q, Wq, Qp);
    proj64<<<gridP, 256>>>(k, Wk, Kp);
    proj64<<<gridP, 256>>>(v, Wv, Vp);

    dim3 gridA(MM / 64, BB * NH);
    attn_kernel<<<gridA, 256, ATTN_SMEM>>>(Qp, Kp, Vp, mask, ctx);

    proj64<<<gridP, 256>>>(ctx, Wo, out);
}

// round 6
// speedup vs baseline: 1.9146x; 1.9146x over previous
#include <cuda_runtime.h>
#include <cuda_bf16.h>
#include <cstdint>

// Problem constants
#define BB   2
#define MM   2048
#define NN   2048
#define DMOD 1024
#define NH   16
#define DK   64

#define KSPLIT (3 * DMOD)          // 3072: [hi|hi|lo] x [hi|lo|hi]

// Scratch (device globals: allocation-free rule)
__device__ float g_Qp[BB * MM * DMOD];
__device__ float g_Kp[BB * NN * DMOD];
__device__ float g_Vp[BB * NN * DMOD];
__device__ float g_ctx[BB * MM * DMOD];
__device__ unsigned char g_mask[BB * (size_t)MM * NN];
__device__ int g_mask_kind;
__device__ __nv_bfloat16 g_A3[(size_t)(BB * MM) * KSPLIT];   // 25 MB
__device__ __nv_bfloat16 g_W3[(size_t)DMOD * KSPLIT];        // 6.3 MB

// ---------------------------------------------------------------------------
// Helpers (sm_80-era only: mma.sync + ldmatrix; NO tcgen05 — harness PTX
// targets base sm_103 which rejects 'a' features)
// ---------------------------------------------------------------------------
__device__ __forceinline__ uint32_t cvta_s(const void* p) {
    uint32_t a;
    asm("{ .reg .u64 t; cvta.to.shared.u64 t, %1; cvt.u32.u64 %0, t; }"
        : "=r"(a) : "l"(p));
    return a;
}

#define LDSM_X4(r0, r1, r2, r3, a)                                            \
    asm volatile("ldmatrix.sync.aligned.m8n8.x4.shared.b16 {%0,%1,%2,%3}, [%4];" \
                 : "=r"(r0), "=r"(r1), "=r"(r2), "=r"(r3) : "r"(a))

#define MMA_BF16(c0, c1, c2, c3, a0, a1, a2, a3, b0, b1)                      \
    asm volatile("mma.sync.aligned.m16n8k16.row.col.f32.bf16.bf16.f32 "       \
                 "{%0,%1,%2,%3}, {%4,%5,%6,%7}, {%8,%9}, {%0,%1,%2,%3};"      \
                 : "+f"(c0), "+f"(c1), "+f"(c2), "+f"(c3)                     \
                 : "r"(a0), "r"(a1), "r"(a2), "r"(a3), "r"(b0), "r"(b1))

// ---------------------------------------------------------------------------
// Mask dtype detection + conversion (known-good from R2)
// ---------------------------------------------------------------------------
__global__ void detect_mask(const unsigned int* __restrict__ w) {
    __shared__ int s_not_int, s_not_float;
    if (threadIdx.x == 0) { s_not_int = 0; s_not_float = 0; }
    __syncthreads();
    int li = 0, lf = 0;
    for (int i = threadIdx.x; i < 65536; i += blockDim.x) {
        unsigned int x = w[i];
        if (x > 1u) li = 1;
        if (x != 0u && x != 0x3F800000u) lf = 1;
    }
    if (li) atomicOr(&s_not_int, 1);
    if (lf) atomicOr(&s_not_float, 1);
    __syncthreads();
    if (threadIdx.x == 0) {
        if (!s_not_int)        g_mask_kind = 1;
        else if (!s_not_float) g_mask_kind = 2;
        else                   g_mask_kind = 0;
    }
}

__global__ void convert_mask(const void* __restrict__ m) {
    size_t i = (size_t)blockIdx.x * blockDim.x + threadIdx.x;
    const size_t total = (size_t)BB * MM * NN;
    if (i >= total) return;
    int kind = g_mask_kind;
    unsigned char v;
    if (kind == 1)      v = (unsigned char)(((const int*)m)[i] != 0);
    else if (kind == 2) v = (unsigned char)(((const float*)m)[i] != 0.0f);
    else                v = ((const unsigned char*)m)[i] ? 1 : 0;
    g_mask[i] = v;
}

// ---------------------------------------------------------------------------
// Split fp32 -> bf16 triples
// ---------------------------------------------------------------------------
__global__ void split_act(const float* __restrict__ X, __nv_bfloat16* __restrict__ O) {
    size_t i = (size_t)blockIdx.x * blockDim.x + threadIdx.x;
    if (i >= (size_t)(BB * MM) * DMOD) return;
    int r = (int)(i >> 10);
    int c = (int)(i & 1023);
    float x = X[i];
    __nv_bfloat16 hi = __float2bfloat16(x);
    __nv_bfloat16 lo = __float2bfloat16(x - __bfloat162float(hi));
    size_t base = (size_t)r * KSPLIT;
    O[base + c] = hi;
    O[base + DMOD + c] = hi;
    O[base + 2 * DMOD + c] = lo;
}

__global__ void split_wgt(const float* __restrict__ W, __nv_bfloat16* __restrict__ O) {
    size_t i = (size_t)blockIdx.x * blockDim.x + threadIdx.x;
    if (i >= (size_t)DMOD * DMOD) return;
    int r = (int)(i >> 10);
    int c = (int)(i & 1023);
    float x = W[i];
    __nv_bfloat16 hi = __float2bfloat16(x);
    __nv_bfloat16 lo = __float2bfloat16(x - __bfloat162float(hi));
    size_t base = (size_t)r * KSPLIT;
    O[base + c] = hi;
    O[base + DMOD + c] = lo;
    O[base + 2 * DMOD + c] = hi;
}

// ---------------------------------------------------------------------------
// HMMA bf16 GEMM: C[m,n] = sum_k A3[m,k] * W3[n,k], K = 3072 (split-bf16)
// CTA 128x128, 128 threads, 4 warps of 64x64. mma.sync m16n8k16.
// Smem: double-buffered 128x32 bf16 tiles, row stride 40 (80B) + 16B-slot
// XOR swizzle keyed by (row>>3)&3 -> conflict-free STS.128 and ldmatrix.
// ---------------------------------------------------------------------------
#define SROWB 80       // smem row stride in bytes (40 bf16)

__global__ void __launch_bounds__(128, 2) gemm_hmma(
        const uint4* __restrict__ A3,   // [4096][384] uint4 (3072 bf16/row)
        const uint4* __restrict__ B3,   // [1024][384]
        float* __restrict__ C) {        // [4096][1024]
    __shared__ __align__(16) char As[2][128 * SROWB];
    __shared__ __align__(16) char Bs[2][128 * SROWB];

    const int t = threadIdx.x;
    const int lane = t & 31, wid = t >> 5;
    const int m0 = blockIdx.y * 128, n0 = blockIdx.x * 128;
    const int wm = (wid & 1) * 64, wn = (wid >> 1) * 64;
    const int g = lane >> 2, tq = lane & 3;

    const uint4* arow = A3 + (size_t)(m0 + t) * 384;
    const uint4* brow = B3 + (size_t)(n0 + t) * 384;
    const int swz = (t >> 3) & 3;

    // prologue: chunk 0 -> smem buf 0
    uint4 pa[4], pb[4];
#pragma unroll
    for (int j = 0; j < 4; j++) { pa[j] = arow[j]; pb[j] = brow[j]; }
#pragma unroll
    for (int j = 0; j < 4; j++) {
        *(uint4*)(As[0] + t * SROWB + ((j ^ swz) << 4)) = pa[j];
        *(uint4*)(Bs[0] + t * SROWB + ((j ^ swz) << 4)) = pb[j];
    }
    __syncthreads();

    float c[4][8][4];
#pragma unroll
    for (int i = 0; i < 4; i++)
#pragma unroll
        for (int j = 0; j < 8; j++)
#pragma unroll
            for (int q = 0; q < 4; q++) c[i][j][q] = 0.f;

    const int jj = lane >> 3;      // which 8x8 matrix this lane addresses
    const int r8 = lane & 7;

    for (int kc = 0; kc < 96; kc++) {
        const int buf = kc & 1;
        if (kc < 95) {
#pragma unroll
            for (int j = 0; j < 4; j++) {
                pa[j] = arow[(kc + 1) * 4 + j];
                pb[j] = brow[(kc + 1) * 4 + j];
            }
        }
        const char* Ab = As[buf];
        const char* Bb = Bs[buf];
#pragma unroll
        for (int ks = 0; ks < 2; ks++) {
            const int ku = ks * 2;             // 16 bf16 = 2 x 16B units
            uint32_t a[4][4], b[8][2];
#pragma unroll
            for (int mt = 0; mt < 4; mt++) {
                int r = wm + mt * 16 + ((jj & 1) << 3) + r8;
                int u = (ku + (jj >> 1)) ^ ((r >> 3) & 3);
                uint32_t ad = cvta_s(Ab + r * SROWB + (u << 4));
                LDSM_X4(a[mt][0], a[mt][1], a[mt][2], a[mt][3], ad);
            }
#pragma unroll
            for (int np = 0; np < 4; np++) {
                int r = wn + np * 16 + ((jj >> 1) << 3) + r8;
                int u = (ku + (jj & 1)) ^ ((r >> 3) & 3);
                uint32_t ad = cvta_s(Bb + r * SROWB + (u << 4));
                LDSM_X4(b[np * 2][0], b[np * 2][1], b[np * 2 + 1][0], b[np * 2 + 1][1], ad);
            }
#pragma unroll
            for (int mt = 0; mt < 4; mt++)
#pragma unroll
                for (int nt = 0; nt < 8; nt++)
                    MMA_BF16(c[mt][nt][0], c[mt][nt][1], c[mt][nt][2], c[mt][nt][3],
                             a[mt][0], a[mt][1], a[mt][2], a[mt][3],
                             b[nt][0], b[nt][1]);
        }
        __syncthreads();
        if (kc < 95) {
#pragma unroll
            for (int j = 0; j < 4; j++) {
                *(uint4*)(As[buf ^ 1] + t * SROWB + ((j ^ swz) << 4)) = pa[j];
                *(uint4*)(Bs[buf ^ 1] + t * SROWB + ((j ^ swz) << 4)) = pb[j];
            }
        }
        __syncthreads();
    }

    // epilogue
#pragma unroll
    for (int mt = 0; mt < 4; mt++) {
        int row = m0 + wm + mt * 16 + g;
#pragma unroll
        for (int nt = 0; nt < 8; nt++) {
            int col = n0 + wn + nt * 8 + tq * 2;
            *(float2*)&C[(size_t)row * DMOD + col] =
                make_float2(c[mt][nt][0], c[mt][nt][1]);
            *(float2*)&C[(size_t)(row + 8) * DMOD + col] =
                make_float2(c[mt][nt][2], c[mt][nt][3]);
        }
    }
}

// ---------------------------------------------------------------------------
// Fused attention (flash style), fp32 — byte-identical logic to R2 (passing)
// ---------------------------------------------------------------------------
#define ATTN_SMEM ((4 * 64 * 68 + 3 * 64) * 4 + 64 * 64)   // 74496 bytes

__global__ void attn_kernel(const float* __restrict__ Qp,
                            const float* __restrict__ Kp,
                            const float* __restrict__ Vp,
                            const unsigned char* __restrict__ mask,
                            float* __restrict__ ctx) {
    extern __shared__ float sm[];
    float* Qt = sm;
    float* Kt = Qt + 64 * 68;
    float* Vs = Kt + 64 * 68;
    float* Ps = Vs + 64 * 68;
    float* rowmax = Ps + 64 * 68;
    float* rowsum = rowmax + 64;
    float* corr   = rowsum + 64;
    unsigned char* msk = (unsigned char*)(corr + 64);

    const int t  = threadIdx.x;
    const int tx = t & 15;
    const int ty = t >> 4;
    const int bh = blockIdx.y;
    const int b = bh >> 4;
    const int h = bh & 15;
    const int m0 = blockIdx.x * 64;

    const int lr = t >> 2;
    const int lq = t & 3;

    {
        const float* qbase = Qp + ((size_t)(b * MM + m0 + lr)) * DMOD + h * DK;
#pragma unroll
        for (int it = 0; it < 4; it++) {
            int d0 = lq * 4 + it * 16;
            float4 v = *(const float4*)(qbase + d0);
            Qt[(d0 + 0) * 68 + lr] = v.x;
            Qt[(d0 + 1) * 68 + lr] = v.y;
            Qt[(d0 + 2) * 68 + lr] = v.z;
            Qt[(d0 + 3) * 68 + lr] = v.w;
        }
    }
    if (t < 64) { rowmax[t] = -1e30f; rowsum[t] = 0.0f; }

    float O[4][4] = {};

    for (int nt = 0; nt < NN / 64; nt++) {
        const int n0 = nt * 64;
        __syncthreads();

        {
            const float* kbase = Kp + ((size_t)(b * NN + n0 + lr)) * DMOD + h * DK;
            const float* vbase = Vp + ((size_t)(b * NN + n0 + lr)) * DMOD + h * DK;
#pragma unroll
            for (int it = 0; it < 4; it++) {
                int d0 = lq * 4 + it * 16;
                float4 kv = *(const float4*)(kbase + d0);
                Kt[(d0 + 0) * 68 + lr] = kv.x;
                Kt[(d0 + 1) * 68 + lr] = kv.y;
                Kt[(d0 + 2) * 68 + lr] = kv.z;
                Kt[(d0 + 3) * 68 + lr] = kv.w;
                float4 vv = *(const float4*)(vbase + d0);
                *(float4*)&Vs[lr * 68 + d0] = vv;
            }
            uint4 mv = *(const uint4*)(mask + ((size_t)(b * MM + m0 + lr)) * NN + n0 + lq * 16);
            *(uint4*)&msk[lr * 64 + lq * 16] = mv;
        }
        __syncthreads();

        float s[4][4] = {};
#pragma unroll 8
        for (int d = 0; d < 64; d++) {
            float4 qa = *(const float4*)&Qt[d * 68 + ty * 4];
            float4 kb = *(const float4*)&Kt[d * 68 + tx * 4];
            float aa[4] = {qa.x, qa.y, qa.z, qa.w};
            float bb[4] = {kb.x, kb.y, kb.z, kb.w};
#pragma unroll
            for (int i = 0; i < 4; i++)
#pragma unroll
                for (int j = 0; j < 4; j++)
                    s[i][j] += aa[i] * bb[j];
        }

#pragma unroll
        for (int i = 0; i < 4; i++)
#pragma unroll
            for (int j = 0; j < 4; j++) {
                float v = msk[(ty * 4 + i) * 64 + tx * 4 + j] ? -1e9f : s[i][j];
                Ps[(tx * 4 + j) * 68 + (ty * 4 + i)] = v * 0.125f;
            }
        __syncthreads();

        if (t < 64) {
            const int mr = t;
            float mxold = rowmax[mr];
            float tm = -1e30f;
#pragma unroll 8
            for (int n = 0; n < 64; n++) tm = fmaxf(tm, Ps[n * 68 + mr]);
            float nm = fmaxf(mxold, tm);
            float cc = __expf(mxold - nm);
            float ps = 0.0f;
#pragma unroll 8
            for (int n = 0; n < 64; n++) {
                float p = __expf(Ps[n * 68 + mr] - nm);
                Ps[n * 68 + mr] = p;
                ps += p;
            }
            rowsum[mr] = rowsum[mr] * cc + ps;
            rowmax[mr] = nm;
            corr[mr]   = cc;
        }
        __syncthreads();

        float cr[4];
#pragma unroll
        for (int i = 0; i < 4; i++) cr[i] = corr[ty * 4 + i];
#pragma unroll
        for (int i = 0; i < 4; i++)
#pragma unroll
            for (int j = 0; j < 4; j++) O[i][j] *= cr[i];

#pragma unroll 8
        for (int n = 0; n < 64; n++) {
            float4 p4 = *(const float4*)&Ps[n * 68 + ty * 4];
            float4 v4 = *(const float4*)&Vs[n * 68 + tx * 4];
            float pp[4] = {p4.x, p4.y, p4.z, p4.w};
            float vv[4] = {v4.x, v4.y, v4.z, v4.w};
#pragma unroll
            for (int i = 0; i < 4; i++)
#pragma unroll
                for (int j = 0; j < 4; j++)
                    O[i][j] += pp[i] * vv[j];
        }
    }
    __syncthreads();

#pragma unroll
    for (int i = 0; i < 4; i++) {
        float inv = 1.0f / rowsum[ty * 4 + i];
        float4 o = make_float4(O[i][0] * inv, O[i][1] * inv, O[i][2] * inv, O[i][3] * inv);
        *(float4*)&ctx[((size_t)(b * MM + m0 + ty * 4 + i)) * DMOD + h * DK + tx * 4] = o;
    }
}

// ---------------------------------------------------------------------------
extern "C" void kernel_launch(void* const* d_in, const int* in_sizes, int n_in,
                              void* d_out, int out_size) {
    const float* q  = (const float*)d_in[0];
    const float* k  = (const float*)d_in[1];
    const float* v  = (const float*)d_in[2];
    const void*  mask_raw = d_in[3];
    const float* Wq = (const float*)d_in[4];
    const float* Wk = (const float*)d_in[5];
    const float* Wv = (const float*)d_in[6];
    const float* Wo = (const float*)d_in[7];
    float* out = (float*)d_out;

    void *Qp_, *Kp_, *Vp_, *ctx_, *mask_, *A3_, *W3_;
    cudaGetSymbolAddress(&Qp_,  g_Qp);
    cudaGetSymbolAddress(&Kp_,  g_Kp);
    cudaGetSymbolAddress(&Vp_,  g_Vp);
    cudaGetSymbolAddress(&ctx_, g_ctx);
    cudaGetSymbolAddress(&mask_, g_mask);
    cudaGetSymbolAddress(&A3_,  g_A3);
    cudaGetSymbolAddress(&W3_,  g_W3);
    float* Qp  = (float*)Qp_;
    float* Kp  = (float*)Kp_;
    float* Vp  = (float*)Vp_;
    float* ctx = (float*)ctx_;
    unsigned char* mask = (unsigned char*)mask_;
    __nv_bfloat16* A3 = (__nv_bfloat16*)A3_;
    __nv_bfloat16* W3 = (__nv_bfloat16*)W3_;

    cudaFuncSetAttribute(attn_kernel,
                         cudaFuncAttributeMaxDynamicSharedMemorySize, ATTN_SMEM);

    // Normalize mask dtype -> uint8
    detect_mask<<<1, 1024>>>((const unsigned int*)mask_raw);
    const size_t mtotal = (size_t)BB * MM * NN;
    convert_mask<<<(unsigned)((mtotal + 511) / 512), 512>>>(mask_raw);

    const size_t act_elems = (size_t)(BB * MM) * DMOD;
    const size_t wgt_elems = (size_t)DMOD * DMOD;
    const unsigned actg = (unsigned)((act_elems + 255) / 256);
    const unsigned wgtg = (unsigned)((wgt_elems + 255) / 256);
    dim3 gridG(DMOD / 128, (BB * MM) / 128);             // (8, 32)

    split_act<<<actg, 256>>>(q, A3);
    split_wgt<<<wgtg, 256>>>(Wq, W3);
    gemm_hmma<<<gridG, 128>>>((const uint4*)A3, (const uint4*)W3, Qp);

    split_act<<<actg, 256>>>(k, A3);
    split_wgt<<<wgtg, 256>>>(Wk, W3);
    gemm_hmma<<<gridG, 128>>>((const uint4*)A3, (const uint4*)W3, Kp);

    split_act<<<actg, 256>>>(v, A3);
    split_wgt<<<wgtg, 256>>>(Wv, W3);
    gemm_hmma<<<gridG, 128>>>((const uint4*)A3, (const uint4*)W3, Vp);

    dim3 gridA(MM / 64, BB * NH);
    attn_kernel<<<gridA, 256, ATTN_SMEM>>>(Qp, Kp, Vp, mask, ctx);

    split_act<<<actg, 256>>>(ctx, A3);
    split_wgt<<<wgtg, 256>>>(Wo, W3);
    gemm_hmma<<<gridG, 128>>>((const uint4*)A3, (const uint4*)W3, out);
}

// round 9
// speedup vs baseline: 2.8701x; 1.4990x over previous
#include <cuda_runtime.h>
#include <cuda_bf16.h>
#include <cstdint>

// Problem constants
#define BB   2
#define MM   2048
#define NN   2048
#define DMOD 1024
#define NH   16
#define DK   64

#define KSPLIT (3 * DMOD)          // 3072: [hi|hi|lo] x [hi|lo|hi]

// Scratch (device globals: allocation-free rule)
__device__ float g_Qp[BB * MM * DMOD];
__device__ float g_Kp[BB * NN * DMOD];
__device__ float g_Vp[BB * NN * DMOD];
__device__ float g_ctx[BB * MM * DMOD];
__device__ unsigned char g_mask[BB * (size_t)MM * NN];
__device__ int g_mask_kind;
__device__ __nv_bfloat16 g_A3[(size_t)(BB * MM) * KSPLIT];   // 25 MB
__device__ __nv_bfloat16 g_W3[(size_t)DMOD * KSPLIT];        // 6.3 MB

// ---------------------------------------------------------------------------
// Helpers (sm_80-era: mma.sync + ldmatrix; NO tcgen05 — harness PTX targets
// base sm_103 which rejects 'a' features)
// ---------------------------------------------------------------------------
__device__ __forceinline__ uint32_t cvta_s(const void* p) {
    uint32_t a;
    asm("{ .reg .u64 t; cvta.to.shared.u64 t, %1; cvt.u32.u64 %0, t; }"
        : "=r"(a) : "l"(p));
    return a;
}

#define LDSM_X4(r0, r1, r2, r3, a)                                            \
    asm volatile("ldmatrix.sync.aligned.m8n8.x4.shared.b16 {%0,%1,%2,%3}, [%4];" \
                 : "=r"(r0), "=r"(r1), "=r"(r2), "=r"(r3) : "r"(a))

#define LDSM_X4_T(r0, r1, r2, r3, a)                                          \
    asm volatile("ldmatrix.sync.aligned.m8n8.x4.trans.shared.b16 {%0,%1,%2,%3}, [%4];" \
                 : "=r"(r0), "=r"(r1), "=r"(r2), "=r"(r3) : "r"(a))

#define MMA_BF16(c0, c1, c2, c3, a0, a1, a2, a3, b0, b1)                      \
    asm volatile("mma.sync.aligned.m16n8k16.row.col.f32.bf16.bf16.f32 "       \
                 "{%0,%1,%2,%3}, {%4,%5,%6,%7}, {%8,%9}, {%0,%1,%2,%3};"      \
                 : "+f"(c0), "+f"(c1), "+f"(c2), "+f"(c3)                     \
                 : "r"(a0), "r"(a1), "r"(a2), "r"(a3), "r"(b0), "r"(b1))

__device__ __forceinline__ uint32_t pack_bf2(float a, float b) {
    __nv_bfloat162 h = __halves2bfloat162(__float2bfloat16(a), __float2bfloat16(b));
    return *(uint32_t*)&h;
}

// ---------------------------------------------------------------------------
// Mask dtype detection + conversion (known-good)
// ---------------------------------------------------------------------------
__global__ void detect_mask(const unsigned int* __restrict__ w) {
    __shared__ int s_not_int, s_not_float;
    if (threadIdx.x == 0) { s_not_int = 0; s_not_float = 0; }
    __syncthreads();
    int li = 0, lf = 0;
    for (int i = threadIdx.x; i < 65536; i += blockDim.x) {
        unsigned int x = w[i];
        if (x > 1u) li = 1;
        if (x != 0u && x != 0x3F800000u) lf = 1;
    }
    if (li) atomicOr(&s_not_int, 1);
    if (lf) atomicOr(&s_not_float, 1);
    __syncthreads();
    if (threadIdx.x == 0) {
        if (!s_not_int)        g_mask_kind = 1;
        else if (!s_not_float) g_mask_kind = 2;
        else                   g_mask_kind = 0;
    }
}

__global__ void convert_mask(const void* __restrict__ m) {
    size_t i = (size_t)blockIdx.x * blockDim.x + threadIdx.x;
    const size_t total = (size_t)BB * MM * NN;
    if (i >= total) return;
    int kind = g_mask_kind;
    unsigned char v;
    if (kind == 1)      v = (unsigned char)(((const int*)m)[i] != 0);
    else if (kind == 2) v = (unsigned char)(((const float*)m)[i] != 0.0f);
    else                v = ((const unsigned char*)m)[i] ? 1 : 0;
    g_mask[i] = v;
}

// ---------------------------------------------------------------------------
// Split fp32 -> bf16 triples
// ---------------------------------------------------------------------------
__global__ void split_act(const float* __restrict__ X, __nv_bfloat16* __restrict__ O) {
    size_t i = (size_t)blockIdx.x * blockDim.x + threadIdx.x;
    if (i >= (size_t)(BB * MM) * DMOD) return;
    int r = (int)(i >> 10);
    int c = (int)(i & 1023);
    float x = X[i];
    __nv_bfloat16 hi = __float2bfloat16(x);
    __nv_bfloat16 lo = __float2bfloat16(x - __bfloat162float(hi));
    size_t base = (size_t)r * KSPLIT;
    O[base + c] = hi;
    O[base + DMOD + c] = hi;
    O[base + 2 * DMOD + c] = lo;
}

__global__ void split_wgt(const float* __restrict__ W, __nv_bfloat16* __restrict__ O) {
    size_t i = (size_t)blockIdx.x * blockDim.x + threadIdx.x;
    if (i >= (size_t)DMOD * DMOD) return;
    int r = (int)(i >> 10);
    int c = (int)(i & 1023);
    float x = W[i];
    __nv_bfloat16 hi = __float2bfloat16(x);
    __nv_bfloat16 lo = __float2bfloat16(x - __bfloat162float(hi));
    size_t base = (size_t)r * KSPLIT;
    O[base + c] = hi;
    O[base + DMOD + c] = lo;
    O[base + 2 * DMOD + c] = hi;
}

// ---------------------------------------------------------------------------
// HMMA bf16 GEMM (unchanged from R6, passing)
// ---------------------------------------------------------------------------
#define SROWB 80

__global__ void __launch_bounds__(128, 2) gemm_hmma(
        const uint4* __restrict__ A3,
        const uint4* __restrict__ B3,
        float* __restrict__ C) {
    __shared__ __align__(16) char As[2][128 * SROWB];
    __shared__ __align__(16) char Bs[2][128 * SROWB];

    const int t = threadIdx.x;
    const int lane = t & 31, wid = t >> 5;
    const int m0 = blockIdx.y * 128, n0 = blockIdx.x * 128;
    const int wm = (wid & 1) * 64, wn = (wid >> 1) * 64;
    const int g = lane >> 2, tq = lane & 3;

    const uint4* arow = A3 + (size_t)(m0 + t) * 384;
    const uint4* brow = B3 + (size_t)(n0 + t) * 384;
    const int swz = (t >> 3) & 3;

    uint4 pa[4], pb[4];
#pragma unroll
    for (int j = 0; j < 4; j++) { pa[j] = arow[j]; pb[j] = brow[j]; }
#pragma unroll
    for (int j = 0; j < 4; j++) {
        *(uint4*)(As[0] + t * SROWB + ((j ^ swz) << 4)) = pa[j];
        *(uint4*)(Bs[0] + t * SROWB + ((j ^ swz) << 4)) = pb[j];
    }
    __syncthreads();

    float c[4][8][4];
#pragma unroll
    for (int i = 0; i < 4; i++)
#pragma unroll
        for (int j = 0; j < 8; j++)
#pragma unroll
            for (int q = 0; q < 4; q++) c[i][j][q] = 0.f;

    const int jj = lane >> 3;
    const int r8 = lane & 7;

    for (int kc = 0; kc < 96; kc++) {
        const int buf = kc & 1;
        if (kc < 95) {
#pragma unroll
            for (int j = 0; j < 4; j++) {
                pa[j] = arow[(kc + 1) * 4 + j];
                pb[j] = brow[(kc + 1) * 4 + j];
            }
        }
        const char* Ab = As[buf];
        const char* Bb = Bs[buf];
#pragma unroll
        for (int ks = 0; ks < 2; ks++) {
            const int ku = ks * 2;
            uint32_t a[4][4], b[8][2];
#pragma unroll
            for (int mt = 0; mt < 4; mt++) {
                int r = wm + mt * 16 + ((jj & 1) << 3) + r8;
                int u = (ku + (jj >> 1)) ^ ((r >> 3) & 3);
                uint32_t ad = cvta_s(Ab + r * SROWB + (u << 4));
                LDSM_X4(a[mt][0], a[mt][1], a[mt][2], a[mt][3], ad);
            }
#pragma unroll
            for (int np = 0; np < 4; np++) {
                int r = wn + np * 16 + ((jj >> 1) << 3) + r8;
                int u = (ku + (jj & 1)) ^ ((r >> 3) & 3);
                uint32_t ad = cvta_s(Bb + r * SROWB + (u << 4));
                LDSM_X4(b[np * 2][0], b[np * 2][1], b[np * 2 + 1][0], b[np * 2 + 1][1], ad);
            }
#pragma unroll
            for (int mt = 0; mt < 4; mt++)
#pragma unroll
                for (int nt = 0; nt < 8; nt++)
                    MMA_BF16(c[mt][nt][0], c[mt][nt][1], c[mt][nt][2], c[mt][nt][3],
                             a[mt][0], a[mt][1], a[mt][2], a[mt][3],
                             b[nt][0], b[nt][1]);
        }
        __syncthreads();
        if (kc < 95) {
#pragma unroll
            for (int j = 0; j < 4; j++) {
                *(uint4*)(As[buf ^ 1] + t * SROWB + ((j ^ swz) << 4)) = pa[j];
                *(uint4*)(Bs[buf ^ 1] + t * SROWB + ((j ^ swz) << 4)) = pb[j];
            }
        }
        __syncthreads();
    }

#pragma unroll
    for (int mt = 0; mt < 4; mt++) {
        int row = m0 + wm + mt * 16 + g;
#pragma unroll
        for (int nt = 0; nt < 8; nt++) {
            int col = n0 + wn + nt * 8 + tq * 2;
            *(float2*)&C[(size_t)row * DMOD + col] =
                make_float2(c[mt][nt][0], c[mt][nt][1]);
            *(float2*)&C[(size_t)(row + 8) * DMOD + col] =
                make_float2(c[mt][nt][2], c[mt][nt][3]);
        }
    }
}

// ---------------------------------------------------------------------------
// HMMA flash attention. CTA: one (b,h), 128 query rows (8 warps x 16 rows),
// N-tile 64, 32 iterations. QK^T split-bf16 (Qcat[192] x Kcat[192]);
// PV split via in-register P fragments (Phi,Plo) x (Vhi,Vlo in smem).
// ---------------------------------------------------------------------------
#define A2_KCAT 0                   // [64][200] bf16 = 25600
#define A2_VHI  25600               // [64][72]  bf16 = 9216
#define A2_VLO  34816               // [64][72]  bf16 = 9216
#define A2_MSK  44032               // [128][64] u8   = 8192
#define A2_SMEM 52224

__global__ void __launch_bounds__(256, 1) attn_hmma(
        const float* __restrict__ Qp,
        const float* __restrict__ Kp,
        const float* __restrict__ Vp,
        const unsigned char* __restrict__ mask,
        float* __restrict__ ctx) {
    extern __shared__ char sm[];
    const uint32_t sb = cvta_s(sm);

    const int t = threadIdx.x;
    const int lane = t & 31, w = t >> 5;
    const int g = lane >> 2, q = lane & 3;
    const int bh = blockIdx.y;
    const int b = bh >> 4, h = bh & 15;
    const int m0 = blockIdx.x * 128;
    const int wm = w * 16;

    // ---- Phase 0: stage Qcat [128][200] bf16, pull A-fragments to registers
    {
        const int row = t >> 1;
        const int cb = (t & 1) * 32;
        const float* qg = Qp + ((size_t)(b * MM + m0 + row)) * DMOD + h * DK + cb;
        __nv_bfloat16* qc = (__nv_bfloat16*)(sm) + row * 200;
#pragma unroll
        for (int i = 0; i < 8; i++) {
            float4 v = *(const float4*)(qg + 4 * i);
            float xs[4] = {v.x, v.y, v.z, v.w};
#pragma unroll
            for (int j = 0; j < 4; j++) {
                int c0 = cb + 4 * i + j;
                __nv_bfloat16 hi = __float2bfloat16(xs[j]);
                __nv_bfloat16 lo = __float2bfloat16(xs[j] - __bfloat162float(hi));
                qc[c0] = hi;
                qc[64 + c0] = hi;
                qc[128 + c0] = lo;
            }
        }
    }
    __syncthreads();

    uint32_t qf[12][4];
    {
        const int mt = lane >> 3, r8 = lane & 7;
#pragma unroll
        for (int kp = 0; kp < 12; kp++) {
            uint32_t ad = sb + (uint32_t)((wm + (mt & 1) * 8 + r8) * 400
                                          + (kp * 16 + (mt >> 1) * 8) * 2);
            LDSM_X4(qf[kp][0], qf[kp][1], qf[kp][2], qf[kp][3], ad);
        }
    }
    __syncthreads();   // Q staging area may now be overwritten

    float O[8][4];
#pragma unroll
    for (int i = 0; i < 8; i++)
#pragma unroll
        for (int j = 0; j < 4; j++) O[i][j] = 0.f;
    float mrow0 = -1e30f, mrow1 = -1e30f, lrow0 = 0.f, lrow1 = 0.f;

    const int mt = lane >> 3, r8 = lane & 7;

    for (int it = 0; it < 32; it++) {
        const int n0g = it * 64;

        // ---- load K,V (fp32 -> split bf16) + mask tile
        {
            const int row = t >> 2;
            const int cb = (t & 3) * 16;
            const float* kg = Kp + ((size_t)(b * NN + n0g + row)) * DMOD + h * DK + cb;
            const float* vg = Vp + ((size_t)(b * NN + n0g + row)) * DMOD + h * DK + cb;
            __nv_bfloat16* kc = (__nv_bfloat16*)(sm + A2_KCAT) + row * 200;
            __nv_bfloat16* vh = (__nv_bfloat16*)(sm + A2_VHI) + row * 72;
            __nv_bfloat16* vl = (__nv_bfloat16*)(sm + A2_VLO) + row * 72;
#pragma unroll
            for (int i = 0; i < 4; i++) {
                float4 kv = *(const float4*)(kg + 4 * i);
                float4 vv = *(const float4*)(vg + 4 * i);
                float ks[4] = {kv.x, kv.y, kv.z, kv.w};
                float vs[4] = {vv.x, vv.y, vv.z, vv.w};
#pragma unroll
                for (int j = 0; j < 4; j++) {
                    int c0 = cb + 4 * i + j;
                    __nv_bfloat16 khi = __float2bfloat16(ks[j]);
                    __nv_bfloat16 klo = __float2bfloat16(ks[j] - __bfloat162float(khi));
                    kc[c0] = khi;
                    kc[64 + c0] = klo;
                    kc[128 + c0] = khi;
                    __nv_bfloat16 vhi = __float2bfloat16(vs[j]);
                    __nv_bfloat16 vlo = __float2bfloat16(vs[j] - __bfloat162float(vhi));
                    vh[c0] = vhi;
                    vl[c0] = vlo;
                }
            }
            const int row2 = t >> 1;
            const int cb2 = (t & 1) * 32;
            const uint4* mg = (const uint4*)(mask + ((size_t)(b * MM + m0 + row2)) * NN + n0g + cb2);
            *(uint4*)(sm + A2_MSK + row2 * 64 + cb2) = mg[0];
            *(uint4*)(sm + A2_MSK + row2 * 64 + cb2 + 16) = mg[1];
        }
        __syncthreads();

        // ---- S = Qcat @ Kcat^T  (12 k-steps of 16)
        float S[8][4];
#pragma unroll
        for (int i = 0; i < 8; i++)
#pragma unroll
            for (int j = 0; j < 4; j++) S[i][j] = 0.f;

#pragma unroll
        for (int nt = 0; nt < 8; nt++) {
#pragma unroll
            for (int kp = 0; kp < 6; kp++) {
                uint32_t b0, b1, b2, b3;
                uint32_t ad = sb + A2_KCAT + (uint32_t)((nt * 8 + r8) * 400
                                                       + (kp * 32 + mt * 8) * 2);
                LDSM_X4(b0, b1, b2, b3, ad);
                MMA_BF16(S[nt][0], S[nt][1], S[nt][2], S[nt][3],
                         qf[2 * kp][0], qf[2 * kp][1], qf[2 * kp][2], qf[2 * kp][3],
                         b0, b1);
                MMA_BF16(S[nt][0], S[nt][1], S[nt][2], S[nt][3],
                         qf[2 * kp + 1][0], qf[2 * kp + 1][1], qf[2 * kp + 1][2], qf[2 * kp + 1][3],
                         b2, b3);
            }
        }

        // ---- mask + scale (matches ref: (mask ? -1e9 : s) * 0.125)
#pragma unroll
        for (int nt = 0; nt < 8; nt++) {
            unsigned short mA = *(const unsigned short*)(sm + A2_MSK + (wm + g) * 64 + nt * 8 + 2 * q);
            unsigned short mB = *(const unsigned short*)(sm + A2_MSK + (wm + g + 8) * 64 + nt * 8 + 2 * q);
            S[nt][0] = (mA & 0xff) ? -1.25e8f : S[nt][0] * 0.125f;
            S[nt][1] = (mA >> 8)   ? -1.25e8f : S[nt][1] * 0.125f;
            S[nt][2] = (mB & 0xff) ? -1.25e8f : S[nt][2] * 0.125f;
            S[nt][3] = (mB >> 8)   ? -1.25e8f : S[nt][3] * 0.125f;
        }

        // ---- online softmax
        float mx0 = -1e30f, mx1 = -1e30f;
#pragma unroll
        for (int nt = 0; nt < 8; nt++) {
            mx0 = fmaxf(mx0, fmaxf(S[nt][0], S[nt][1]));
            mx1 = fmaxf(mx1, fmaxf(S[nt][2], S[nt][3]));
        }
        mx0 = fmaxf(mx0, __shfl_xor_sync(0xffffffffu, mx0, 1));
        mx0 = fmaxf(mx0, __shfl_xor_sync(0xffffffffu, mx0, 2));
        mx1 = fmaxf(mx1, __shfl_xor_sync(0xffffffffu, mx1, 1));
        mx1 = fmaxf(mx1, __shfl_xor_sync(0xffffffffu, mx1, 2));
        const float nm0 = fmaxf(mrow0, mx0);
        const float nm1 = fmaxf(mrow1, mx1);
        const float c0 = __expf(mrow0 - nm0);
        const float c1 = __expf(mrow1 - nm1);
        mrow0 = nm0; mrow1 = nm1;

        float s0 = 0.f, s1 = 0.f;
        uint32_t pahi[4][4], palo[4][4];
#pragma unroll
        for (int nt = 0; nt < 8; nt++) {
            float p0 = __expf(S[nt][0] - nm0);
            float p1 = __expf(S[nt][1] - nm0);
            float p2 = __expf(S[nt][2] - nm1);
            float p3 = __expf(S[nt][3] - nm1);
            s0 += p0 + p1;
            s1 += p2 + p3;
            float h0 = __bfloat162float(__float2bfloat16(p0));
            float h1 = __bfloat162float(__float2bfloat16(p1));
            float h2 = __bfloat162float(__float2bfloat16(p2));
            float h3 = __bfloat162float(__float2bfloat16(p3));
            const int ks = nt >> 1;
            const int hv = (nt & 1) * 2;
            pahi[ks][hv]     = pack_bf2(h0, h1);
            pahi[ks][hv + 1] = pack_bf2(h2, h3);
            palo[ks][hv]     = pack_bf2(p0 - h0, p1 - h1);
            palo[ks][hv + 1] = pack_bf2(p2 - h2, p3 - h3);
        }
        s0 += __shfl_xor_sync(0xffffffffu, s0, 1);
        s0 += __shfl_xor_sync(0xffffffffu, s0, 2);
        s1 += __shfl_xor_sync(0xffffffffu, s1, 1);
        s1 += __shfl_xor_sync(0xffffffffu, s1, 2);
        lrow0 = lrow0 * c0 + s0;
        lrow1 = lrow1 * c1 + s1;

#pragma unroll
        for (int dt = 0; dt < 8; dt++) {
            O[dt][0] *= c0; O[dt][1] *= c0;
            O[dt][2] *= c1; O[dt][3] *= c1;
        }

        // ---- O += P @ V  (4 n-ksteps of 16; 3-term split)
#pragma unroll
        for (int ks = 0; ks < 4; ks++) {
#pragma unroll
            for (int dp = 0; dp < 4; dp++) {
                uint32_t h0, h1, h2, h3, l0, l1, l2, l3;
                uint32_t vrow = (uint32_t)(ks * 16 + (mt & 1) * 8 + r8);
                uint32_t vcol = (uint32_t)(dp * 16 + (mt >> 1) * 8);
                LDSM_X4_T(h0, h1, h2, h3, sb + A2_VHI + vrow * 144 + vcol * 2);
                LDSM_X4_T(l0, l1, l2, l3, sb + A2_VLO + vrow * 144 + vcol * 2);
                MMA_BF16(O[2*dp][0], O[2*dp][1], O[2*dp][2], O[2*dp][3],
                         pahi[ks][0], pahi[ks][1], pahi[ks][2], pahi[ks][3], h0, h1);
                MMA_BF16(O[2*dp][0], O[2*dp][1], O[2*dp][2], O[2*dp][3],
                         pahi[ks][0], pahi[ks][1], pahi[ks][2], pahi[ks][3], l0, l1);
                MMA_BF16(O[2*dp][0], O[2*dp][1], O[2*dp][2], O[2*dp][3],
                         palo[ks][0], palo[ks][1], palo[ks][2], palo[ks][3], h0, h1);
                MMA_BF16(O[2*dp+1][0], O[2*dp+1][1], O[2*dp+1][2], O[2*dp+1][3],
                         pahi[ks][0], pahi[ks][1], pahi[ks][2], pahi[ks][3], h2, h3);
                MMA_BF16(O[2*dp+1][0], O[2*dp+1][1], O[2*dp+1][2], O[2*dp+1][3],
                         pahi[ks][0], pahi[ks][1], pahi[ks][2], pahi[ks][3], l2, l3);
                MMA_BF16(O[2*dp+1][0], O[2*dp+1][1], O[2*dp+1][2], O[2*dp+1][3],
                         palo[ks][0], palo[ks][1], palo[ks][2], palo[ks][3], h2, h3);
            }
        }
        __syncthreads();   // smem consumed; next iter may overwrite
    }

    // ---- epilogue
    const float inv0 = 1.0f / lrow0;
    const float inv1 = 1.0f / lrow1;
    const int row0 = m0 + wm + g;
#pragma unroll
    for (int dt = 0; dt < 8; dt++) {
        int col = h * DK + dt * 8 + 2 * q;
        *(float2*)&ctx[((size_t)(b * MM + row0)) * DMOD + col] =
            make_float2(O[dt][0] * inv0, O[dt][1] * inv0);
        *(float2*)&ctx[((size_t)(b * MM + row0 + 8)) * DMOD + col] =
            make_float2(O[dt][2] * inv1, O[dt][3] * inv1);
    }
}

// ---------------------------------------------------------------------------
extern "C" void kernel_launch(void* const* d_in, const int* in_sizes, int n_in,
                              void* d_out, int out_size) {
    const float* q  = (const float*)d_in[0];
    const float* k  = (const float*)d_in[1];
    const float* v  = (const float*)d_in[2];
    const void*  mask_raw = d_in[3];
    const float* Wq = (const float*)d_in[4];
    const float* Wk = (const float*)d_in[5];
    const float* Wv = (const float*)d_in[6];
    const float* Wo = (const float*)d_in[7];
    float* out = (float*)d_out;

    void *Qp_, *Kp_, *Vp_, *ctx_, *mask_, *A3_, *W3_;
    cudaGetSymbolAddress(&Qp_,  g_Qp);
    cudaGetSymbolAddress(&Kp_,  g_Kp);
    cudaGetSymbolAddress(&Vp_,  g_Vp);
    cudaGetSymbolAddress(&ctx_, g_ctx);
    cudaGetSymbolAddress(&mask_, g_mask);
    cudaGetSymbolAddress(&A3_,  g_A3);
    cudaGetSymbolAddress(&W3_,  g_W3);
    float* Qp  = (float*)Qp_;
    float* Kp  = (float*)Kp_;
    float* Vp  = (float*)Vp_;
    float* ctx = (float*)ctx_;
    unsigned char* mask = (unsigned char*)mask_;
    __nv_bfloat16* A3 = (__nv_bfloat16*)A3_;
    __nv_bfloat16* W3 = (__nv_bfloat16*)W3_;

    cudaFuncSetAttribute(attn_hmma,
                         cudaFuncAttributeMaxDynamicSharedMemorySize, A2_SMEM);

    // Normalize mask dtype -> uint8
    detect_mask<<<1, 1024>>>((const unsigned int*)mask_raw);
    const size_t mtotal = (size_t)BB * MM * NN;
    convert_mask<<<(unsigned)((mtotal + 511) / 512), 512>>>(mask_raw);

    const size_t act_elems = (size_t)(BB * MM) * DMOD;
    const size_t wgt_elems = (size_t)DMOD * DMOD;
    const unsigned actg = (unsigned)((act_elems + 255) / 256);
    const unsigned wgtg = (unsigned)((wgt_elems + 255) / 256);
    dim3 gridG(DMOD / 128, (BB * MM) / 128);             // (8, 32)

    split_act<<<actg, 256>>>(q, A3);
    split_wgt<<<wgtg, 256>>>(Wq, W3);
    gemm_hmma<<<gridG, 128>>>((const uint4*)A3, (const uint4*)W3, Qp);

    split_act<<<actg, 256>>>(k, A3);
    split_wgt<<<wgtg, 256>>>(Wk, W3);
    gemm_hmma<<<gridG, 128>>>((const uint4*)A3, (const uint4*)W3, Kp);

    split_act<<<actg, 256>>>(v, A3);
    split_wgt<<<wgtg, 256>>>(Wv, W3);
    gemm_hmma<<<gridG, 128>>>((const uint4*)A3, (const uint4*)W3, Vp);

    dim3 gridA(MM / 128, BB * NH);                       // (16, 32)
    attn_hmma<<<gridA, 256, A2_SMEM>>>(Qp, Kp, Vp, mask, ctx);

    split_act<<<actg, 256>>>(ctx, A3);
    split_wgt<<<wgtg, 256>>>(Wo, W3);
    gemm_hmma<<<gridG, 128>>>((const uint4*)A3, (const uint4*)W3, out);
}

// round 10
// speedup vs baseline: 3.1835x; 1.1092x over previous
#include <cuda_runtime.h>
#include <cuda_bf16.h>
#include <cstdint>

// Problem constants
#define BB   2
#define MM   2048
#define NN   2048
#define DMOD 1024
#define NH   16
#define DK   64

#define KSPLIT (3 * DMOD)          // 3072: [hi|hi|lo] x [hi|lo|hi]

// Scratch (device globals: allocation-free rule)
__device__ float g_Qp[BB * MM * DMOD];
__device__ float g_Kp[BB * NN * DMOD];
__device__ float g_Vp[BB * NN * DMOD];
__device__ float g_ctx[BB * MM * DMOD];
__device__ unsigned char g_mask[BB * (size_t)MM * NN];
__device__ int g_mask_kind;
__device__ __nv_bfloat16 g_A3[(size_t)(BB * MM) * KSPLIT];       // 25 MB
__device__ __nv_bfloat16 g_W3[(size_t)DMOD * KSPLIT];            // 6.3 MB
__device__ __nv_bfloat16 g_Kc[(size_t)BB * NH * NN * 192];       // 25 MB, head-major
__device__ __nv_bfloat16 g_Vh[(size_t)BB * NH * NN * DK];        // 8.4 MB
__device__ __nv_bfloat16 g_Vl[(size_t)BB * NH * NN * DK];        // 8.4 MB

// ---------------------------------------------------------------------------
// Helpers (sm_80-era: mma.sync + ldmatrix + cp.async; NO tcgen05 — harness
// PTX targets base sm_103 which rejects 'a' features)
// ---------------------------------------------------------------------------
__device__ __forceinline__ uint32_t cvta_s(const void* p) {
    uint32_t a;
    asm("{ .reg .u64 t; cvta.to.shared.u64 t, %1; cvt.u32.u64 %0, t; }"
        : "=r"(a) : "l"(p));
    return a;
}

#define LDSM_X4(r0, r1, r2, r3, a)                                            \
    asm volatile("ldmatrix.sync.aligned.m8n8.x4.shared.b16 {%0,%1,%2,%3}, [%4];" \
                 : "=r"(r0), "=r"(r1), "=r"(r2), "=r"(r3) : "r"(a))

#define LDSM_X4_T(r0, r1, r2, r3, a)                                          \
    asm volatile("ldmatrix.sync.aligned.m8n8.x4.trans.shared.b16 {%0,%1,%2,%3}, [%4];" \
                 : "=r"(r0), "=r"(r1), "=r"(r2), "=r"(r3) : "r"(a))

#define MMA_BF16(c0, c1, c2, c3, a0, a1, a2, a3, b0, b1)                      \
    asm volatile("mma.sync.aligned.m16n8k16.row.col.f32.bf16.bf16.f32 "       \
                 "{%0,%1,%2,%3}, {%4,%5,%6,%7}, {%8,%9}, {%0,%1,%2,%3};"      \
                 : "+f"(c0), "+f"(c1), "+f"(c2), "+f"(c3)                     \
                 : "r"(a0), "r"(a1), "r"(a2), "r"(a3), "r"(b0), "r"(b1))

#define CP_ASYNC16(s, g)                                                      \
    asm volatile("cp.async.cg.shared.global [%0], [%1], 16;" :: "r"(s), "l"(g))
#define CP_COMMIT() asm volatile("cp.async.commit_group;" ::: "memory")
#define CP_WAIT0()  asm volatile("cp.async.wait_group 0;" ::: "memory")

__device__ __forceinline__ uint32_t pack_bf2(float a, float b) {
    __nv_bfloat162 h = __halves2bfloat162(__float2bfloat16(a), __float2bfloat16(b));
    return *(uint32_t*)&h;
}

// ---------------------------------------------------------------------------
// Mask dtype detection + conversion (known-good)
// ---------------------------------------------------------------------------
__global__ void detect_mask(const unsigned int* __restrict__ w) {
    __shared__ int s_not_int, s_not_float;
    if (threadIdx.x == 0) { s_not_int = 0; s_not_float = 0; }
    __syncthreads();
    int li = 0, lf = 0;
    for (int i = threadIdx.x; i < 65536; i += blockDim.x) {
        unsigned int x = w[i];
        if (x > 1u) li = 1;
        if (x != 0u && x != 0x3F800000u) lf = 1;
    }
    if (li) atomicOr(&s_not_int, 1);
    if (lf) atomicOr(&s_not_float, 1);
    __syncthreads();
    if (threadIdx.x == 0) {
        if (!s_not_int)        g_mask_kind = 1;
        else if (!s_not_float) g_mask_kind = 2;
        else                   g_mask_kind = 0;
    }
}

__global__ void convert_mask(const void* __restrict__ m) {
    size_t i = (size_t)blockIdx.x * blockDim.x + threadIdx.x;
    const size_t total = (size_t)BB * MM * NN;
    if (i >= total) return;
    int kind = g_mask_kind;
    unsigned char v;
    if (kind == 1)      v = (unsigned char)(((const int*)m)[i] != 0);
    else if (kind == 2) v = (unsigned char)(((const float*)m)[i] != 0.0f);
    else                v = ((const unsigned char*)m)[i] ? 1 : 0;
    g_mask[i] = v;
}

// ---------------------------------------------------------------------------
// Split fp32 -> bf16 triples (projection operands)
// ---------------------------------------------------------------------------
__global__ void split_act(const float* __restrict__ X, __nv_bfloat16* __restrict__ O) {
    size_t i = (size_t)blockIdx.x * blockDim.x + threadIdx.x;
    if (i >= (size_t)(BB * MM) * DMOD) return;
    int r = (int)(i >> 10);
    int c = (int)(i & 1023);
    float x = X[i];
    __nv_bfloat16 hi = __float2bfloat16(x);
    __nv_bfloat16 lo = __float2bfloat16(x - __bfloat162float(hi));
    size_t base = (size_t)r * KSPLIT;
    O[base + c] = hi;
    O[base + DMOD + c] = hi;
    O[base + 2 * DMOD + c] = lo;
}

__global__ void split_wgt(const float* __restrict__ W, __nv_bfloat16* __restrict__ O) {
    size_t i = (size_t)blockIdx.x * blockDim.x + threadIdx.x;
    if (i >= (size_t)DMOD * DMOD) return;
    int r = (int)(i >> 10);
    int c = (int)(i & 1023);
    float x = W[i];
    __nv_bfloat16 hi = __float2bfloat16(x);
    __nv_bfloat16 lo = __float2bfloat16(x - __bfloat162float(hi));
    size_t base = (size_t)r * KSPLIT;
    O[base + c] = hi;
    O[base + DMOD + c] = lo;
    O[base + 2 * DMOD + c] = hi;
}

// ---------------------------------------------------------------------------
// split_kv: Kp/Vp [b, n, h*64+d] fp32 -> head-major split buffers
//   Kc[(b,h,n)][0:64]=Khi [64:128]=Klo [128:192]=Khi ; Vh/Vl[(b,h,n)][d]
// ---------------------------------------------------------------------------
__global__ void split_kv(const float* __restrict__ Kp, const float* __restrict__ Vp,
                         __nv_bfloat16* __restrict__ Kc,
                         __nv_bfloat16* __restrict__ Vh,
                         __nv_bfloat16* __restrict__ Vl) {
    size_t i = (size_t)blockIdx.x * blockDim.x + threadIdx.x;
    if (i >= (size_t)BB * NN * DMOD) return;
    int bn = (int)(i >> 10);
    int c  = (int)(i & 1023);
    int h = c >> 6, d = c & 63;
    int b = bn >> 11, n = bn & 2047;
    size_t hb = ((size_t)(b * NH + h)) * NN + n;
    float kx = Kp[i];
    __nv_bfloat16 khi = __float2bfloat16(kx);
    __nv_bfloat16 klo = __float2bfloat16(kx - __bfloat162float(khi));
    Kc[hb * 192 + d] = khi;
    Kc[hb * 192 + 64 + d] = klo;
    Kc[hb * 192 + 128 + d] = khi;
    float vx = Vp[i];
    __nv_bfloat16 vhi = __float2bfloat16(vx);
    __nv_bfloat16 vlo = __float2bfloat16(vx - __bfloat162float(vhi));
    Vh[hb * DK + d] = vhi;
    Vl[hb * DK + d] = vlo;
}

// ---------------------------------------------------------------------------
// HMMA bf16 GEMM (unchanged from R6, passing)
// ---------------------------------------------------------------------------
#define SROWB 80

__global__ void __launch_bounds__(128, 2) gemm_hmma(
        const uint4* __restrict__ A3,
        const uint4* __restrict__ B3,
        float* __restrict__ C) {
    __shared__ __align__(16) char As[2][128 * SROWB];
    __shared__ __align__(16) char Bs[2][128 * SROWB];

    const int t = threadIdx.x;
    const int lane = t & 31, wid = t >> 5;
    const int m0 = blockIdx.y * 128, n0 = blockIdx.x * 128;
    const int wm = (wid & 1) * 64, wn = (wid >> 1) * 64;
    const int g = lane >> 2, tq = lane & 3;

    const uint4* arow = A3 + (size_t)(m0 + t) * 384;
    const uint4* brow = B3 + (size_t)(n0 + t) * 384;
    const int swz = (t >> 3) & 3;

    uint4 pa[4], pb[4];
#pragma unroll
    for (int j = 0; j < 4; j++) { pa[j] = arow[j]; pb[j] = brow[j]; }
#pragma unroll
    for (int j = 0; j < 4; j++) {
        *(uint4*)(As[0] + t * SROWB + ((j ^ swz) << 4)) = pa[j];
        *(uint4*)(Bs[0] + t * SROWB + ((j ^ swz) << 4)) = pb[j];
    }
    __syncthreads();

    float c[4][8][4];
#pragma unroll
    for (int i = 0; i < 4; i++)
#pragma unroll
        for (int j = 0; j < 8; j++)
#pragma unroll
            for (int q = 0; q < 4; q++) c[i][j][q] = 0.f;

    const int jj = lane >> 3;
    const int r8 = lane & 7;

    for (int kc = 0; kc < 96; kc++) {
        const int buf = kc & 1;
        if (kc < 95) {
#pragma unroll
            for (int j = 0; j < 4; j++) {
                pa[j] = arow[(kc + 1) * 4 + j];
                pb[j] = brow[(kc + 1) * 4 + j];
            }
        }
        const char* Ab = As[buf];
        const char* Bb = Bs[buf];
#pragma unroll
        for (int ks = 0; ks < 2; ks++) {
            const int ku = ks * 2;
            uint32_t a[4][4], b[8][2];
#pragma unroll
            for (int mt = 0; mt < 4; mt++) {
                int r = wm + mt * 16 + ((jj & 1) << 3) + r8;
                int u = (ku + (jj >> 1)) ^ ((r >> 3) & 3);
                uint32_t ad = cvta_s(Ab + r * SROWB + (u << 4));
                LDSM_X4(a[mt][0], a[mt][1], a[mt][2], a[mt][3], ad);
            }
#pragma unroll
            for (int np = 0; np < 4; np++) {
                int r = wn + np * 16 + ((jj >> 1) << 3) + r8;
                int u = (ku + (jj & 1)) ^ ((r >> 3) & 3);
                uint32_t ad = cvta_s(Bb + r * SROWB + (u << 4));
                LDSM_X4(b[np * 2][0], b[np * 2][1], b[np * 2 + 1][0], b[np * 2 + 1][1], ad);
            }
#pragma unroll
            for (int mt = 0; mt < 4; mt++)
#pragma unroll
                for (int nt = 0; nt < 8; nt++)
                    MMA_BF16(c[mt][nt][0], c[mt][nt][1], c[mt][nt][2], c[mt][nt][3],
                             a[mt][0], a[mt][1], a[mt][2], a[mt][3],
                             b[nt][0], b[nt][1]);
        }
        __syncthreads();
        if (kc < 95) {
#pragma unroll
            for (int j = 0; j < 4; j++) {
                *(uint4*)(As[buf ^ 1] + t * SROWB + ((j ^ swz) << 4)) = pa[j];
                *(uint4*)(Bs[buf ^ 1] + t * SROWB + ((j ^ swz) << 4)) = pb[j];
            }
        }
        __syncthreads();
    }

#pragma unroll
    for (int mt = 0; mt < 4; mt++) {
        int row = m0 + wm + mt * 16 + g;
#pragma unroll
        for (int nt = 0; nt < 8; nt++) {
            int col = n0 + wn + nt * 8 + tq * 2;
            *(float2*)&C[(size_t)row * DMOD + col] =
                make_float2(c[mt][nt][0], c[mt][nt][1]);
            *(float2*)&C[(size_t)(row + 8) * DMOD + col] =
                make_float2(c[mt][nt][2], c[mt][nt][3]);
        }
    }
}

// ---------------------------------------------------------------------------
// HMMA flash attention, cp.async double-buffered, precomputed split K/V.
// CTA: one (b,h) x 128 query rows (8 warps x 16 rows), N-tile 64, 32 iters.
// ---------------------------------------------------------------------------
#define BUFSZ   52224
#define OFF_VH  25600               // [64][144B]
#define OFF_VL  34816               // [64][144B]
#define OFF_MSK 44032               // [128][64B]
#define A2_SMEM (2 * BUFSZ)         // 104448

__global__ void __launch_bounds__(256, 1) attn_hmma(
        const float* __restrict__ Qp,
        const __nv_bfloat16* __restrict__ Kc,
        const __nv_bfloat16* __restrict__ Vh,
        const __nv_bfloat16* __restrict__ Vl,
        const unsigned char* __restrict__ mask,
        float* __restrict__ ctx) {
    extern __shared__ char sm[];
    const uint32_t sb = cvta_s(sm);

    const int t = threadIdx.x;
    const int lane = t & 31, w = t >> 5;
    const int g = lane >> 2, q = lane & 3;
    const int bh = blockIdx.y;
    const int b = bh >> 4, h = bh & 15;
    const int bh2 = b * NH + h;
    const int m0 = blockIdx.x * 128;
    const int wm = w * 16;

    // ---- Phase 0: stage Qcat [128][400B] (overlays buffer 0), pull qf regs
    {
        const int row = t >> 1;
        const int cb = (t & 1) * 32;
        const float* qg = Qp + ((size_t)(b * MM + m0 + row)) * DMOD + h * DK + cb;
        __nv_bfloat16* qc = (__nv_bfloat16*)(sm) + row * 200;
#pragma unroll
        for (int i = 0; i < 8; i++) {
            float4 v = *(const float4*)(qg + 4 * i);
            float xs[4] = {v.x, v.y, v.z, v.w};
#pragma unroll
            for (int j = 0; j < 4; j++) {
                int c0 = cb + 4 * i + j;
                __nv_bfloat16 hi = __float2bfloat16(xs[j]);
                __nv_bfloat16 lo = __float2bfloat16(xs[j] - __bfloat162float(hi));
                qc[c0] = hi;
                qc[64 + c0] = hi;
                qc[128 + c0] = lo;
            }
        }
    }
    __syncthreads();

    uint32_t qf[12][4];
    {
        const int mt_ = lane >> 3, r8_ = lane & 7;
#pragma unroll
        for (int kp = 0; kp < 12; kp++) {
            uint32_t ad = sb + (uint32_t)((wm + (mt_ & 1) * 8 + r8_) * 400
                                          + (kp * 16 + (mt_ >> 1) * 8) * 2);
            LDSM_X4(qf[kp][0], qf[kp][1], qf[kp][2], qf[kp][3], ad);
        }
    }
    __syncthreads();   // staging area may now be overwritten

    // tile loader: 12 cp.async x 16B per thread
    auto load_tile = [&](int itn, uint32_t bufb) {
        const int n0g = itn * 64;
        const uint32_t sdst = sb + bufb;
        const char* kgb = (const char*)(Kc + ((size_t)bh2 * NN + n0g) * 192);
#pragma unroll
        for (int i = 0; i < 6; i++) {
            int e = t + i * 256;
            int row = e / 24, cc = e - row * 24;
            CP_ASYNC16(sdst + row * 400 + cc * 16, kgb + (size_t)row * 384 + cc * 16);
        }
        const char* vhb = (const char*)(Vh + ((size_t)bh2 * NN + n0g) * DK);
        const char* vlb = (const char*)(Vl + ((size_t)bh2 * NN + n0g) * DK);
#pragma unroll
        for (int i = 0; i < 2; i++) {
            int e = t + i * 256;
            int row = e >> 3, cc = e & 7;
            CP_ASYNC16(sdst + OFF_VH + row * 144 + cc * 16, vhb + row * 128 + cc * 16);
            CP_ASYNC16(sdst + OFF_VL + row * 144 + cc * 16, vlb + row * 128 + cc * 16);
        }
        const char* mb = (const char*)(mask + ((size_t)(b * MM + m0)) * NN + n0g);
#pragma unroll
        for (int i = 0; i < 2; i++) {
            int e = t + i * 256;
            int row = e >> 2, cc = e & 3;
            CP_ASYNC16(sdst + OFF_MSK + row * 64 + cc * 16, mb + (size_t)row * NN + cc * 16);
        }
    };

    float O[8][4];
#pragma unroll
    for (int i = 0; i < 8; i++)
#pragma unroll
        for (int j = 0; j < 4; j++) O[i][j] = 0.f;
    float mrow0 = -1e30f, mrow1 = -1e30f, lrow0 = 0.f, lrow1 = 0.f;

    const int mt = lane >> 3, r8 = lane & 7;

    load_tile(0, 0);
    CP_COMMIT();

    for (int it = 0; it < 32; it++) {
        const uint32_t bufb = (uint32_t)(it & 1) * BUFSZ;
        CP_WAIT0();
        __syncthreads();                    // tile it visible; compute(it-1) done
        if (it < 31) {
            load_tile(it + 1, (uint32_t)((it + 1) & 1) * BUFSZ);
            CP_COMMIT();
        }

        // ---- S = Qcat @ Kcat^T  (12 k-steps of 16)
        float S[8][4];
#pragma unroll
        for (int i = 0; i < 8; i++)
#pragma unroll
            for (int j = 0; j < 4; j++) S[i][j] = 0.f;

#pragma unroll
        for (int nt = 0; nt < 8; nt++) {
#pragma unroll
            for (int kp = 0; kp < 6; kp++) {
                uint32_t b0, b1, b2, b3;
                uint32_t ad = sb + bufb + (uint32_t)((nt * 8 + r8) * 400
                                                    + (kp * 32 + mt * 8) * 2);
                LDSM_X4(b0, b1, b2, b3, ad);
                MMA_BF16(S[nt][0], S[nt][1], S[nt][2], S[nt][3],
                         qf[2 * kp][0], qf[2 * kp][1], qf[2 * kp][2], qf[2 * kp][3],
                         b0, b1);
                MMA_BF16(S[nt][0], S[nt][1], S[nt][2], S[nt][3],
                         qf[2 * kp + 1][0], qf[2 * kp + 1][1], qf[2 * kp + 1][2], qf[2 * kp + 1][3],
                         b2, b3);
            }
        }

        // ---- mask + scale (matches ref: (mask ? -1e9 : s) * 0.125)
        const char* mbuf = sm + bufb + OFF_MSK;
#pragma unroll
        for (int nt = 0; nt < 8; nt++) {
            unsigned short mA = *(const unsigned short*)(mbuf + (wm + g) * 64 + nt * 8 + 2 * q);
            unsigned short mB = *(const unsigned short*)(mbuf + (wm + g + 8) * 64 + nt * 8 + 2 * q);
            S[nt][0] = (mA & 0xff) ? -1.25e8f : S[nt][0] * 0.125f;
            S[nt][1] = (mA >> 8)   ? -1.25e8f : S[nt][1] * 0.125f;
            S[nt][2] = (mB & 0xff) ? -1.25e8f : S[nt][2] * 0.125f;
            S[nt][3] = (mB >> 8)   ? -1.25e8f : S[nt][3] * 0.125f;
        }

        // ---- online softmax
        float mx0 = -1e30f, mx1 = -1e30f;
#pragma unroll
        for (int nt = 0; nt < 8; nt++) {
            mx0 = fmaxf(mx0, fmaxf(S[nt][0], S[nt][1]));
            mx1 = fmaxf(mx1, fmaxf(S[nt][2], S[nt][3]));
        }
        mx0 = fmaxf(mx0, __shfl_xor_sync(0xffffffffu, mx0, 1));
        mx0 = fmaxf(mx0, __shfl_xor_sync(0xffffffffu, mx0, 2));
        mx1 = fmaxf(mx1, __shfl_xor_sync(0xffffffffu, mx1, 1));
        mx1 = fmaxf(mx1, __shfl_xor_sync(0xffffffffu, mx1, 2));
        const float nm0 = fmaxf(mrow0, mx0);
        const float nm1 = fmaxf(mrow1, mx1);
        const float c0 = __expf(mrow0 - nm0);
        const float c1 = __expf(mrow1 - nm1);
        mrow0 = nm0; mrow1 = nm1;

        float s0 = 0.f, s1 = 0.f;
        uint32_t pahi[4][4], palo[4][4];
#pragma unroll
        for (int nt = 0; nt < 8; nt++) {
            float p0 = __expf(S[nt][0] - nm0);
            float p1 = __expf(S[nt][1] - nm0);
            float p2 = __expf(S[nt][2] - nm1);
            float p3 = __expf(S[nt][3] - nm1);
            s0 += p0 + p1;
            s1 += p2 + p3;
            float h0 = __bfloat162float(__float2bfloat16(p0));
            float h1 = __bfloat162float(__float2bfloat16(p1));
            float h2 = __bfloat162float(__float2bfloat16(p2));
            float h3 = __bfloat162float(__float2bfloat16(p3));
            const int ks = nt >> 1;
            const int hv = (nt & 1) * 2;
            pahi[ks][hv]     = pack_bf2(h0, h1);
            pahi[ks][hv + 1] = pack_bf2(h2, h3);
            palo[ks][hv]     = pack_bf2(p0 - h0, p1 - h1);
            palo[ks][hv + 1] = pack_bf2(p2 - h2, p3 - h3);
        }
        s0 += __shfl_xor_sync(0xffffffffu, s0, 1);
        s0 += __shfl_xor_sync(0xffffffffu, s0, 2);
        s1 += __shfl_xor_sync(0xffffffffu, s1, 1);
        s1 += __shfl_xor_sync(0xffffffffu, s1, 2);
        lrow0 = lrow0 * c0 + s0;
        lrow1 = lrow1 * c1 + s1;

#pragma unroll
        for (int dt = 0; dt < 8; dt++) {
            O[dt][0] *= c0; O[dt][1] *= c0;
            O[dt][2] *= c1; O[dt][3] *= c1;
        }

        // ---- O += P @ V  (4 n-ksteps of 16; 3-term split)
#pragma unroll
        for (int ks = 0; ks < 4; ks++) {
#pragma unroll
            for (int dp = 0; dp < 4; dp++) {
                uint32_t h0, h1, h2, h3, l0, l1, l2, l3;
                uint32_t vrow = (uint32_t)(ks * 16 + (mt & 1) * 8 + r8);
                uint32_t vcol = (uint32_t)(dp * 16 + (mt >> 1) * 8);
                LDSM_X4_T(h0, h1, h2, h3, sb + bufb + OFF_VH + vrow * 144 + vcol * 2);
                LDSM_X4_T(l0, l1, l2, l3, sb + bufb + OFF_VL + vrow * 144 + vcol * 2);
                MMA_BF16(O[2*dp][0], O[2*dp][1], O[2*dp][2], O[2*dp][3],
                         pahi[ks][0], pahi[ks][1], pahi[ks][2], pahi[ks][3], h0, h1);
                MMA_BF16(O[2*dp][0], O[2*dp][1], O[2*dp][2], O[2*dp][3],
                         pahi[ks][0], pahi[ks][1], pahi[ks][2], pahi[ks][3], l0, l1);
                MMA_BF16(O[2*dp][0], O[2*dp][1], O[2*dp][2], O[2*dp][3],
                         palo[ks][0], palo[ks][1], palo[ks][2], palo[ks][3], h0, h1);
                MMA_BF16(O[2*dp+1][0], O[2*dp+1][1], O[2*dp+1][2], O[2*dp+1][3],
                         pahi[ks][0], pahi[ks][1], pahi[ks][2], pahi[ks][3], h2, h3);
                MMA_BF16(O[2*dp+1][0], O[2*dp+1][1], O[2*dp+1][2], O[2*dp+1][3],
                         pahi[ks][0], pahi[ks][1], pahi[ks][2], pahi[ks][3], l2, l3);
                MMA_BF16(O[2*dp+1][0], O[2*dp+1][1], O[2*dp+1][2], O[2*dp+1][3],
                         palo[ks][0], palo[ks][1], palo[ks][2], palo[ks][3], h2, h3);
            }
        }
        // no trailing barrier needed: buffer `bufb` is only overwritten by the
        // prefetch issued at iteration it+2, which is behind it+1's barrier.
    }

    // ---- epilogue
    const float inv0 = 1.0f / lrow0;
    const float inv1 = 1.0f / lrow1;
    const int row0 = m0 + wm + g;
#pragma unroll
    for (int dt = 0; dt < 8; dt++) {
        int col = h * DK + dt * 8 + 2 * q;
        *(float2*)&ctx[((size_t)(b * MM + row0)) * DMOD + col] =
            make_float2(O[dt][0] * inv0, O[dt][1] * inv0);
        *(float2*)&ctx[((size_t)(b * MM + row0 + 8)) * DMOD + col] =
            make_float2(O[dt][2] * inv1, O[dt][3] * inv1);
    }
}

// ---------------------------------------------------------------------------
extern "C" void kernel_launch(void* const* d_in, const int* in_sizes, int n_in,
                              void* d_out, int out_size) {
    const float* q  = (const float*)d_in[0];
    const float* k  = (const float*)d_in[1];
    const float* v  = (const float*)d_in[2];
    const void*  mask_raw = d_in[3];
    const float* Wq = (const float*)d_in[4];
    const float* Wk = (const float*)d_in[5];
    const float* Wv = (const float*)d_in[6];
    const float* Wo = (const float*)d_in[7];
    float* out = (float*)d_out;

    void *Qp_, *Kp_, *Vp_, *ctx_, *mask_, *A3_, *W3_, *Kc_, *Vh_, *Vl_;
    cudaGetSymbolAddress(&Qp_,  g_Qp);
    cudaGetSymbolAddress(&Kp_,  g_Kp);
    cudaGetSymbolAddress(&Vp_,  g_Vp);
    cudaGetSymbolAddress(&ctx_, g_ctx);
    cudaGetSymbolAddress(&mask_, g_mask);
    cudaGetSymbolAddress(&A3_,  g_A3);
    cudaGetSymbolAddress(&W3_,  g_W3);
    cudaGetSymbolAddress(&Kc_,  g_Kc);
    cudaGetSymbolAddress(&Vh_,  g_Vh);
    cudaGetSymbolAddress(&Vl_,  g_Vl);
    float* Qp  = (float*)Qp_;
    float* Kp  = (float*)Kp_;
    float* Vp  = (float*)Vp_;
    float* ctx = (float*)ctx_;
    unsigned char* mask = (unsigned char*)mask_;
    __nv_bfloat16* A3 = (__nv_bfloat16*)A3_;
    __nv_bfloat16* W3 = (__nv_bfloat16*)W3_;
    __nv_bfloat16* Kc = (__nv_bfloat16*)Kc_;
    __nv_bfloat16* Vh = (__nv_bfloat16*)Vh_;
    __nv_bfloat16* Vl = (__nv_bfloat16*)Vl_;

    cudaFuncSetAttribute(attn_hmma,
                         cudaFuncAttributeMaxDynamicSharedMemorySize, A2_SMEM);

    // Normalize mask dtype -> uint8
    detect_mask<<<1, 1024>>>((const unsigned int*)mask_raw);
    const size_t mtotal = (size_t)BB * MM * NN;
    convert_mask<<<(unsigned)((mtotal + 511) / 512), 512>>>(mask_raw);

    const size_t act_elems = (size_t)(BB * MM) * DMOD;
    const size_t wgt_elems = (size_t)DMOD * DMOD;
    const unsigned actg = (unsigned)((act_elems + 255) / 256);
    const unsigned wgtg = (unsigned)((wgt_elems + 255) / 256);
    dim3 gridG(DMOD / 128, (BB * MM) / 128);             // (8, 32)

    split_act<<<actg, 256>>>(q, A3);
    split_wgt<<<wgtg, 256>>>(Wq, W3);
    gemm_hmma<<<gridG, 128>>>((const uint4*)A3, (const uint4*)W3, Qp);

    split_act<<<actg, 256>>>(k, A3);
    split_wgt<<<wgtg, 256>>>(Wk, W3);
    gemm_hmma<<<gridG, 128>>>((const uint4*)A3, (const uint4*)W3, Kp);

    split_act<<<actg, 256>>>(v, A3);
    split_wgt<<<wgtg, 256>>>(Wv, W3);
    gemm_hmma<<<gridG, 128>>>((const uint4*)A3, (const uint4*)W3, Vp);

    // Precompute head-major split K/V for attention
    split_kv<<<actg, 256>>>(Kp, Vp, Kc, Vh, Vl);

    dim3 gridA(MM / 128, BB * NH);                       // (16, 32)
    attn_hmma<<<gridA, 256, A2_SMEM>>>(Qp, Kc, Vh, Vl, mask, ctx);

    split_act<<<actg, 256>>>(ctx, A3);
    split_wgt<<<wgtg, 256>>>(Wo, W3);
    gemm_hmma<<<gridG, 128>>>((const uint4*)A3, (const uint4*)W3, out);
}

// round 11
// speedup vs baseline: 3.3065x; 1.0386x over previous
#include <cuda_runtime.h>
#include <cuda_bf16.h>
#include <cstdint>

// Problem constants
#define BB   2
#define MM   2048
#define NN   2048
#define DMOD 1024
#define NH   16
#define DK   64

#define KSPLIT (3 * DMOD)          // 3072: [hi|hi|lo] x [hi|lo|hi]
#define AS3 ((size_t)(BB * MM) * KSPLIT)
#define WS3 ((size_t)DMOD * KSPLIT)

// Scratch (device globals: allocation-free rule)
__device__ float g_Qp[BB * MM * DMOD];
__device__ float g_Kp[BB * NN * DMOD];
__device__ float g_Vp[BB * NN * DMOD];
__device__ float g_ctx[BB * MM * DMOD];
__device__ unsigned char g_mask[BB * (size_t)MM * NN];
__device__ int g_mask_kind;
__device__ __nv_bfloat16 g_A3[3 * ((size_t)(BB * MM) * KSPLIT)];   // 75 MB
__device__ __nv_bfloat16 g_W3[3 * ((size_t)DMOD * KSPLIT)];        // 19 MB
__device__ __nv_bfloat16 g_Kc[(size_t)BB * NH * NN * 192];         // 25 MB
__device__ __nv_bfloat16 g_Vh[(size_t)BB * NH * NN * DK];          // 8.4 MB
__device__ __nv_bfloat16 g_Vl[(size_t)BB * NH * NN * DK];          // 8.4 MB

// ---------------------------------------------------------------------------
// Helpers (sm_80-era: mma.sync + ldmatrix + cp.async; NO tcgen05 — harness
// PTX targets base sm_103 which rejects 'a' features)
// ---------------------------------------------------------------------------
__device__ __forceinline__ uint32_t cvta_s(const void* p) {
    uint32_t a;
    asm("{ .reg .u64 t; cvta.to.shared.u64 t, %1; cvt.u32.u64 %0, t; }"
        : "=r"(a) : "l"(p));
    return a;
}

#define LDSM_X4(r0, r1, r2, r3, a)                                            \
    asm volatile("ldmatrix.sync.aligned.m8n8.x4.shared.b16 {%0,%1,%2,%3}, [%4];" \
                 : "=r"(r0), "=r"(r1), "=r"(r2), "=r"(r3) : "r"(a))

#define LDSM_X4_T(r0, r1, r2, r3, a)                                          \
    asm volatile("ldmatrix.sync.aligned.m8n8.x4.trans.shared.b16 {%0,%1,%2,%3}, [%4];" \
                 : "=r"(r0), "=r"(r1), "=r"(r2), "=r"(r3) : "r"(a))

#define MMA_BF16(c0, c1, c2, c3, a0, a1, a2, a3, b0, b1)                      \
    asm volatile("mma.sync.aligned.m16n8k16.row.col.f32.bf16.bf16.f32 "       \
                 "{%0,%1,%2,%3}, {%4,%5,%6,%7}, {%8,%9}, {%0,%1,%2,%3};"      \
                 : "+f"(c0), "+f"(c1), "+f"(c2), "+f"(c3)                     \
                 : "r"(a0), "r"(a1), "r"(a2), "r"(a3), "r"(b0), "r"(b1))

#define CP_ASYNC16(s, g)                                                      \
    asm volatile("cp.async.cg.shared.global [%0], [%1], 16;" :: "r"(s), "l"(g))
#define CP_COMMIT() asm volatile("cp.async.commit_group;" ::: "memory")
#define CP_WAIT0()  asm volatile("cp.async.wait_group 0;" ::: "memory")
#define CP_WAIT1()  asm volatile("cp.async.wait_group 1;" ::: "memory")

__device__ __forceinline__ uint32_t pack_bf2(float a, float b) {
    __nv_bfloat162 h = __halves2bfloat162(__float2bfloat16(a), __float2bfloat16(b));
    return *(uint32_t*)&h;
}
__device__ __forceinline__ void split2(float a, float b, uint32_t& h, uint32_t& l) {
    __nv_bfloat16 ha = __float2bfloat16(a), hb = __float2bfloat16(b);
    h = pack_bf2(__bfloat162float(ha), __bfloat162float(hb));
    l = pack_bf2(a - __bfloat162float(ha), b - __bfloat162float(hb));
}

// ---------------------------------------------------------------------------
// Mask dtype detection + conversion (vectorized)
// ---------------------------------------------------------------------------
__global__ void detect_mask(const unsigned int* __restrict__ w) {
    __shared__ int s_not_int, s_not_float;
    if (threadIdx.x == 0) { s_not_int = 0; s_not_float = 0; }
    __syncthreads();
    int li = 0, lf = 0;
    for (int i = threadIdx.x; i < 65536; i += blockDim.x) {
        unsigned int x = w[i];
        if (x > 1u) li = 1;
        if (x != 0u && x != 0x3F800000u) lf = 1;
    }
    if (li) atomicOr(&s_not_int, 1);
    if (lf) atomicOr(&s_not_float, 1);
    __syncthreads();
    if (threadIdx.x == 0) {
        if (!s_not_int)        g_mask_kind = 1;
        else if (!s_not_float) g_mask_kind = 2;
        else                   g_mask_kind = 0;
    }
}

__global__ void convert_mask(const void* __restrict__ m) {
    size_t i = (size_t)blockIdx.x * blockDim.x + threadIdx.x;   // group of 4
    const size_t total = (size_t)BB * MM * NN / 4;
    if (i >= total) return;
    int kind = g_mask_kind;
    uchar4 o;
    if (kind == 1) {
        int4 v = ((const int4*)m)[i];
        o = make_uchar4(v.x != 0, v.y != 0, v.z != 0, v.w != 0);
    } else if (kind == 2) {
        float4 v = ((const float4*)m)[i];
        o = make_uchar4(v.x != 0.f, v.y != 0.f, v.z != 0.f, v.w != 0.f);
    } else {
        unsigned int v = ((const unsigned int*)m)[i];
        o = make_uchar4((v & 0xffu) != 0, ((v >> 8) & 0xffu) != 0,
                        ((v >> 16) & 0xffu) != 0, (v >> 24) != 0);
    }
    ((uchar4*)g_mask)[i] = o;
}

// ---------------------------------------------------------------------------
// Vectorized splits: 8 elements/thread
// ---------------------------------------------------------------------------
__global__ void split_act(const float* __restrict__ X, __nv_bfloat16* __restrict__ O) {
    size_t i = (size_t)blockIdx.x * blockDim.x + threadIdx.x;   // 8-el group
    const size_t NG = (size_t)(BB * MM) * DMOD / 8;
    if (i >= NG) return;
    int r = (int)(i >> 7);
    int c = (int)(i & 127) << 3;
    const float4* xp = (const float4*)(X + ((size_t)r << 10) + c);
    float4 x0 = xp[0], x1 = xp[1];
    uint4 HI, LO;
    split2(x0.x, x0.y, HI.x, LO.x);
    split2(x0.z, x0.w, HI.y, LO.y);
    split2(x1.x, x1.y, HI.z, LO.z);
    split2(x1.z, x1.w, HI.w, LO.w);
    __nv_bfloat16* base = O + (size_t)r * KSPLIT + c;
    *(uint4*)(base)        = HI;
    *(uint4*)(base + 1024) = HI;
    *(uint4*)(base + 2048) = LO;
}

__global__ void split_wgt(const float* __restrict__ W, __nv_bfloat16* __restrict__ O) {
    size_t i = (size_t)blockIdx.x * blockDim.x + threadIdx.x;
    const size_t NG = (size_t)DMOD * DMOD / 8;
    if (i >= NG) return;
    int r = (int)(i >> 7);
    int c = (int)(i & 127) << 3;
    const float4* xp = (const float4*)(W + ((size_t)r << 10) + c);
    float4 x0 = xp[0], x1 = xp[1];
    uint4 HI, LO;
    split2(x0.x, x0.y, HI.x, LO.x);
    split2(x0.z, x0.w, HI.y, LO.y);
    split2(x1.x, x1.y, HI.z, LO.z);
    split2(x1.z, x1.w, HI.w, LO.w);
    __nv_bfloat16* base = O + (size_t)r * KSPLIT + c;
    *(uint4*)(base)        = HI;
    *(uint4*)(base + 1024) = LO;
    *(uint4*)(base + 2048) = HI;
}

// split_kv: Kp/Vp [b, n, h*64+d] fp32 -> head-major split buffers (4 els/thread)
__global__ void split_kv(const float* __restrict__ Kp, const float* __restrict__ Vp,
                         __nv_bfloat16* __restrict__ Kc,
                         __nv_bfloat16* __restrict__ Vh,
                         __nv_bfloat16* __restrict__ Vl) {
    size_t i = (size_t)blockIdx.x * blockDim.x + threadIdx.x;   // 4-el group
    const size_t NG = (size_t)BB * NN * DMOD / 4;
    if (i >= NG) return;
    int bn = (int)(i >> 8);
    int c  = (int)(i & 255) << 2;
    int h = c >> 6, d = c & 63;
    int b = bn >> 11, n = bn & 2047;
    size_t hb = ((size_t)(b * NH + h)) * NN + n;
    float4 kx = *(const float4*)(Kp + ((size_t)bn << 10) + c);
    float4 vx = *(const float4*)(Vp + ((size_t)bn << 10) + c);
    uint2 KH, KL, VH, VL;
    split2(kx.x, kx.y, KH.x, KL.x);
    split2(kx.z, kx.w, KH.y, KL.y);
    split2(vx.x, vx.y, VH.x, VL.x);
    split2(vx.z, vx.w, VH.y, VL.y);
    *(uint2*)(Kc + hb * 192 + d)       = KH;
    *(uint2*)(Kc + hb * 192 + 64 + d)  = KL;
    *(uint2*)(Kc + hb * 192 + 128 + d) = KH;
    *(uint2*)(Vh + hb * DK + d) = VH;
    *(uint2*)(Vl + hb * DK + d) = VL;
}

// ---------------------------------------------------------------------------
// HMMA bf16 GEMM (R6 core); grid.z selects (A-region, W-region, C-output)
// ---------------------------------------------------------------------------
#define SROWB 80

__global__ void __launch_bounds__(128, 2) gemm_hmma(
        const uint4* __restrict__ A3,
        const uint4* __restrict__ B3,
        float* __restrict__ C0, float* __restrict__ C1, float* __restrict__ C2) {
    __shared__ __align__(16) char As[2][128 * SROWB];
    __shared__ __align__(16) char Bs[2][128 * SROWB];

    const int t = threadIdx.x;
    const int lane = t & 31, wid = t >> 5;
    const int m0 = blockIdx.y * 128, n0 = blockIdx.x * 128;
    const int z = blockIdx.z;
    const int wm = (wid & 1) * 64, wn = (wid >> 1) * 64;
    const int g = lane >> 2, tq = lane & 3;

    const uint4* Az = A3 + (size_t)z * (AS3 / 8);
    const uint4* Bz = B3 + (size_t)z * (WS3 / 8);
    float* C = (z == 0) ? C0 : (z == 1) ? C1 : C2;

    const uint4* arow = Az + (size_t)(m0 + t) * 384;
    const uint4* brow = Bz + (size_t)(n0 + t) * 384;
    const int swz = (t >> 3) & 3;

    uint4 pa[4], pb[4];
#pragma unroll
    for (int j = 0; j < 4; j++) { pa[j] = arow[j]; pb[j] = brow[j]; }
#pragma unroll
    for (int j = 0; j < 4; j++) {
        *(uint4*)(As[0] + t * SROWB + ((j ^ swz) << 4)) = pa[j];
        *(uint4*)(Bs[0] + t * SROWB + ((j ^ swz) << 4)) = pb[j];
    }
    __syncthreads();

    float c[4][8][4];
#pragma unroll
    for (int i = 0; i < 4; i++)
#pragma unroll
        for (int j = 0; j < 8; j++)
#pragma unroll
            for (int q = 0; q < 4; q++) c[i][j][q] = 0.f;

    const int jj = lane >> 3;
    const int r8 = lane & 7;

    for (int kc = 0; kc < 96; kc++) {
        const int buf = kc & 1;
        if (kc < 95) {
#pragma unroll
            for (int j = 0; j < 4; j++) {
                pa[j] = arow[(kc + 1) * 4 + j];
                pb[j] = brow[(kc + 1) * 4 + j];
            }
        }
        const char* Ab = As[buf];
        const char* Bb = Bs[buf];
#pragma unroll
        for (int ks = 0; ks < 2; ks++) {
            const int ku = ks * 2;
            uint32_t a[4][4], b[8][2];
#pragma unroll
            for (int mt = 0; mt < 4; mt++) {
                int r = wm + mt * 16 + ((jj & 1) << 3) + r8;
                int u = (ku + (jj >> 1)) ^ ((r >> 3) & 3);
                uint32_t ad = cvta_s(Ab + r * SROWB + (u << 4));
                LDSM_X4(a[mt][0], a[mt][1], a[mt][2], a[mt][3], ad);
            }
#pragma unroll
            for (int np = 0; np < 4; np++) {
                int r = wn + np * 16 + ((jj >> 1) << 3) + r8;
                int u = (ku + (jj & 1)) ^ ((r >> 3) & 3);
                uint32_t ad = cvta_s(Bb + r * SROWB + (u << 4));
                LDSM_X4(b[np * 2][0], b[np * 2][1], b[np * 2 + 1][0], b[np * 2 + 1][1], ad);
            }
#pragma unroll
            for (int mt = 0; mt < 4; mt++)
#pragma unroll
                for (int nt = 0; nt < 8; nt++)
                    MMA_BF16(c[mt][nt][0], c[mt][nt][1], c[mt][nt][2], c[mt][nt][3],
                             a[mt][0], a[mt][1], a[mt][2], a[mt][3],
                             b[nt][0], b[nt][1]);
        }
        __syncthreads();
        if (kc < 95) {
#pragma unroll
            for (int j = 0; j < 4; j++) {
                *(uint4*)(As[buf ^ 1] + t * SROWB + ((j ^ swz) << 4)) = pa[j];
                *(uint4*)(Bs[buf ^ 1] + t * SROWB + ((j ^ swz) << 4)) = pb[j];
            }
        }
        __syncthreads();
    }

#pragma unroll
    for (int mt = 0; mt < 4; mt++) {
        int row = m0 + wm + mt * 16 + g;
#pragma unroll
        for (int nt = 0; nt < 8; nt++) {
            int col = n0 + wn + nt * 8 + tq * 2;
            *(float2*)&C[(size_t)row * DMOD + col] =
                make_float2(c[mt][nt][0], c[mt][nt][1]);
            *(float2*)&C[(size_t)(row + 8) * DMOD + col] =
                make_float2(c[mt][nt][2], c[mt][nt][3]);
        }
    }
}

// ---------------------------------------------------------------------------
// HMMA flash attention, 3-stage cp.async pipeline, ILP-ordered MMA loops.
// ---------------------------------------------------------------------------
#define BUFSZ   52224
#define OFF_VH  25600               // [64][144B]
#define OFF_VL  34816               // [64][144B]
#define OFF_MSK 44032               // [128][64B]
#define A2_SMEM (3 * BUFSZ)         // 156672

__global__ void __launch_bounds__(256, 1) attn_hmma(
        const float* __restrict__ Qp,
        const __nv_bfloat16* __restrict__ Kc,
        const __nv_bfloat16* __restrict__ Vh,
        const __nv_bfloat16* __restrict__ Vl,
        const unsigned char* __restrict__ mask,
        float* __restrict__ ctx) {
    extern __shared__ char sm[];
    const uint32_t sb = cvta_s(sm);

    const int t = threadIdx.x;
    const int lane = t & 31, w = t >> 5;
    const int g = lane >> 2, q = lane & 3;
    const int bh = blockIdx.y;
    const int b = bh >> 4, h = bh & 15;
    const int bh2 = b * NH + h;
    const int m0 = blockIdx.x * 128;
    const int wm = w * 16;

    // ---- Phase 0: stage Qcat [128][400B] (overlays buffer 0), pull qf regs
    {
        const int row = t >> 1;
        const int cb = (t & 1) * 32;
        const float* qg = Qp + ((size_t)(b * MM + m0 + row)) * DMOD + h * DK + cb;
        __nv_bfloat16* qc = (__nv_bfloat16*)(sm) + row * 200;
#pragma unroll
        for (int i = 0; i < 8; i++) {
            float4 v = *(const float4*)(qg + 4 * i);
            float xs[4] = {v.x, v.y, v.z, v.w};
#pragma unroll
            for (int j = 0; j < 4; j++) {
                int c0 = cb + 4 * i + j;
                __nv_bfloat16 hi = __float2bfloat16(xs[j]);
                __nv_bfloat16 lo = __float2bfloat16(xs[j] - __bfloat162float(hi));
                qc[c0] = hi;
                qc[64 + c0] = hi;
                qc[128 + c0] = lo;
            }
        }
    }
    __syncthreads();

    uint32_t qf[12][4];
    {
        const int mt_ = lane >> 3, r8_ = lane & 7;
#pragma unroll
        for (int kp = 0; kp < 12; kp++) {
            uint32_t ad = sb + (uint32_t)((wm + (mt_ & 1) * 8 + r8_) * 400
                                          + (kp * 16 + (mt_ >> 1) * 8) * 2);
            LDSM_X4(qf[kp][0], qf[kp][1], qf[kp][2], qf[kp][3], ad);
        }
    }
    __syncthreads();   // staging area may now be overwritten

    // tile loader: 12 cp.async x 16B per thread
    auto load_tile = [&](int itn, uint32_t bufb) {
        const int n0g = itn * 64;
        const uint32_t sdst = sb + bufb;
        const char* kgb = (const char*)(Kc + ((size_t)bh2 * NN + n0g) * 192);
#pragma unroll
        for (int i = 0; i < 6; i++) {
            int e = t + i * 256;
            int row = e / 24, cc = e - row * 24;
            CP_ASYNC16(sdst + row * 400 + cc * 16, kgb + (size_t)row * 384 + cc * 16);
        }
        const char* vhb = (const char*)(Vh + ((size_t)bh2 * NN + n0g) * DK);
        const char* vlb = (const char*)(Vl + ((size_t)bh2 * NN + n0g) * DK);
#pragma unroll
        for (int i = 0; i < 2; i++) {
            int e = t + i * 256;
            int row = e >> 3, cc = e & 7;
            CP_ASYNC16(sdst + OFF_VH + row * 144 + cc * 16, vhb + row * 128 + cc * 16);
            CP_ASYNC16(sdst + OFF_VL + row * 144 + cc * 16, vlb + row * 128 + cc * 16);
        }
        const char* mb = (const char*)(mask + ((size_t)(b * MM + m0)) * NN + n0g);
#pragma unroll
        for (int i = 0; i < 2; i++) {
            int e = t + i * 256;
            int row = e >> 2, cc = e & 3;
            CP_ASYNC16(sdst + OFF_MSK + row * 64 + cc * 16, mb + (size_t)row * NN + cc * 16);
        }
    };

    float O[8][4];
#pragma unroll
    for (int i = 0; i < 8; i++)
#pragma unroll
        for (int j = 0; j < 4; j++) O[i][j] = 0.f;
    float mrow0 = -1e30f, mrow1 = -1e30f, lrow0 = 0.f, lrow1 = 0.f;

    const int mt = lane >> 3, r8 = lane & 7;

    load_tile(0, 0);
    CP_COMMIT();
    load_tile(1, BUFSZ);
    CP_COMMIT();

    for (int it = 0; it < 32; it++) {
        const uint32_t bufb = (uint32_t)(it % 3) * BUFSZ;
        if (it == 31) { CP_WAIT0(); } else { CP_WAIT1(); }
        __syncthreads();                    // tile it visible; compute(it-1) done everywhere
        if (it < 30) {
            load_tile(it + 2, (uint32_t)((it + 2) % 3) * BUFSZ);
            CP_COMMIT();
        }

        // ---- S = Qcat @ Kcat^T : kp outer, nt inner (8 independent accums)
        float S[8][4];
#pragma unroll
        for (int i = 0; i < 8; i++)
#pragma unroll
            for (int j = 0; j < 4; j++) S[i][j] = 0.f;

#pragma unroll
        for (int kp = 0; kp < 6; kp++) {
#pragma unroll
            for (int nt = 0; nt < 8; nt++) {
                uint32_t b0, b1, b2, b3;
                uint32_t ad = sb + bufb + (uint32_t)((nt * 8 + r8) * 400
                                                    + (kp * 32 + mt * 8) * 2);
                LDSM_X4(b0, b1, b2, b3, ad);
                MMA_BF16(S[nt][0], S[nt][1], S[nt][2], S[nt][3],
                         qf[2 * kp][0], qf[2 * kp][1], qf[2 * kp][2], qf[2 * kp][3],
                         b0, b1);
                MMA_BF16(S[nt][0], S[nt][1], S[nt][2], S[nt][3],
                         qf[2 * kp + 1][0], qf[2 * kp + 1][1], qf[2 * kp + 1][2], qf[2 * kp + 1][3],
                         b2, b3);
            }
        }

        // ---- mask + scale (matches ref: (mask ? -1e9 : s) * 0.125)
        const char* mbuf = sm + bufb + OFF_MSK;
#pragma unroll
        for (int nt = 0; nt < 8; nt++) {
            unsigned short mA = *(const unsigned short*)(mbuf + (wm + g) * 64 + nt * 8 + 2 * q);
            unsigned short mB = *(const unsigned short*)(mbuf + (wm + g + 8) * 64 + nt * 8 + 2 * q);
            S[nt][0] = (mA & 0xff) ? -1.25e8f : S[nt][0] * 0.125f;
            S[nt][1] = (mA >> 8)   ? -1.25e8f : S[nt][1] * 0.125f;
            S[nt][2] = (mB & 0xff) ? -1.25e8f : S[nt][2] * 0.125f;
            S[nt][3] = (mB >> 8)   ? -1.25e8f : S[nt][3] * 0.125f;
        }

        // ---- online softmax
        float mx0 = -1e30f, mx1 = -1e30f;
#pragma unroll
        for (int nt = 0; nt < 8; nt++) {
            mx0 = fmaxf(mx0, fmaxf(S[nt][0], S[nt][1]));
            mx1 = fmaxf(mx1, fmaxf(S[nt][2], S[nt][3]));
        }
        mx0 = fmaxf(mx0, __shfl_xor_sync(0xffffffffu, mx0, 1));
        mx0 = fmaxf(mx0, __shfl_xor_sync(0xffffffffu, mx0, 2));
        mx1 = fmaxf(mx1, __shfl_xor_sync(0xffffffffu, mx1, 1));
        mx1 = fmaxf(mx1, __shfl_xor_sync(0xffffffffu, mx1, 2));
        const float nm0 = fmaxf(mrow0, mx0);
        const float nm1 = fmaxf(mrow1, mx1);
        const float c0 = __expf(mrow0 - nm0);
        const float c1 = __expf(mrow1 - nm1);
        mrow0 = nm0; mrow1 = nm1;

        float s0 = 0.f, s1 = 0.f;
        uint32_t pahi[4][4], palo[4][4];
#pragma unroll
        for (int nt = 0; nt < 8; nt++) {
            float p0 = __expf(S[nt][0] - nm0);
            float p1 = __expf(S[nt][1] - nm0);
            float p2 = __expf(S[nt][2] - nm1);
            float p3 = __expf(S[nt][3] - nm1);
            s0 += p0 + p1;
            s1 += p2 + p3;
            float h0 = __bfloat162float(__float2bfloat16(p0));
            float h1 = __bfloat162float(__float2bfloat16(p1));
            float h2 = __bfloat162float(__float2bfloat16(p2));
            float h3 = __bfloat162float(__float2bfloat16(p3));
            const int ks = nt >> 1;
            const int hv = (nt & 1) * 2;
            pahi[ks][hv]     = pack_bf2(h0, h1);
            pahi[ks][hv + 1] = pack_bf2(h2, h3);
            palo[ks][hv]     = pack_bf2(p0 - h0, p1 - h1);
            palo[ks][hv + 1] = pack_bf2(p2 - h2, p3 - h3);
        }
        s0 += __shfl_xor_sync(0xffffffffu, s0, 1);
        s0 += __shfl_xor_sync(0xffffffffu, s0, 2);
        s1 += __shfl_xor_sync(0xffffffffu, s1, 1);
        s1 += __shfl_xor_sync(0xffffffffu, s1, 2);
        lrow0 = lrow0 * c0 + s0;
        lrow1 = lrow1 * c1 + s1;

#pragma unroll
        for (int dt = 0; dt < 8; dt++) {
            O[dt][0] *= c0; O[dt][1] *= c0;
            O[dt][2] *= c1; O[dt][3] *= c1;
        }

        // ---- O += P @ V : per ks, load all V frags, then term-major MMAs
#pragma unroll
        for (int ks = 0; ks < 4; ks++) {
            uint32_t vh_[4][4], vl_[4][4];
            const uint32_t vrow = (uint32_t)(ks * 16 + (mt & 1) * 8 + r8);
#pragma unroll
            for (int dp = 0; dp < 4; dp++) {
                const uint32_t vcol = (uint32_t)(dp * 16 + (mt >> 1) * 8);
                LDSM_X4_T(vh_[dp][0], vh_[dp][1], vh_[dp][2], vh_[dp][3],
                          sb + bufb + OFF_VH + vrow * 144 + vcol * 2);
                LDSM_X4_T(vl_[dp][0], vl_[dp][1], vl_[dp][2], vl_[dp][3],
                          sb + bufb + OFF_VL + vrow * 144 + vcol * 2);
            }
#pragma unroll
            for (int dp = 0; dp < 4; dp++) {
                MMA_BF16(O[2*dp][0], O[2*dp][1], O[2*dp][2], O[2*dp][3],
                         pahi[ks][0], pahi[ks][1], pahi[ks][2], pahi[ks][3],
                         vh_[dp][0], vh_[dp][1]);
                MMA_BF16(O[2*dp+1][0], O[2*dp+1][1], O[2*dp+1][2], O[2*dp+1][3],
                         pahi[ks][0], pahi[ks][1], pahi[ks][2], pahi[ks][3],
                         vh_[dp][2], vh_[dp][3]);
            }
#pragma unroll
            for (int dp = 0; dp < 4; dp++) {
                MMA_BF16(O[2*dp][0], O[2*dp][1], O[2*dp][2], O[2*dp][3],
                         pahi[ks][0], pahi[ks][1], pahi[ks][2], pahi[ks][3],
                         vl_[dp][0], vl_[dp][1]);
                MMA_BF16(O[2*dp+1][0], O[2*dp+1][1], O[2*dp+1][2], O[2*dp+1][3],
                         pahi[ks][0], pahi[ks][1], pahi[ks][2], pahi[ks][3],
                         vl_[dp][2], vl_[dp][3]);
            }
#pragma unroll
            for (int dp = 0; dp < 4; dp++) {
                MMA_BF16(O[2*dp][0], O[2*dp][1], O[2*dp][2], O[2*dp][3],
                         palo[ks][0], palo[ks][1], palo[ks][2], palo[ks][3],
                         vh_[dp][0], vh_[dp][1]);
                MMA_BF16(O[2*dp+1][0], O[2*dp+1][1], O[2*dp+1][2], O[2*dp+1][3],
                         palo[ks][0], palo[ks][1], palo[ks][2], palo[ks][3],
                         vh_[dp][2], vh_[dp][3]);
            }
        }
    }

    // ---- epilogue
    const float inv0 = 1.0f / lrow0;
    const float inv1 = 1.0f / lrow1;
    const int row0 = m0 + wm + g;
#pragma unroll
    for (int dt = 0; dt < 8; dt++) {
        int col = h * DK + dt * 8 + 2 * q;
        *(float2*)&ctx[((size_t)(b * MM + row0)) * DMOD + col] =
            make_float2(O[dt][0] * inv0, O[dt][1] * inv0);
        *(float2*)&ctx[((size_t)(b * MM + row0 + 8)) * DMOD + col] =
            make_float2(O[dt][2] * inv1, O[dt][3] * inv1);
    }
}

// ---------------------------------------------------------------------------
extern "C" void kernel_launch(void* const* d_in, const int* in_sizes, int n_in,
                              void* d_out, int out_size) {
    const float* q  = (const float*)d_in[0];
    const float* k  = (const float*)d_in[1];
    const float* v  = (const float*)d_in[2];
    const void*  mask_raw = d_in[3];
    const float* Wq = (const float*)d_in[4];
    const float* Wk = (const float*)d_in[5];
    const float* Wv = (const float*)d_in[6];
    const float* Wo = (const float*)d_in[7];
    float* out = (float*)d_out;

    void *Qp_, *Kp_, *Vp_, *ctx_, *mask_, *A3_, *W3_, *Kc_, *Vh_, *Vl_;
    cudaGetSymbolAddress(&Qp_,  g_Qp);
    cudaGetSymbolAddress(&Kp_,  g_Kp);
    cudaGetSymbolAddress(&Vp_,  g_Vp);
    cudaGetSymbolAddress(&ctx_, g_ctx);
    cudaGetSymbolAddress(&mask_, g_mask);
    cudaGetSymbolAddress(&A3_,  g_A3);
    cudaGetSymbolAddress(&W3_,  g_W3);
    cudaGetSymbolAddress(&Kc_,  g_Kc);
    cudaGetSymbolAddress(&Vh_,  g_Vh);
    cudaGetSymbolAddress(&Vl_,  g_Vl);
    float* Qp  = (float*)Qp_;
    float* Kp  = (float*)Kp_;
    float* Vp  = (float*)Vp_;
    float* ctx = (float*)ctx_;
    unsigned char* mask = (unsigned char*)mask_;
    __nv_bfloat16* A3 = (__nv_bfloat16*)A3_;
    __nv_bfloat16* W3 = (__nv_bfloat16*)W3_;
    __nv_bfloat16* Kc = (__nv_bfloat16*)Kc_;
    __nv_bfloat16* Vh = (__nv_bfloat16*)Vh_;
    __nv_bfloat16* Vl = (__nv_bfloat16*)Vl_;

    cudaFuncSetAttribute(attn_hmma,
                         cudaFuncAttributeMaxDynamicSharedMemorySize, A2_SMEM);

    // Normalize mask dtype -> uint8
    detect_mask<<<1, 1024>>>((const unsigned int*)mask_raw);
    convert_mask<<<(unsigned)(((size_t)BB * MM * NN / 4 + 255) / 256), 256>>>(mask_raw);

    const unsigned actg = (unsigned)(((size_t)(BB * MM) * DMOD / 8 + 255) / 256);
    const unsigned wgtg = (unsigned)(((size_t)DMOD * DMOD / 8 + 255) / 256);
    const unsigned kvg  = (unsigned)(((size_t)BB * NN * DMOD / 4 + 255) / 256);

    // Stage all three input projections, run as one batched GEMM launch
    split_act<<<actg, 256>>>(q, A3);
    split_act<<<actg, 256>>>(k, A3 + AS3);
    split_act<<<actg, 256>>>(v, A3 + 2 * AS3);
    split_wgt<<<wgtg, 256>>>(Wq, W3);
    split_wgt<<<wgtg, 256>>>(Wk, W3 + WS3);
    split_wgt<<<wgtg, 256>>>(Wv, W3 + 2 * WS3);

    dim3 gridG3(DMOD / 128, (BB * MM) / 128, 3);        // (8, 32, 3)
    gemm_hmma<<<gridG3, 128>>>((const uint4*)A3, (const uint4*)W3, Qp, Kp, Vp);

    // Precompute head-major split K/V for attention
    split_kv<<<kvg, 256>>>(Kp, Vp, Kc, Vh, Vl);

    dim3 gridA(MM / 128, BB * NH);                      // (16, 32)
    attn_hmma<<<gridA, 256, A2_SMEM>>>(Qp, Kc, Vh, Vl, mask, ctx);

    // out = ctx @ Wo^T
    split_act<<<actg, 256>>>(ctx, A3);
    split_wgt<<<wgtg, 256>>>(Wo, W3);
    dim3 gridG(DMOD / 128, (BB * MM) / 128, 1);
    gemm_hmma<<<gridG, 128>>>((const uint4*)A3, (const uint4*)W3, out, out, out);
}

// round 12
// speedup vs baseline: 3.4322x; 1.0380x over previous
#include <cuda_runtime.h>
#include <cuda_bf16.h>
#include <cstdint>

// Problem constants
#define BB   2
#define MM   2048
#define NN   2048
#define DMOD 1024
#define NH   16
#define DK   64

#define KSPLIT (3 * DMOD)          // 3072: [hi|hi|lo] x [hi|lo|hi]
#define AS3 ((size_t)(BB * MM) * KSPLIT)
#define WS3 ((size_t)DMOD * KSPLIT)

// Scratch (device globals: allocation-free rule)
__device__ float g_Qp[BB * MM * DMOD];
__device__ float g_Kp[BB * NN * DMOD];
__device__ float g_Vp[BB * NN * DMOD];
__device__ float g_ctx[BB * MM * DMOD];
__device__ unsigned char g_mask[BB * (size_t)MM * NN];
__device__ int g_mask_kind;
__device__ __nv_bfloat16 g_A3[3 * ((size_t)(BB * MM) * KSPLIT)];   // 75 MB
__device__ __nv_bfloat16 g_W3[3 * ((size_t)DMOD * KSPLIT)];        // 19 MB
__device__ __nv_bfloat16 g_Kc[(size_t)BB * NH * NN * 192];         // 25 MB
__device__ __nv_bfloat16 g_Vh[(size_t)BB * NH * NN * DK];          // 8.4 MB
__device__ __nv_bfloat16 g_Vl[(size_t)BB * NH * NN * DK];          // 8.4 MB

// ---------------------------------------------------------------------------
// Helpers (sm_80-era: mma.sync + ldmatrix + cp.async; NO tcgen05 — harness
// PTX targets base sm_103 which rejects 'a' features)
// ---------------------------------------------------------------------------
__device__ __forceinline__ uint32_t cvta_s(const void* p) {
    uint32_t a;
    asm("{ .reg .u64 t; cvta.to.shared.u64 t, %1; cvt.u32.u64 %0, t; }"
        : "=r"(a) : "l"(p));
    return a;
}

#define LDSM_X4(r0, r1, r2, r3, a)                                            \
    asm volatile("ldmatrix.sync.aligned.m8n8.x4.shared.b16 {%0,%1,%2,%3}, [%4];" \
                 : "=r"(r0), "=r"(r1), "=r"(r2), "=r"(r3) : "r"(a))

#define LDSM_X4_T(r0, r1, r2, r3, a)                                          \
    asm volatile("ldmatrix.sync.aligned.m8n8.x4.trans.shared.b16 {%0,%1,%2,%3}, [%4];" \
                 : "=r"(r0), "=r"(r1), "=r"(r2), "=r"(r3) : "r"(a))

#define MMA_BF16(c0, c1, c2, c3, a0, a1, a2, a3, b0, b1)                      \
    asm volatile("mma.sync.aligned.m16n8k16.row.col.f32.bf16.bf16.f32 "       \
                 "{%0,%1,%2,%3}, {%4,%5,%6,%7}, {%8,%9}, {%0,%1,%2,%3};"      \
                 : "+f"(c0), "+f"(c1), "+f"(c2), "+f"(c3)                     \
                 : "r"(a0), "r"(a1), "r"(a2), "r"(a3), "r"(b0), "r"(b1))

#define CP_ASYNC16(s, g)                                                      \
    asm volatile("cp.async.cg.shared.global [%0], [%1], 16;" :: "r"(s), "l"(g))
#define CP_COMMIT() asm volatile("cp.async.commit_group;" ::: "memory")
#define CP_WAIT0()  asm volatile("cp.async.wait_group 0;" ::: "memory")
#define CP_WAIT1()  asm volatile("cp.async.wait_group 1;" ::: "memory")
#define CP_WAIT2()  asm volatile("cp.async.wait_group 2;" ::: "memory")

__device__ __forceinline__ uint32_t pack_bf2(float a, float b) {
    __nv_bfloat162 h = __halves2bfloat162(__float2bfloat16(a), __float2bfloat16(b));
    return *(uint32_t*)&h;
}
__device__ __forceinline__ void split2(float a, float b, uint32_t& h, uint32_t& l) {
    __nv_bfloat16 ha = __float2bfloat16(a), hb = __float2bfloat16(b);
    h = pack_bf2(__bfloat162float(ha), __bfloat162float(hb));
    l = pack_bf2(a - __bfloat162float(ha), b - __bfloat162float(hb));
}

// ---------------------------------------------------------------------------
// Mask dtype detection + conversion (vectorized, known-good)
// ---------------------------------------------------------------------------
__global__ void detect_mask(const unsigned int* __restrict__ w) {
    __shared__ int s_not_int, s_not_float;
    if (threadIdx.x == 0) { s_not_int = 0; s_not_float = 0; }
    __syncthreads();
    int li = 0, lf = 0;
    for (int i = threadIdx.x; i < 65536; i += blockDim.x) {
        unsigned int x = w[i];
        if (x > 1u) li = 1;
        if (x != 0u && x != 0x3F800000u) lf = 1;
    }
    if (li) atomicOr(&s_not_int, 1);
    if (lf) atomicOr(&s_not_float, 1);
    __syncthreads();
    if (threadIdx.x == 0) {
        if (!s_not_int)        g_mask_kind = 1;
        else if (!s_not_float) g_mask_kind = 2;
        else                   g_mask_kind = 0;
    }
}

__global__ void convert_mask(const void* __restrict__ m) {
    size_t i = (size_t)blockIdx.x * blockDim.x + threadIdx.x;
    const size_t total = (size_t)BB * MM * NN / 4;
    if (i >= total) return;
    int kind = g_mask_kind;
    uchar4 o;
    if (kind == 1) {
        int4 v = ((const int4*)m)[i];
        o = make_uchar4(v.x != 0, v.y != 0, v.z != 0, v.w != 0);
    } else if (kind == 2) {
        float4 v = ((const float4*)m)[i];
        o = make_uchar4(v.x != 0.f, v.y != 0.f, v.z != 0.f, v.w != 0.f);
    } else {
        unsigned int v = ((const unsigned int*)m)[i];
        o = make_uchar4((v & 0xffu) != 0, ((v >> 8) & 0xffu) != 0,
                        ((v >> 16) & 0xffu) != 0, (v >> 24) != 0);
    }
    ((uchar4*)g_mask)[i] = o;
}

// ---------------------------------------------------------------------------
// Vectorized splits
// ---------------------------------------------------------------------------
__global__ void split_act(const float* __restrict__ X, __nv_bfloat16* __restrict__ O) {
    size_t i = (size_t)blockIdx.x * blockDim.x + threadIdx.x;
    const size_t NG = (size_t)(BB * MM) * DMOD / 8;
    if (i >= NG) return;
    int r = (int)(i >> 7);
    int c = (int)(i & 127) << 3;
    const float4* xp = (const float4*)(X + ((size_t)r << 10) + c);
    float4 x0 = xp[0], x1 = xp[1];
    uint4 HI, LO;
    split2(x0.x, x0.y, HI.x, LO.x);
    split2(x0.z, x0.w, HI.y, LO.y);
    split2(x1.x, x1.y, HI.z, LO.z);
    split2(x1.z, x1.w, HI.w, LO.w);
    __nv_bfloat16* base = O + (size_t)r * KSPLIT + c;
    *(uint4*)(base)        = HI;
    *(uint4*)(base + 1024) = HI;
    *(uint4*)(base + 2048) = LO;
}

__global__ void split_wgt(const float* __restrict__ W, __nv_bfloat16* __restrict__ O) {
    size_t i = (size_t)blockIdx.x * blockDim.x + threadIdx.x;
    const size_t NG = (size_t)DMOD * DMOD / 8;
    if (i >= NG) return;
    int r = (int)(i >> 7);
    int c = (int)(i & 127) << 3;
    const float4* xp = (const float4*)(W + ((size_t)r << 10) + c);
    float4 x0 = xp[0], x1 = xp[1];
    uint4 HI, LO;
    split2(x0.x, x0.y, HI.x, LO.x);
    split2(x0.z, x0.w, HI.y, LO.y);
    split2(x1.x, x1.y, HI.z, LO.z);
    split2(x1.z, x1.w, HI.w, LO.w);
    __nv_bfloat16* base = O + (size_t)r * KSPLIT + c;
    *(uint4*)(base)        = HI;
    *(uint4*)(base + 1024) = LO;
    *(uint4*)(base + 2048) = HI;
}

__global__ void split_kv(const float* __restrict__ Kp, const float* __restrict__ Vp,
                         __nv_bfloat16* __restrict__ Kc,
                         __nv_bfloat16* __restrict__ Vh,
                         __nv_bfloat16* __restrict__ Vl) {
    size_t i = (size_t)blockIdx.x * blockDim.x + threadIdx.x;
    const size_t NG = (size_t)BB * NN * DMOD / 4;
    if (i >= NG) return;
    int bn = (int)(i >> 8);
    int c  = (int)(i & 255) << 2;
    int h = c >> 6, d = c & 63;
    int b = bn >> 11, n = bn & 2047;
    size_t hb = ((size_t)(b * NH + h)) * NN + n;
    float4 kx = *(const float4*)(Kp + ((size_t)bn << 10) + c);
    float4 vx = *(const float4*)(Vp + ((size_t)bn << 10) + c);
    uint2 KH, KL, VH, VL;
    split2(kx.x, kx.y, KH.x, KL.x);
    split2(kx.z, kx.w, KH.y, KL.y);
    split2(vx.x, vx.y, VH.x, VL.x);
    split2(vx.z, vx.w, VH.y, VL.y);
    *(uint2*)(Kc + hb * 192 + d)       = KH;
    *(uint2*)(Kc + hb * 192 + 64 + d)  = KL;
    *(uint2*)(Kc + hb * 192 + 128 + d) = KH;
    *(uint2*)(Vh + hb * DK + d) = VH;
    *(uint2*)(Vl + hb * DK + d) = VL;
}

// ---------------------------------------------------------------------------
// HMMA bf16 GEMM, 4-stage cp.async pipeline. grid.z selects operand region.
// CTA 128x128, 128 threads, 4 warps of 64x64, BK=32.
// ---------------------------------------------------------------------------
#define SROWB  80
#define GSTAGE (128 * SROWB * 2)          // A+B tile per stage: 20480 B
#define G_SMEM (4 * GSTAGE)               // 81920 B

__global__ void __launch_bounds__(128, 2) gemm_hmma(
        const uint4* __restrict__ A3,
        const uint4* __restrict__ B3,
        float* __restrict__ C0, float* __restrict__ C1, float* __restrict__ C2) {
    extern __shared__ char gsm[];
    const uint32_t sb = cvta_s(gsm);

    const int t = threadIdx.x;
    const int lane = t & 31, wid = t >> 5;
    const int m0 = blockIdx.y * 128, n0 = blockIdx.x * 128;
    const int z = blockIdx.z;
    const int wm = (wid & 1) * 64, wn = (wid >> 1) * 64;
    const int g = lane >> 2, tq = lane & 3;

    const uint4* Az = A3 + (size_t)z * (AS3 / 8);
    const uint4* Bz = B3 + (size_t)z * (WS3 / 8);
    float* C = (z == 0) ? C0 : (z == 1) ? C1 : C2;

    const uint4* arow = Az + (size_t)(m0 + t) * 384;
    const uint4* brow = Bz + (size_t)(n0 + t) * 384;
    const int swz = (t >> 3) & 3;
    const uint32_t strow = (uint32_t)(t * SROWB);

    // issue one stage's loads (A+B tile, 8 x cp.async.16 per thread)
    auto load_stage = [&](int kc, int stg) {
        const uint32_t sa = sb + (uint32_t)stg * GSTAGE;
        const uint32_t sbB = sa + 128 * SROWB;
        const uint4* ap = arow + kc * 4;
        const uint4* bp = brow + kc * 4;
#pragma unroll
        for (int j = 0; j < 4; j++) {
            uint32_t off = strow + (uint32_t)((j ^ swz) << 4);
            CP_ASYNC16(sa + off, (const char*)(ap + j));
            CP_ASYNC16(sbB + off, (const char*)(bp + j));
        }
    };

    load_stage(0, 0); CP_COMMIT();
    load_stage(1, 1); CP_COMMIT();
    load_stage(2, 2); CP_COMMIT();

    float c[4][8][4];
#pragma unroll
    for (int i = 0; i < 4; i++)
#pragma unroll
        for (int j = 0; j < 8; j++)
#pragma unroll
            for (int q = 0; q < 4; q++) c[i][j][q] = 0.f;

    const int jj = lane >> 3;
    const int r8 = lane & 7;

    for (int kc = 0; kc < 96; kc++) {
        CP_WAIT2();
        __syncthreads();                  // stage kc ready; compute(kc-1) done
        if (kc < 93) load_stage(kc + 3, (kc + 3) & 3);
        CP_COMMIT();                      // commit every iter (may be empty)

        const char* Ab = gsm + (kc & 3) * GSTAGE;
        const char* Bb = Ab + 128 * SROWB;
#pragma unroll
        for (int ks = 0; ks < 2; ks++) {
            const int ku = ks * 2;
            uint32_t a[4][4], b[8][2];
#pragma unroll
            for (int mt = 0; mt < 4; mt++) {
                int r = wm + mt * 16 + ((jj & 1) << 3) + r8;
                int u = (ku + (jj >> 1)) ^ ((r >> 3) & 3);
                uint32_t ad = cvta_s(Ab + r * SROWB + (u << 4));
                LDSM_X4(a[mt][0], a[mt][1], a[mt][2], a[mt][3], ad);
            }
#pragma unroll
            for (int np = 0; np < 4; np++) {
                int r = wn + np * 16 + ((jj >> 1) << 3) + r8;
                int u = (ku + (jj & 1)) ^ ((r >> 3) & 3);
                uint32_t ad = cvta_s(Bb + r * SROWB + (u << 4));
                LDSM_X4(b[np * 2][0], b[np * 2][1], b[np * 2 + 1][0], b[np * 2 + 1][1], ad);
            }
#pragma unroll
            for (int mt = 0; mt < 4; mt++)
#pragma unroll
                for (int nt = 0; nt < 8; nt++)
                    MMA_BF16(c[mt][nt][0], c[mt][nt][1], c[mt][nt][2], c[mt][nt][3],
                             a[mt][0], a[mt][1], a[mt][2], a[mt][3],
                             b[nt][0], b[nt][1]);
        }
    }

#pragma unroll
    for (int mt = 0; mt < 4; mt++) {
        int row = m0 + wm + mt * 16 + g;
#pragma unroll
        for (int nt = 0; nt < 8; nt++) {
            int col = n0 + wn + nt * 8 + tq * 2;
            *(float2*)&C[(size_t)row * DMOD + col] =
                make_float2(c[mt][nt][0], c[mt][nt][1]);
            *(float2*)&C[(size_t)(row + 8) * DMOD + col] =
                make_float2(c[mt][nt][2], c[mt][nt][3]);
        }
    }
}

// ---------------------------------------------------------------------------
// HMMA flash attention (unchanged from R11, passing)
// ---------------------------------------------------------------------------
#define BUFSZ   52224
#define OFF_VH  25600
#define OFF_VL  34816
#define OFF_MSK 44032
#define A2_SMEM (3 * BUFSZ)

__global__ void __launch_bounds__(256, 1) attn_hmma(
        const float* __restrict__ Qp,
        const __nv_bfloat16* __restrict__ Kc,
        const __nv_bfloat16* __restrict__ Vh,
        const __nv_bfloat16* __restrict__ Vl,
        const unsigned char* __restrict__ mask,
        float* __restrict__ ctx) {
    extern __shared__ char sm[];
    const uint32_t sb = cvta_s(sm);

    const int t = threadIdx.x;
    const int lane = t & 31, w = t >> 5;
    const int g = lane >> 2, q = lane & 3;
    const int bh = blockIdx.y;
    const int b = bh >> 4, h = bh & 15;
    const int bh2 = b * NH + h;
    const int m0 = blockIdx.x * 128;
    const int wm = w * 16;

    {
        const int row = t >> 1;
        const int cb = (t & 1) * 32;
        const float* qg = Qp + ((size_t)(b * MM + m0 + row)) * DMOD + h * DK + cb;
        __nv_bfloat16* qc = (__nv_bfloat16*)(sm) + row * 200;
#pragma unroll
        for (int i = 0; i < 8; i++) {
            float4 v = *(const float4*)(qg + 4 * i);
            float xs[4] = {v.x, v.y, v.z, v.w};
#pragma unroll
            for (int j = 0; j < 4; j++) {
                int c0 = cb + 4 * i + j;
                __nv_bfloat16 hi = __float2bfloat16(xs[j]);
                __nv_bfloat16 lo = __float2bfloat16(xs[j] - __bfloat162float(hi));
                qc[c0] = hi;
                qc[64 + c0] = hi;
                qc[128 + c0] = lo;
            }
        }
    }
    __syncthreads();

    uint32_t qf[12][4];
    {
        const int mt_ = lane >> 3, r8_ = lane & 7;
#pragma unroll
        for (int kp = 0; kp < 12; kp++) {
            uint32_t ad = sb + (uint32_t)((wm + (mt_ & 1) * 8 + r8_) * 400
                                          + (kp * 16 + (mt_ >> 1) * 8) * 2);
            LDSM_X4(qf[kp][0], qf[kp][1], qf[kp][2], qf[kp][3], ad);
        }
    }
    __syncthreads();

    auto load_tile = [&](int itn, uint32_t bufb) {
        const int n0g = itn * 64;
        const uint32_t sdst = sb + bufb;
        const char* kgb = (const char*)(Kc + ((size_t)bh2 * NN + n0g) * 192);
#pragma unroll
        for (int i = 0; i < 6; i++) {
            int e = t + i * 256;
            int row = e / 24, cc = e - row * 24;
            CP_ASYNC16(sdst + row * 400 + cc * 16, kgb + (size_t)row * 384 + cc * 16);
        }
        const char* vhb = (const char*)(Vh + ((size_t)bh2 * NN + n0g) * DK);
        const char* vlb = (const char*)(Vl + ((size_t)bh2 * NN + n0g) * DK);
#pragma unroll
        for (int i = 0; i < 2; i++) {
            int e = t + i * 256;
            int row = e >> 3, cc = e & 7;
            CP_ASYNC16(sdst + OFF_VH + row * 144 + cc * 16, vhb + row * 128 + cc * 16);
            CP_ASYNC16(sdst + OFF_VL + row * 144 + cc * 16, vlb + row * 128 + cc * 16);
        }
        const char* mb = (const char*)(mask + ((size_t)(b * MM + m0)) * NN + n0g);
#pragma unroll
        for (int i = 0; i < 2; i++) {
            int e = t + i * 256;
            int row = e >> 2, cc = e & 3;
            CP_ASYNC16(sdst + OFF_MSK + row * 64 + cc * 16, mb + (size_t)row * NN + cc * 16);
        }
    };

    float O[8][4];
#pragma unroll
    for (int i = 0; i < 8; i++)
#pragma unroll
        for (int j = 0; j < 4; j++) O[i][j] = 0.f;
    float mrow0 = -1e30f, mrow1 = -1e30f, lrow0 = 0.f, lrow1 = 0.f;

    const int mt = lane >> 3, r8 = lane & 7;

    load_tile(0, 0);
    CP_COMMIT();
    load_tile(1, BUFSZ);
    CP_COMMIT();

    for (int it = 0; it < 32; it++) {
        const uint32_t bufb = (uint32_t)(it % 3) * BUFSZ;
        if (it == 31) { CP_WAIT0(); } else { CP_WAIT1(); }
        __syncthreads();
        if (it < 30) {
            load_tile(it + 2, (uint32_t)((it + 2) % 3) * BUFSZ);
            CP_COMMIT();
        }

        float S[8][4];
#pragma unroll
        for (int i = 0; i < 8; i++)
#pragma unroll
            for (int j = 0; j < 4; j++) S[i][j] = 0.f;

#pragma unroll
        for (int kp = 0; kp < 6; kp++) {
#pragma unroll
            for (int nt = 0; nt < 8; nt++) {
                uint32_t b0, b1, b2, b3;
                uint32_t ad = sb + bufb + (uint32_t)((nt * 8 + r8) * 400
                                                    + (kp * 32 + mt * 8) * 2);
                LDSM_X4(b0, b1, b2, b3, ad);
                MMA_BF16(S[nt][0], S[nt][1], S[nt][2], S[nt][3],
                         qf[2 * kp][0], qf[2 * kp][1], qf[2 * kp][2], qf[2 * kp][3],
                         b0, b1);
                MMA_BF16(S[nt][0], S[nt][1], S[nt][2], S[nt][3],
                         qf[2 * kp + 1][0], qf[2 * kp + 1][1], qf[2 * kp + 1][2], qf[2 * kp + 1][3],
                         b2, b3);
            }
        }

        const char* mbuf = sm + bufb + OFF_MSK;
#pragma unroll
        for (int nt = 0; nt < 8; nt++) {
            unsigned short mA = *(const unsigned short*)(mbuf + (wm + g) * 64 + nt * 8 + 2 * q);
            unsigned short mB = *(const unsigned short*)(mbuf + (wm + g + 8) * 64 + nt * 8 + 2 * q);
            S[nt][0] = (mA & 0xff) ? -1.25e8f : S[nt][0] * 0.125f;
            S[nt][1] = (mA >> 8)   ? -1.25e8f : S[nt][1] * 0.125f;
            S[nt][2] = (mB & 0xff) ? -1.25e8f : S[nt][2] * 0.125f;
            S[nt][3] = (mB >> 8)   ? -1.25e8f : S[nt][3] * 0.125f;
        }

        float mx0 = -1e30f, mx1 = -1e30f;
#pragma unroll
        for (int nt = 0; nt < 8; nt++) {
            mx0 = fmaxf(mx0, fmaxf(S[nt][0], S[nt][1]));
            mx1 = fmaxf(mx1, fmaxf(S[nt][2], S[nt][3]));
        }
        mx0 = fmaxf(mx0, __shfl_xor_sync(0xffffffffu, mx0, 1));
        mx0 = fmaxf(mx0, __shfl_xor_sync(0xffffffffu, mx0, 2));
        mx1 = fmaxf(mx1, __shfl_xor_sync(0xffffffffu, mx1, 1));
        mx1 = fmaxf(mx1, __shfl_xor_sync(0xffffffffu, mx1, 2));
        const float nm0 = fmaxf(mrow0, mx0);
        const float nm1 = fmaxf(mrow1, mx1);
        const float c0 = __expf(mrow0 - nm0);
        const float c1 = __expf(mrow1 - nm1);
        mrow0 = nm0; mrow1 = nm1;

        float s0 = 0.f, s1 = 0.f;
        uint32_t pahi[4][4], palo[4][4];
#pragma unroll
        for (int nt = 0; nt < 8; nt++) {
            float p0 = __expf(S[nt][0] - nm0);
            float p1 = __expf(S[nt][1] - nm0);
            float p2 = __expf(S[nt][2] - nm1);
            float p3 = __expf(S[nt][3] - nm1);
            s0 += p0 + p1;
            s1 += p2 + p3;
            float h0 = __bfloat162float(__float2bfloat16(p0));
            float h1 = __bfloat162float(__float2bfloat16(p1));
            float h2 = __bfloat162float(__float2bfloat16(p2));
            float h3 = __bfloat162float(__float2bfloat16(p3));
            const int ks = nt >> 1;
            const int hv = (nt & 1) * 2;
            pahi[ks][hv]     = pack_bf2(h0, h1);
            pahi[ks][hv + 1] = pack_bf2(h2, h3);
            palo[ks][hv]     = pack_bf2(p0 - h0, p1 - h1);
            palo[ks][hv + 1] = pack_bf2(p2 - h2, p3 - h3);
        }
        s0 += __shfl_xor_sync(0xffffffffu, s0, 1);
        s0 += __shfl_xor_sync(0xffffffffu, s0, 2);
        s1 += __shfl_xor_sync(0xffffffffu, s1, 1);
        s1 += __shfl_xor_sync(0xffffffffu, s1, 2);
        lrow0 = lrow0 * c0 + s0;
        lrow1 = lrow1 * c1 + s1;

#pragma unroll
        for (int dt = 0; dt < 8; dt++) {
            O[dt][0] *= c0; O[dt][1] *= c0;
            O[dt][2] *= c1; O[dt][3] *= c1;
        }

#pragma unroll
        for (int ks = 0; ks < 4; ks++) {
            uint32_t vh_[4][4], vl_[4][4];
            const uint32_t vrow = (uint32_t)(ks * 16 + (mt & 1) * 8 + r8);
#pragma unroll
            for (int dp = 0; dp < 4; dp++) {
                const uint32_t vcol = (uint32_t)(dp * 16 + (mt >> 1) * 8);
                LDSM_X4_T(vh_[dp][0], vh_[dp][1], vh_[dp][2], vh_[dp][3],
                          sb + bufb + OFF_VH + vrow * 144 + vcol * 2);
                LDSM_X4_T(vl_[dp][0], vl_[dp][1], vl_[dp][2], vl_[dp][3],
                          sb + bufb + OFF_VL + vrow * 144 + vcol * 2);
            }
#pragma unroll
            for (int dp = 0; dp < 4; dp++) {
                MMA_BF16(O[2*dp][0], O[2*dp][1], O[2*dp][2], O[2*dp][3],
                         pahi[ks][0], pahi[ks][1], pahi[ks][2], pahi[ks][3],
                         vh_[dp][0], vh_[dp][1]);
                MMA_BF16(O[2*dp+1][0], O[2*dp+1][1], O[2*dp+1][2], O[2*dp+1][3],
                         pahi[ks][0], pahi[ks][1], pahi[ks][2], pahi[ks][3],
                         vh_[dp][2], vh_[dp][3]);
            }
#pragma unroll
            for (int dp = 0; dp < 4; dp++) {
                MMA_BF16(O[2*dp][0], O[2*dp][1], O[2*dp][2], O[2*dp][3],
                         pahi[ks][0], pahi[ks][1], pahi[ks][2], pahi[ks][3],
                         vl_[dp][0], vl_[dp][1]);
                MMA_BF16(O[2*dp+1][0], O[2*dp+1][1], O[2*dp+1][2], O[2*dp+1][3],
                         pahi[ks][0], pahi[ks][1], pahi[ks][2], pahi[ks][3],
                         vl_[dp][2], vl_[dp][3]);
            }
#pragma unroll
            for (int dp = 0; dp < 4; dp++) {
                MMA_BF16(O[2*dp][0], O[2*dp][1], O[2*dp][2], O[2*dp][3],
                         palo[ks][0], palo[ks][1], palo[ks][2], palo[ks][3],
                         vh_[dp][0], vh_[dp][1]);
                MMA_BF16(O[2*dp+1][0], O[2*dp+1][1], O[2*dp+1][2], O[2*dp+1][3],
                         palo[ks][0], palo[ks][1], palo[ks][2], palo[ks][3],
                         vh_[dp][2], vh_[dp][3]);
            }
        }
    }

    const float inv0 = 1.0f / lrow0;
    const float inv1 = 1.0f / lrow1;
    const int row0 = m0 + wm + g;
#pragma unroll
    for (int dt = 0; dt < 8; dt++) {
        int col = h * DK + dt * 8 + 2 * q;
        *(float2*)&ctx[((size_t)(b * MM + row0)) * DMOD + col] =
            make_float2(O[dt][0] * inv0, O[dt][1] * inv0);
        *(float2*)&ctx[((size_t)(b * MM + row0 + 8)) * DMOD + col] =
            make_float2(O[dt][2] * inv1, O[dt][3] * inv1);
    }
}

// ---------------------------------------------------------------------------
extern "C" void kernel_launch(void* const* d_in, const int* in_sizes, int n_in,
                              void* d_out, int out_size) {
    const float* q  = (const float*)d_in[0];
    const float* k  = (const float*)d_in[1];
    const float* v  = (const float*)d_in[2];
    const void*  mask_raw = d_in[3];
    const float* Wq = (const float*)d_in[4];
    const float* Wk = (const float*)d_in[5];
    const float* Wv = (const float*)d_in[6];
    const float* Wo = (const float*)d_in[7];
    float* out = (float*)d_out;

    void *Qp_, *Kp_, *Vp_, *ctx_, *mask_, *A3_, *W3_, *Kc_, *Vh_, *Vl_;
    cudaGetSymbolAddress(&Qp_,  g_Qp);
    cudaGetSymbolAddress(&Kp_,  g_Kp);
    cudaGetSymbolAddress(&Vp_,  g_Vp);
    cudaGetSymbolAddress(&ctx_, g_ctx);
    cudaGetSymbolAddress(&mask_, g_mask);
    cudaGetSymbolAddress(&A3_,  g_A3);
    cudaGetSymbolAddress(&W3_,  g_W3);
    cudaGetSymbolAddress(&Kc_,  g_Kc);
    cudaGetSymbolAddress(&Vh_,  g_Vh);
    cudaGetSymbolAddress(&Vl_,  g_Vl);
    float* Qp  = (float*)Qp_;
    float* Kp  = (float*)Kp_;
    float* Vp  = (float*)Vp_;
    float* ctx = (float*)ctx_;
    unsigned char* mask = (unsigned char*)mask_;
    __nv_bfloat16* A3 = (__nv_bfloat16*)A3_;
    __nv_bfloat16* W3 = (__nv_bfloat16*)W3_;
    __nv_bfloat16* Kc = (__nv_bfloat16*)Kc_;
    __nv_bfloat16* Vh = (__nv_bfloat16*)Vh_;
    __nv_bfloat16* Vl = (__nv_bfloat16*)Vl_;

    cudaFuncSetAttribute(attn_hmma,
                         cudaFuncAttributeMaxDynamicSharedMemorySize, A2_SMEM);
    cudaFuncSetAttribute(gemm_hmma,
                         cudaFuncAttributeMaxDynamicSharedMemorySize, G_SMEM);

    // Normalize mask dtype -> uint8
    detect_mask<<<1, 1024>>>((const unsigned int*)mask_raw);
    convert_mask<<<(unsigned)(((size_t)BB * MM * NN / 4 + 255) / 256), 256>>>(mask_raw);

    const unsigned actg = (unsigned)(((size_t)(BB * MM) * DMOD / 8 + 255) / 256);
    const unsigned wgtg = (unsigned)(((size_t)DMOD * DMOD / 8 + 255) / 256);
    const unsigned kvg  = (unsigned)(((size_t)BB * NN * DMOD / 4 + 255) / 256);

    // Stage all three input projections, run as one batched GEMM launch
    split_act<<<actg, 256>>>(q, A3);
    split_act<<<actg, 256>>>(k, A3 + AS3);
    split_act<<<actg, 256>>>(v, A3 + 2 * AS3);
    split_wgt<<<wgtg, 256>>>(Wq, W3);
    split_wgt<<<wgtg, 256>>>(Wk, W3 + WS3);
    split_wgt<<<wgtg, 256>>>(Wv, W3 + 2 * WS3);

    dim3 gridG3(DMOD / 128, (BB * MM) / 128, 3);        // (8, 32, 3)
    gemm_hmma<<<gridG3, 128, G_SMEM>>>((const uint4*)A3, (const uint4*)W3, Qp, Kp, Vp);

    // Precompute head-major split K/V for attention
    split_kv<<<kvg, 256>>>(Kp, Vp, Kc, Vh, Vl);

    dim3 gridA(MM / 128, BB * NH);                      // (16, 32)
    attn_hmma<<<gridA, 256, A2_SMEM>>>(Qp, Kc, Vh, Vl, mask, ctx);

    // out = ctx @ Wo^T
    split_act<<<actg, 256>>>(ctx, A3);
    split_wgt<<<wgtg, 256>>>(Wo, W3);
    dim3 gridG(DMOD / 128, (BB * MM) / 128, 1);
    gemm_hmma<<<gridG, 128, G_SMEM>>>((const uint4*)A3, (const uint4*)W3, out, out, out);
}

// round 13
// speedup vs baseline: 5.0154x; 1.4613x over previous
#include <cuda_runtime.h>
#include <cuda_fp16.h>
#include <cstdint>

// Problem constants
#define BB   2
#define MM   2048
#define NN   2048
#define DMOD 1024
#define NH   16
#define DK   64

#define KW2  2048                         // weight split width [Whi|Wlo]
#define AS2 ((size_t)(BB * MM) * DMOD)    // A (hi-only) region elems
#define WS2 ((size_t)DMOD * KW2)          // W region elems

// Scratch (device globals: allocation-free rule)
__device__ float g_Qp[BB * MM * DMOD];
__device__ float g_Kp[BB * NN * DMOD];
__device__ float g_Vp[BB * NN * DMOD];
__device__ float g_ctx[BB * MM * DMOD];
__device__ unsigned char g_mask[BB * (size_t)MM * NN];
__device__ int g_mask_kind;
__device__ __half g_A2[3 * ((size_t)(BB * MM) * DMOD)];      // 25 MB
__device__ __half g_W2[3 * ((size_t)DMOD * KW2)];            // 12.6 MB
__device__ __half g_Kc[(size_t)BB * NH * NN * 128];          // 16.8 MB [Khi|Klo]
__device__ __half g_Vh[(size_t)BB * NH * NN * DK];           // 8.4 MB
__device__ __half g_Vl[(size_t)BB * NH * NN * DK];           // 8.4 MB

// ---------------------------------------------------------------------------
// Helpers (sm_80-era: mma.sync + ldmatrix + cp.async; NO tcgen05)
// ---------------------------------------------------------------------------
__device__ __forceinline__ uint32_t cvta_s(const void* p) {
    uint32_t a;
    asm("{ .reg .u64 t; cvta.to.shared.u64 t, %1; cvt.u32.u64 %0, t; }"
        : "=r"(a) : "l"(p));
    return a;
}

#define LDSM_X4(r0, r1, r2, r3, a)                                            \
    asm volatile("ldmatrix.sync.aligned.m8n8.x4.shared.b16 {%0,%1,%2,%3}, [%4];" \
                 : "=r"(r0), "=r"(r1), "=r"(r2), "=r"(r3) : "r"(a))

#define LDSM_X4_T(r0, r1, r2, r3, a)                                          \
    asm volatile("ldmatrix.sync.aligned.m8n8.x4.trans.shared.b16 {%0,%1,%2,%3}, [%4];" \
                 : "=r"(r0), "=r"(r1), "=r"(r2), "=r"(r3) : "r"(a))

#define MMA_F16(c0, c1, c2, c3, a0, a1, a2, a3, b0, b1)                       \
    asm volatile("mma.sync.aligned.m16n8k16.row.col.f32.f16.f16.f32 "         \
                 "{%0,%1,%2,%3}, {%4,%5,%6,%7}, {%8,%9}, {%0,%1,%2,%3};"      \
                 : "+f"(c0), "+f"(c1), "+f"(c2), "+f"(c3)                     \
                 : "r"(a0), "r"(a1), "r"(a2), "r"(a3), "r"(b0), "r"(b1))

#define CP_ASYNC16(s, g)                                                      \
    asm volatile("cp.async.cg.shared.global [%0], [%1], 16;" :: "r"(s), "l"(g))
#define CP_COMMIT() asm volatile("cp.async.commit_group;" ::: "memory")
#define CP_WAIT0()  asm volatile("cp.async.wait_group 0;" ::: "memory")
#define CP_WAIT1()  asm volatile("cp.async.wait_group 1;" ::: "memory")
#define CP_WAIT2()  asm volatile("cp.async.wait_group 2;" ::: "memory")

__device__ __forceinline__ uint32_t pack_hf2(float a, float b) {
    __half2 h = __floats2half2_rn(a, b);
    return *(uint32_t*)&h;
}
__device__ __forceinline__ void split2h(float a, float b, uint32_t& h, uint32_t& l) {
    __half ha = __float2half_rn(a), hb = __float2half_rn(b);
    __half2 hh = __halves2half2(ha, hb);
    h = *(uint32_t*)&hh;
    l = pack_hf2(a - __half2float(ha), b - __half2float(hb));
}

// ---------------------------------------------------------------------------
// Mask dtype detection + conversion (known-good)
// ---------------------------------------------------------------------------
__global__ void detect_mask(const unsigned int* __restrict__ w) {
    __shared__ int s_not_int, s_not_float;
    if (threadIdx.x == 0) { s_not_int = 0; s_not_float = 0; }
    __syncthreads();
    int li = 0, lf = 0;
    for (int i = threadIdx.x; i < 65536; i += blockDim.x) {
        unsigned int x = w[i];
        if (x > 1u) li = 1;
        if (x != 0u && x != 0x3F800000u) lf = 1;
    }
    if (li) atomicOr(&s_not_int, 1);
    if (lf) atomicOr(&s_not_float, 1);
    __syncthreads();
    if (threadIdx.x == 0) {
        if (!s_not_int)        g_mask_kind = 1;
        else if (!s_not_float) g_mask_kind = 2;
        else                   g_mask_kind = 0;
    }
}

__global__ void convert_mask(const void* __restrict__ m) {
    size_t i = (size_t)blockIdx.x * blockDim.x + threadIdx.x;
    const size_t total = (size_t)BB * MM * NN / 4;
    if (i >= total) return;
    int kind = g_mask_kind;
    uchar4 o;
    if (kind == 1) {
        int4 v = ((const int4*)m)[i];
        o = make_uchar4(v.x != 0, v.y != 0, v.z != 0, v.w != 0);
    } else if (kind == 2) {
        float4 v = ((const float4*)m)[i];
        o = make_uchar4(v.x != 0.f, v.y != 0.f, v.z != 0.f, v.w != 0.f);
    } else {
        unsigned int v = ((const unsigned int*)m)[i];
        o = make_uchar4((v & 0xffu) != 0, ((v >> 8) & 0xffu) != 0,
                        ((v >> 16) & 0xffu) != 0, (v >> 24) != 0);
    }
    ((uchar4*)g_mask)[i] = o;
}

// ---------------------------------------------------------------------------
// Splits (fp16): act -> hi only [r][1024]; wgt -> [Whi|Wlo] [r][2048]
// ---------------------------------------------------------------------------
__global__ void split_act(const float* __restrict__ X, __half* __restrict__ O) {
    size_t i = (size_t)blockIdx.x * blockDim.x + threadIdx.x;   // 8-el group
    const size_t NG = (size_t)(BB * MM) * DMOD / 8;
    if (i >= NG) return;
    int r = (int)(i >> 7);
    int c = (int)(i & 127) << 3;
    const float4* xp = (const float4*)(X + ((size_t)r << 10) + c);
    float4 x0 = xp[0], x1 = xp[1];
    uint4 HI;
    HI.x = pack_hf2(x0.x, x0.y);
    HI.y = pack_hf2(x0.z, x0.w);
    HI.z = pack_hf2(x1.x, x1.y);
    HI.w = pack_hf2(x1.z, x1.w);
    *(uint4*)(O + ((size_t)r << 10) + c) = HI;
}

__global__ void split_wgt(const float* __restrict__ W, __half* __restrict__ O) {
    size_t i = (size_t)blockIdx.x * blockDim.x + threadIdx.x;
    const size_t NG = (size_t)DMOD * DMOD / 8;
    if (i >= NG) return;
    int r = (int)(i >> 7);
    int c = (int)(i & 127) << 3;
    const float4* xp = (const float4*)(W + ((size_t)r << 10) + c);
    float4 x0 = xp[0], x1 = xp[1];
    uint4 HI, LO;
    split2h(x0.x, x0.y, HI.x, LO.x);
    split2h(x0.z, x0.w, HI.y, LO.y);
    split2h(x1.x, x1.y, HI.z, LO.z);
    split2h(x1.z, x1.w, HI.w, LO.w);
    __half* base = O + (size_t)r * KW2 + c;
    *(uint4*)(base)        = HI;
    *(uint4*)(base + 1024) = LO;
}

// split_kv: -> head-major Kc=[Khi|Klo] (128 fp16/row), Vh, Vl
__global__ void split_kv(const float* __restrict__ Kp, const float* __restrict__ Vp,
                         __half* __restrict__ Kc,
                         __half* __restrict__ Vh,
                         __half* __restrict__ Vl) {
    size_t i = (size_t)blockIdx.x * blockDim.x + threadIdx.x;   // 4-el group
    const size_t NG = (size_t)BB * NN * DMOD / 4;
    if (i >= NG) return;
    int bn = (int)(i >> 8);
    int c  = (int)(i & 255) << 2;
    int h = c >> 6, d = c & 63;
    int b = bn >> 11, n = bn & 2047;
    size_t hb = ((size_t)(b * NH + h)) * NN + n;
    float4 kx = *(const float4*)(Kp + ((size_t)bn << 10) + c);
    float4 vx = *(const float4*)(Vp + ((size_t)bn << 10) + c);
    uint2 KH, KL, VH, VL;
    split2h(kx.x, kx.y, KH.x, KL.x);
    split2h(kx.z, kx.w, KH.y, KL.y);
    split2h(vx.x, vx.y, VH.x, VL.x);
    split2h(vx.z, vx.w, VH.y, VL.y);
    *(uint2*)(Kc + hb * 128 + d)      = KH;
    *(uint2*)(Kc + hb * 128 + 64 + d) = KL;
    *(uint2*)(Vh + hb * DK + d) = VH;
    *(uint2*)(Vl + hb * DK + d) = VL;
}

// ---------------------------------------------------------------------------
// HMMA fp16 GEMM, K=2048 ([Ahi] x [Whi|Wlo]), 4-stage cp.async pipeline.
// A region is 1024 wide; chunks 32..63 re-read A chunk (kc&31).
// ---------------------------------------------------------------------------
#define SROWB  80
#define GSTAGE (128 * SROWB * 2)
#define G_SMEM (4 * GSTAGE)               // 81920 B

__global__ void __launch_bounds__(128, 2) gemm_hmma(
        const uint4* __restrict__ A2,
        const uint4* __restrict__ B2,
        float* __restrict__ C0, float* __restrict__ C1, float* __restrict__ C2) {
    extern __shared__ char gsm[];
    const uint32_t sb = cvta_s(gsm);

    const int t = threadIdx.x;
    const int lane = t & 31, wid = t >> 5;
    const int m0 = blockIdx.y * 128, n0 = blockIdx.x * 128;
    const int z = blockIdx.z;
    const int wm = (wid & 1) * 64, wn = (wid >> 1) * 64;
    const int g = lane >> 2, tq = lane & 3;

    const uint4* Az = A2 + (size_t)z * (AS2 / 8);
    const uint4* Bz = B2 + (size_t)z * (WS2 / 8);
    float* C = (z == 0) ? C0 : (z == 1) ? C1 : C2;

    const uint4* arow = Az + (size_t)(m0 + t) * 128;   // 1024 fp16 = 128 uint4
    const uint4* brow = Bz + (size_t)(n0 + t) * 256;   // 2048 fp16 = 256 uint4
    const int swz = (t >> 3) & 3;
    const uint32_t strow = (uint32_t)(t * SROWB);

    auto load_stage = [&](int kc, int stg) {
        const uint32_t sa = sb + (uint32_t)stg * GSTAGE;
        const uint32_t sbB = sa + 128 * SROWB;
        const uint4* ap = arow + (kc & 31) * 4;
        const uint4* bp = brow + kc * 4;
#pragma unroll
        for (int j = 0; j < 4; j++) {
            uint32_t off = strow + (uint32_t)((j ^ swz) << 4);
            CP_ASYNC16(sa + off, (const char*)(ap + j));
            CP_ASYNC16(sbB + off, (const char*)(bp + j));
        }
    };

    load_stage(0, 0); CP_COMMIT();
    load_stage(1, 1); CP_COMMIT();
    load_stage(2, 2); CP_COMMIT();

    float c[4][8][4];
#pragma unroll
    for (int i = 0; i < 4; i++)
#pragma unroll
        for (int j = 0; j < 8; j++)
#pragma unroll
            for (int q = 0; q < 4; q++) c[i][j][q] = 0.f;

    const int jj = lane >> 3;
    const int r8 = lane & 7;

    for (int kc = 0; kc < 64; kc++) {
        CP_WAIT2();
        __syncthreads();
        if (kc < 61) load_stage(kc + 3, (kc + 3) & 3);
        CP_COMMIT();

        const char* Ab = gsm + (kc & 3) * GSTAGE;
        const char* Bb = Ab + 128 * SROWB;
#pragma unroll
        for (int ks = 0; ks < 2; ks++) {
            const int ku = ks * 2;
            uint32_t a[4][4], b[8][2];
#pragma unroll
            for (int mt = 0; mt < 4; mt++) {
                int r = wm + mt * 16 + ((jj & 1) << 3) + r8;
                int u = (ku + (jj >> 1)) ^ ((r >> 3) & 3);
                uint32_t ad = cvta_s(Ab + r * SROWB + (u << 4));
                LDSM_X4(a[mt][0], a[mt][1], a[mt][2], a[mt][3], ad);
            }
#pragma unroll
            for (int np = 0; np < 4; np++) {
                int r = wn + np * 16 + ((jj >> 1) << 3) + r8;
                int u = (ku + (jj & 1)) ^ ((r >> 3) & 3);
                uint32_t ad = cvta_s(Bb + r * SROWB + (u << 4));
                LDSM_X4(b[np * 2][0], b[np * 2][1], b[np * 2 + 1][0], b[np * 2 + 1][1], ad);
            }
#pragma unroll
            for (int mt = 0; mt < 4; mt++)
#pragma unroll
                for (int nt = 0; nt < 8; nt++)
                    MMA_F16(c[mt][nt][0], c[mt][nt][1], c[mt][nt][2], c[mt][nt][3],
                            a[mt][0], a[mt][1], a[mt][2], a[mt][3],
                            b[nt][0], b[nt][1]);
        }
    }

#pragma unroll
    for (int mt = 0; mt < 4; mt++) {
        int row = m0 + wm + mt * 16 + g;
#pragma unroll
        for (int nt = 0; nt < 8; nt++) {
            int col = n0 + wn + nt * 8 + tq * 2;
            *(float2*)&C[(size_t)row * DMOD + col] =
                make_float2(c[mt][nt][0], c[mt][nt][1]);
            *(float2*)&C[(size_t)(row + 8) * DMOD + col] =
                make_float2(c[mt][nt][2], c[mt][nt][3]);
        }
    }
}

// ---------------------------------------------------------------------------
// HMMA fp16 flash attention: Qhi x [Khi|Klo]; Phi x (Vhi + Vlo).
// 3-stage cp.async pipeline; CTA = (b,h) x 128 q-rows; N-tile 64, 32 iters.
// ---------------------------------------------------------------------------
#define OFF_KC  0                   // [64][272B]  (128 fp16 data + pad)
#define OFF_VH  17408               // [64][144B]
#define OFF_VL  26624               // [64][144B]
#define OFF_MSK 35840               // [128][64B]
#define BUFSZ   44032
#define A2_SMEM (3 * BUFSZ)         // 132096

__global__ void __launch_bounds__(256, 1) attn_hmma(
        const float* __restrict__ Qp,
        const __half* __restrict__ Kc,
        const __half* __restrict__ Vh,
        const __half* __restrict__ Vl,
        const unsigned char* __restrict__ mask,
        float* __restrict__ ctx) {
    extern __shared__ char sm[];
    const uint32_t sb = cvta_s(sm);

    const int t = threadIdx.x;
    const int lane = t & 31, w = t >> 5;
    const int g = lane >> 2, q = lane & 3;
    const int bh = blockIdx.y;
    const int b = bh >> 4, h = bh & 15;
    const int bh2 = b * NH + h;
    const int m0 = blockIdx.x * 128;
    const int wm = w * 16;

    // ---- Phase 0: stage Qhi [128][144B] (overlays buffer 0), pull qf regs
    {
        const int row = t >> 1;
        const int cb = (t & 1) * 32;
        const float* qg = Qp + ((size_t)(b * MM + m0 + row)) * DMOD + h * DK + cb;
        char* qs = sm + row * 144 + cb * 2;
#pragma unroll
        for (int i = 0; i < 8; i++) {
            float4 v = *(const float4*)(qg + 4 * i);
            uint2 o;
            o.x = pack_hf2(v.x, v.y);
            o.y = pack_hf2(v.z, v.w);
            *(uint2*)(qs + 8 * i) = o;
        }
    }
    __syncthreads();

    uint32_t qf[4][4];
    {
        const int mt_ = lane >> 3, r8_ = lane & 7;
#pragma unroll
        for (int kp = 0; kp < 4; kp++) {
            uint32_t ad = sb + (uint32_t)((wm + (mt_ & 1) * 8 + r8_) * 144
                                          + (kp * 16 + (mt_ >> 1) * 8) * 2);
            LDSM_X4(qf[kp][0], qf[kp][1], qf[kp][2], qf[kp][3], ad);
        }
    }
    __syncthreads();   // staging area may now be overwritten

    // tile loader: 10 cp.async x 16B per thread
    auto load_tile = [&](int itn, uint32_t bufb) {
        const int n0g = itn * 64;
        const uint32_t sdst = sb + bufb;
        const char* kgb = (const char*)(Kc + ((size_t)bh2 * NN + n0g) * 128);
#pragma unroll
        for (int i = 0; i < 4; i++) {
            int e = t + i * 256;
            int row = e >> 4, cc = e & 15;
            CP_ASYNC16(sdst + OFF_KC + row * 272 + cc * 16, kgb + row * 256 + cc * 16);
        }
        const char* vhb = (const char*)(Vh + ((size_t)bh2 * NN + n0g) * DK);
        const char* vlb = (const char*)(Vl + ((size_t)bh2 * NN + n0g) * DK);
#pragma unroll
        for (int i = 0; i < 2; i++) {
            int e = t + i * 256;
            int row = e >> 3, cc = e & 7;
            CP_ASYNC16(sdst + OFF_VH + row * 144 + cc * 16, vhb + row * 128 + cc * 16);
            CP_ASYNC16(sdst + OFF_VL + row * 144 + cc * 16, vlb + row * 128 + cc * 16);
        }
        const char* mb = (const char*)(mask + ((size_t)(b * MM + m0)) * NN + n0g);
#pragma unroll
        for (int i = 0; i < 2; i++) {
            int e = t + i * 256;
            int row = e >> 2, cc = e & 3;
            CP_ASYNC16(sdst + OFF_MSK + row * 64 + cc * 16, mb + (size_t)row * NN + cc * 16);
        }
    };

    float O[8][4];
#pragma unroll
    for (int i = 0; i < 8; i++)
#pragma unroll
        for (int j = 0; j < 4; j++) O[i][j] = 0.f;
    float mrow0 = -1e30f, mrow1 = -1e30f, lrow0 = 0.f, lrow1 = 0.f;

    const int mt = lane >> 3, r8 = lane & 7;

    load_tile(0, 0);
    CP_COMMIT();
    load_tile(1, BUFSZ);
    CP_COMMIT();

    for (int it = 0; it < 32; it++) {
        const uint32_t bufb = (uint32_t)(it % 3) * BUFSZ;
        if (it == 31) { CP_WAIT0(); } else { CP_WAIT1(); }
        __syncthreads();
        if (it < 30) {
            load_tile(it + 2, (uint32_t)((it + 2) % 3) * BUFSZ);
            CP_COMMIT();
        }

        // ---- S = Qhi @ [Khi|Klo]^T  (4 chunks of 32)
        float S[8][4];
#pragma unroll
        for (int i = 0; i < 8; i++)
#pragma unroll
            for (int j = 0; j < 4; j++) S[i][j] = 0.f;

#pragma unroll
        for (int kp = 0; kp < 4; kp++) {
            const int qi = (kp & 1) * 2;
#pragma unroll
            for (int nt = 0; nt < 8; nt++) {
                uint32_t b0, b1, b2, b3;
                uint32_t ad = sb + bufb + OFF_KC + (uint32_t)((nt * 8 + r8) * 272
                                                             + (kp * 32 + mt * 8) * 2);
                LDSM_X4(b0, b1, b2, b3, ad);
                MMA_F16(S[nt][0], S[nt][1], S[nt][2], S[nt][3],
                        qf[qi][0], qf[qi][1], qf[qi][2], qf[qi][3], b0, b1);
                MMA_F16(S[nt][0], S[nt][1], S[nt][2], S[nt][3],
                        qf[qi + 1][0], qf[qi + 1][1], qf[qi + 1][2], qf[qi + 1][3], b2, b3);
            }
        }

        // ---- mask + scale (matches ref: (mask ? -1e9 : s) * 0.125)
        const char* mbuf = sm + bufb + OFF_MSK;
#pragma unroll
        for (int nt = 0; nt < 8; nt++) {
            unsigned short mA = *(const unsigned short*)(mbuf + (wm + g) * 64 + nt * 8 + 2 * q);
            unsigned short mB = *(const unsigned short*)(mbuf + (wm + g + 8) * 64 + nt * 8 + 2 * q);
            S[nt][0] = (mA & 0xff) ? -1.25e8f : S[nt][0] * 0.125f;
            S[nt][1] = (mA >> 8)   ? -1.25e8f : S[nt][1] * 0.125f;
            S[nt][2] = (mB & 0xff) ? -1.25e8f : S[nt][2] * 0.125f;
            S[nt][3] = (mB >> 8)   ? -1.25e8f : S[nt][3] * 0.125f;
        }

        // ---- online softmax
        float mx0 = -1e30f, mx1 = -1e30f;
#pragma unroll
        for (int nt = 0; nt < 8; nt++) {
            mx0 = fmaxf(mx0, fmaxf(S[nt][0], S[nt][1]));
            mx1 = fmaxf(mx1, fmaxf(S[nt][2], S[nt][3]));
        }
        mx0 = fmaxf(mx0, __shfl_xor_sync(0xffffffffu, mx0, 1));
        mx0 = fmaxf(mx0, __shfl_xor_sync(0xffffffffu, mx0, 2));
        mx1 = fmaxf(mx1, __shfl_xor_sync(0xffffffffu, mx1, 1));
        mx1 = fmaxf(mx1, __shfl_xor_sync(0xffffffffu, mx1, 2));
        const float nm0 = fmaxf(mrow0, mx0);
        const float nm1 = fmaxf(mrow1, mx1);
        const float c0 = __expf(mrow0 - nm0);
        const float c1 = __expf(mrow1 - nm1);
        mrow0 = nm0; mrow1 = nm1;

        float s0 = 0.f, s1 = 0.f;
        uint32_t pa[4][4];
#pragma unroll
        for (int nt = 0; nt < 8; nt++) {
            float p0 = __expf(S[nt][0] - nm0);
            float p1 = __expf(S[nt][1] - nm0);
            float p2 = __expf(S[nt][2] - nm1);
            float p3 = __expf(S[nt][3] - nm1);
            s0 += p0 + p1;
            s1 += p2 + p3;
            const int ks = nt >> 1;
            const int hv = (nt & 1) * 2;
            pa[ks][hv]     = pack_hf2(p0, p1);
            pa[ks][hv + 1] = pack_hf2(p2, p3);
        }
        s0 += __shfl_xor_sync(0xffffffffu, s0, 1);
        s0 += __shfl_xor_sync(0xffffffffu, s0, 2);
        s1 += __shfl_xor_sync(0xffffffffu, s1, 1);
        s1 += __shfl_xor_sync(0xffffffffu, s1, 2);
        lrow0 = lrow0 * c0 + s0;
        lrow1 = lrow1 * c1 + s1;

#pragma unroll
        for (int dt = 0; dt < 8; dt++) {
            O[dt][0] *= c0; O[dt][1] *= c0;
            O[dt][2] *= c1; O[dt][3] *= c1;
        }

        // ---- O += Phi @ (Vhi + Vlo)
#pragma unroll
        for (int ks = 0; ks < 4; ks++) {
            uint32_t vh_[4][4], vl_[4][4];
            const uint32_t vrow = (uint32_t)(ks * 16 + (mt & 1) * 8 + r8);
#pragma unroll
            for (int dp = 0; dp < 4; dp++) {
                const uint32_t vcol = (uint32_t)(dp * 16 + (mt >> 1) * 8);
                LDSM_X4_T(vh_[dp][0], vh_[dp][1], vh_[dp][2], vh_[dp][3],
                          sb + bufb + OFF_VH + vrow * 144 + vcol * 2);
                LDSM_X4_T(vl_[dp][0], vl_[dp][1], vl_[dp][2], vl_[dp][3],
                          sb + bufb + OFF_VL + vrow * 144 + vcol * 2);
            }
#pragma unroll
            for (int dp = 0; dp < 4; dp++) {
                MMA_F16(O[2*dp][0], O[2*dp][1], O[2*dp][2], O[2*dp][3],
                        pa[ks][0], pa[ks][1], pa[ks][2], pa[ks][3],
                        vh_[dp][0], vh_[dp][1]);
                MMA_F16(O[2*dp+1][0], O[2*dp+1][1], O[2*dp+1][2], O[2*dp+1][3],
                        pa[ks][0], pa[ks][1], pa[ks][2], pa[ks][3],
                        vh_[dp][2], vh_[dp][3]);
            }
#pragma unroll
            for (int dp = 0; dp < 4; dp++) {
                MMA_F16(O[2*dp][0], O[2*dp][1], O[2*dp][2], O[2*dp][3],
                        pa[ks][0], pa[ks][1], pa[ks][2], pa[ks][3],
                        vl_[dp][0], vl_[dp][1]);
                MMA_F16(O[2*dp+1][0], O[2*dp+1][1], O[2*dp+1][2], O[2*dp+1][3],
                        pa[ks][0], pa[ks][1], pa[ks][2], pa[ks][3],
                        vl_[dp][2], vl_[dp][3]);
            }
        }
    }

    // ---- epilogue
    const float inv0 = 1.0f / lrow0;
    const float inv1 = 1.0f / lrow1;
    const int row0 = m0 + wm + g;
#pragma unroll
    for (int dt = 0; dt < 8; dt++) {
        int col = h * DK + dt * 8 + 2 * q;
        *(float2*)&ctx[((size_t)(b * MM + row0)) * DMOD + col] =
            make_float2(O[dt][0] * inv0, O[dt][1] * inv0);
        *(float2*)&ctx[((size_t)(b * MM + row0 + 8)) * DMOD + col] =
            make_float2(O[dt][2] * inv1, O[dt][3] * inv1);
    }
}

// ---------------------------------------------------------------------------
extern "C" void kernel_launch(void* const* d_in, const int* in_sizes, int n_in,
                              void* d_out, int out_size) {
    const float* q  = (const float*)d_in[0];
    const float* k  = (const float*)d_in[1];
    const float* v  = (const float*)d_in[2];
    const void*  mask_raw = d_in[3];
    const float* Wq = (const float*)d_in[4];
    const float* Wk = (const float*)d_in[5];
    const float* Wv = (const float*)d_in[6];
    const float* Wo = (const float*)d_in[7];
    float* out = (float*)d_out;

    void *Qp_, *Kp_, *Vp_, *ctx_, *mask_, *A2_, *W2_, *Kc_, *Vh_, *Vl_;
    cudaGetSymbolAddress(&Qp_,  g_Qp);
    cudaGetSymbolAddress(&Kp_,  g_Kp);
    cudaGetSymbolAddress(&Vp_,  g_Vp);
    cudaGetSymbolAddress(&ctx_, g_ctx);
    cudaGetSymbolAddress(&mask_, g_mask);
    cudaGetSymbolAddress(&A2_,  g_A2);
    cudaGetSymbolAddress(&W2_,  g_W2);
    cudaGetSymbolAddress(&Kc_,  g_Kc);
    cudaGetSymbolAddress(&Vh_,  g_Vh);
    cudaGetSymbolAddress(&Vl_,  g_Vl);
    float* Qp  = (float*)Qp_;
    float* Kp  = (float*)Kp_;
    float* Vp  = (float*)Vp_;
    float* ctx = (float*)ctx_;
    unsigned char* mask = (unsigned char*)mask_;
    __half* A2 = (__half*)A2_;
    __half* W2 = (__half*)W2_;
    __half* Kc = (__half*)Kc_;
    __half* Vh = (__half*)Vh_;
    __half* Vl = (__half*)Vl_;

    cudaFuncSetAttribute(attn_hmma,
                         cudaFuncAttributeMaxDynamicSharedMemorySize, A2_SMEM);
    cudaFuncSetAttribute(gemm_hmma,
                         cudaFuncAttributeMaxDynamicSharedMemorySize, G_SMEM);

    // Normalize mask dtype -> uint8
    detect_mask<<<1, 1024>>>((const unsigned int*)mask_raw);
    convert_mask<<<(unsigned)(((size_t)BB * MM * NN / 4 + 255) / 256), 256>>>(mask_raw);

    const unsigned actg = (unsigned)(((size_t)(BB * MM) * DMOD / 8 + 255) / 256);
    const unsigned wgtg = (unsigned)(((size_t)DMOD * DMOD / 8 + 255) / 256);
    const unsigned kvg  = (unsigned)(((size_t)BB * NN * DMOD / 4 + 255) / 256);

    // Stage all three input projections, run as one batched GEMM launch
    split_act<<<actg, 256>>>(q, A2);
    split_act<<<actg, 256>>>(k, A2 + AS2);
    split_act<<<actg, 256>>>(v, A2 + 2 * AS2);
    split_wgt<<<wgtg, 256>>>(Wq, W2);
    split_wgt<<<wgtg, 256>>>(Wk, W2 + WS2);
    split_wgt<<<wgtg, 256>>>(Wv, W2 + 2 * WS2);

    dim3 gridG3(DMOD / 128, (BB * MM) / 128, 3);        // (8, 32, 3)
    gemm_hmma<<<gridG3, 128, G_SMEM>>>((const uint4*)A2, (const uint4*)W2, Qp, Kp, Vp);

    // Precompute head-major split K/V for attention
    split_kv<<<kvg, 256>>>(Kp, Vp, Kc, Vh, Vl);

    dim3 gridA(MM / 128, BB * NH);                      // (16, 32)
    attn_hmma<<<gridA, 256, A2_SMEM>>>(Qp, Kc, Vh, Vl, mask, ctx);

    // out = ctx @ Wo^T
    split_act<<<actg, 256>>>(ctx, A2);
    split_wgt<<<wgtg, 256>>>(Wo, W2);
    dim3 gridG(DMOD / 128, (BB * MM) / 128, 1);
    gemm_hmma<<<gridG, 128, G_SMEM>>>((const uint4*)A2, (const uint4*)W2, out, out, out);
}

// round 15
// speedup vs baseline: 5.2855x; 1.0539x over previous
#include <cuda_runtime.h>
#include <cuda_fp16.h>
#include <cstdint>

// Problem constants
#define BB   2
#define MM   2048
#define NN   2048
#define DMOD 1024
#define NH   16
#define DK   64

#define KW2  2048                         // weight split width [Whi|Wlo]
#define AS2 ((size_t)(BB * MM) * DMOD)    // A (hi-only) region elems
#define WS2 ((size_t)DMOD * KW2)          // W region elems

// Scratch (device globals: allocation-free rule)
__device__ unsigned char g_mask[BB * (size_t)MM * NN];
__device__ int g_mask_kind;
__device__ __half g_A2[3 * ((size_t)(BB * MM) * DMOD)];      // 25 MB
__device__ __half g_W2[3 * ((size_t)DMOD * KW2)];            // 12.6 MB
__device__ __half g_Qh[(size_t)BB * MM * DMOD];              // 8.4 MB
__device__ __half g_Kc[(size_t)BB * NH * NN * 128];          // 16.8 MB [Khi|Klo]
__device__ __half g_Vh[(size_t)BB * NH * NN * DK];           // 8.4 MB
__device__ __half g_Vl[(size_t)BB * NH * NN * DK];           // 8.4 MB

// ---------------------------------------------------------------------------
// Helpers (sm_80-era: mma.sync + ldmatrix + cp.async; NO tcgen05)
// ---------------------------------------------------------------------------
__device__ __forceinline__ uint32_t cvta_s(const void* p) {
    uint32_t a;
    asm("{ .reg .u64 t; cvta.to.shared.u64 t, %1; cvt.u32.u64 %0, t; }"
        : "=r"(a) : "l"(p));
    return a;
}

#define LDSM_X4(r0, r1, r2, r3, a)                                            \
    asm volatile("ldmatrix.sync.aligned.m8n8.x4.shared.b16 {%0,%1,%2,%3}, [%4];" \
                 : "=r"(r0), "=r"(r1), "=r"(r2), "=r"(r3) : "r"(a))

#define LDSM_X4_T(r0, r1, r2, r3, a)                                          \
    asm volatile("ldmatrix.sync.aligned.m8n8.x4.trans.shared.b16 {%0,%1,%2,%3}, [%4];" \
                 : "=r"(r0), "=r"(r1), "=r"(r2), "=r"(r3) : "r"(a))

#define MMA_F16(c0, c1, c2, c3, a0, a1, a2, a3, b0, b1)                       \
    asm volatile("mma.sync.aligned.m16n8k16.row.col.f32.f16.f16.f32 "         \
                 "{%0,%1,%2,%3}, {%4,%5,%6,%7}, {%8,%9}, {%0,%1,%2,%3};"      \
                 : "+f"(c0), "+f"(c1), "+f"(c2), "+f"(c3)                     \
                 : "r"(a0), "r"(a1), "r"(a2), "r"(a3), "r"(b0), "r"(b1))

#define CP_ASYNC16(s, g)                                                      \
    asm volatile("cp.async.cg.shared.global [%0], [%1], 16;" :: "r"(s), "l"(g))
#define CP_COMMIT() asm volatile("cp.async.commit_group;" ::: "memory")
#define CP_WAIT0()  asm volatile("cp.async.wait_group 0;" ::: "memory")
#define CP_WAIT2()  asm volatile("cp.async.wait_group 2;" ::: "memory")

__device__ __forceinline__ uint32_t pack_hf2(float a, float b) {
    __half2 h = __floats2half2_rn(a, b);
    return *(uint32_t*)&h;
}
__device__ __forceinline__ void split2h(float a, float b, uint32_t& h, uint32_t& l) {
    __half ha = __float2half_rn(a), hb = __float2half_rn(b);
    __half2 hh = __halves2half2(ha, hb);
    h = *(uint32_t*)&hh;
    l = pack_hf2(a - __half2float(ha), b - __half2float(hb));
}

// ---------------------------------------------------------------------------
// Mask dtype detection + conversion (known-good)
// ---------------------------------------------------------------------------
__global__ void detect_mask(const unsigned int* __restrict__ w) {
    __shared__ int s_not_int, s_not_float;
    if (threadIdx.x == 0) { s_not_int = 0; s_not_float = 0; }
    __syncthreads();
    int li = 0, lf = 0;
    for (int i = threadIdx.x; i < 65536; i += blockDim.x) {
        unsigned int x = w[i];
        if (x > 1u) li = 1;
        if (x != 0u && x != 0x3F800000u) lf = 1;
    }
    if (li) atomicOr(&s_not_int, 1);
    if (lf) atomicOr(&s_not_float, 1);
    __syncthreads();
    if (threadIdx.x == 0) {
        if (!s_not_int)        g_mask_kind = 1;
        else if (!s_not_float) g_mask_kind = 2;
        else                   g_mask_kind = 0;
    }
}

__global__ void convert_mask(const void* __restrict__ m) {
    size_t i = (size_t)blockIdx.x * blockDim.x + threadIdx.x;
    const size_t total = (size_t)BB * MM * NN / 4;
    if (i >= total) return;
    int kind = g_mask_kind;
    uchar4 o;
    if (kind == 1) {
        int4 v = ((const int4*)m)[i];
        o = make_uchar4(v.x != 0, v.y != 0, v.z != 0, v.w != 0);
    } else if (kind == 2) {
        float4 v = ((const float4*)m)[i];
        o = make_uchar4(v.x != 0.f, v.y != 0.f, v.z != 0.f, v.w != 0.f);
    } else {
        unsigned int v = ((const unsigned int*)m)[i];
        o = make_uchar4((v & 0xffu) != 0, ((v >> 8) & 0xffu) != 0,
                        ((v >> 16) & 0xffu) != 0, (v >> 24) != 0);
    }
    ((uchar4*)g_mask)[i] = o;
}

// ---------------------------------------------------------------------------
// Splits (fp16): act -> hi only [r][1024]; wgt -> [Whi|Wlo] [r][2048]
// ---------------------------------------------------------------------------
__global__ void split_act(const float* __restrict__ X, __half* __restrict__ O) {
    size_t i = (size_t)blockIdx.x * blockDim.x + threadIdx.x;
    const size_t NG = (size_t)(BB * MM) * DMOD / 8;
    if (i >= NG) return;
    int r = (int)(i >> 7);
    int c = (int)(i & 127) << 3;
    const float4* xp = (const float4*)(X + ((size_t)r << 10) + c);
    float4 x0 = xp[0], x1 = xp[1];
    uint4 HI;
    HI.x = pack_hf2(x0.x, x0.y);
    HI.y = pack_hf2(x0.z, x0.w);
    HI.z = pack_hf2(x1.x, x1.y);
    HI.w = pack_hf2(x1.z, x1.w);
    *(uint4*)(O + ((size_t)r << 10) + c) = HI;
}

__global__ void split_wgt(const float* __restrict__ W, __half* __restrict__ O) {
    size_t i = (size_t)blockIdx.x * blockDim.x + threadIdx.x;
    const size_t NG = (size_t)DMOD * DMOD / 8;
    if (i >= NG) return;
    int r = (int)(i >> 7);
    int c = (int)(i & 127) << 3;
    const float4* xp = (const float4*)(W + ((size_t)r << 10) + c);
    float4 x0 = xp[0], x1 = xp[1];
    uint4 HI, LO;
    split2h(x0.x, x0.y, HI.x, LO.x);
    split2h(x0.z, x0.w, HI.y, LO.y);
    split2h(x1.x, x1.y, HI.z, LO.z);
    split2h(x1.z, x1.w, HI.w, LO.w);
    __half* base = O + (size_t)r * KW2 + c;
    *(uint4*)(base)        = HI;
    *(uint4*)(base + 1024) = LO;
}

// ---------------------------------------------------------------------------
// HMMA fp16 GEMM, K=2048 ([Ahi] x [Whi|Wlo]), 4-stage cp.async pipeline.
// fin=0: z=0 -> Qh (fp16 hi), z=1 -> Kc (head-major split), z=2 -> Vh/Vl.
// fin=1: fp32 output to Cout.
// ---------------------------------------------------------------------------
#define SROWB  80
#define GSTAGE (128 * SROWB * 2)
#define G_SMEM (4 * GSTAGE)               // 81920 B

__global__ void __launch_bounds__(128, 2) gemm_hmma(
        const uint4* __restrict__ A2,
        const uint4* __restrict__ B2,
        float* __restrict__ Cout,
        __half* __restrict__ Qh,
        __half* __restrict__ Kc,
        __half* __restrict__ Vh,
        __half* __restrict__ Vl,
        int fin) {
    extern __shared__ char gsm[];
    const uint32_t sb = cvta_s(gsm);

    const int t = threadIdx.x;
    const int lane = t & 31, wid = t >> 5;
    const int m0 = blockIdx.y * 128, n0 = blockIdx.x * 128;
    const int z = blockIdx.z;
    const int wm = (wid & 1) * 64, wn = (wid >> 1) * 64;
    const int g = lane >> 2, tq = lane & 3;

    const uint4* Az = A2 + (size_t)z * (AS2 / 8);
    const uint4* Bz = B2 + (size_t)z * (WS2 / 8);

    const uint4* arow = Az + (size_t)(m0 + t) * 128;
    const uint4* brow = Bz + (size_t)(n0 + t) * 256;
    const int swz = (t >> 3) & 3;
    const uint32_t strow = (uint32_t)(t * SROWB);

    auto load_stage = [&](int kc, int stg) {
        const uint32_t sa = sb + (uint32_t)stg * GSTAGE;
        const uint32_t sbB = sa + 128 * SROWB;
        const uint4* ap = arow + (kc & 31) * 4;
        const uint4* bp = brow + kc * 4;
#pragma unroll
        for (int j = 0; j < 4; j++) {
            uint32_t off = strow + (uint32_t)((j ^ swz) << 4);
            CP_ASYNC16(sa + off, (const char*)(ap + j));
            CP_ASYNC16(sbB + off, (const char*)(bp + j));
        }
    };

    load_stage(0, 0); CP_COMMIT();
    load_stage(1, 1); CP_COMMIT();
    load_stage(2, 2); CP_COMMIT();

    float c[4][8][4];
#pragma unroll
    for (int i = 0; i < 4; i++)
#pragma unroll
        for (int j = 0; j < 8; j++)
#pragma unroll
            for (int q = 0; q < 4; q++) c[i][j][q] = 0.f;

    const int jj = lane >> 3;
    const int r8 = lane & 7;

    for (int kc = 0; kc < 64; kc++) {
        CP_WAIT2();
        __syncthreads();
        if (kc < 61) load_stage(kc + 3, (kc + 3) & 3);
        CP_COMMIT();

        const char* Ab = gsm + (kc & 3) * GSTAGE;
        const char* Bb = Ab + 128 * SROWB;
#pragma unroll
        for (int ks = 0; ks < 2; ks++) {
            const int ku = ks * 2;
            uint32_t a[4][4], b[8][2];
#pragma unroll
            for (int mt = 0; mt < 4; mt++) {
                int r = wm + mt * 16 + ((jj & 1) << 3) + r8;
                int u = (ku + (jj >> 1)) ^ ((r >> 3) & 3);
                uint32_t ad = cvta_s(Ab + r * SROWB + (u << 4));
                LDSM_X4(a[mt][0], a[mt][1], a[mt][2], a[mt][3], ad);
            }
#pragma unroll
            for (int np = 0; np < 4; np++) {
                int r = wn + np * 16 + ((jj >> 1) << 3) + r8;
                int u = (ku + (jj & 1)) ^ ((r >> 3) & 3);
                uint32_t ad = cvta_s(Bb + r * SROWB + (u << 4));
                LDSM_X4(b[np * 2][0], b[np * 2][1], b[np * 2 + 1][0], b[np * 2 + 1][1], ad);
            }
#pragma unroll
            for (int mt = 0; mt < 4; mt++)
#pragma unroll
                for (int nt = 0; nt < 8; nt++)
                    MMA_F16(c[mt][nt][0], c[mt][nt][1], c[mt][nt][2], c[mt][nt][3],
                            a[mt][0], a[mt][1], a[mt][2], a[mt][3],
                            b[nt][0], b[nt][1]);
        }
    }

    // Epilogue: route by mode
    if (fin) {
#pragma unroll
        for (int mt = 0; mt < 4; mt++) {
            int row = m0 + wm + mt * 16 + g;
#pragma unroll
            for (int nt = 0; nt < 8; nt++) {
                int col = n0 + wn + nt * 8 + tq * 2;
                *(float2*)&Cout[(size_t)row * DMOD + col] =
                    make_float2(c[mt][nt][0], c[mt][nt][1]);
                *(float2*)&Cout[(size_t)(row + 8) * DMOD + col] =
                    make_float2(c[mt][nt][2], c[mt][nt][3]);
            }
        }
    } else if (z == 0) {
#pragma unroll
        for (int mt = 0; mt < 4; mt++) {
            int row = m0 + wm + mt * 16 + g;
#pragma unroll
            for (int nt = 0; nt < 8; nt++) {
                int col = n0 + wn + nt * 8 + tq * 2;
                *(uint32_t*)&Qh[(size_t)row * DMOD + col] = pack_hf2(c[mt][nt][0], c[mt][nt][1]);
                *(uint32_t*)&Qh[(size_t)(row + 8) * DMOD + col] = pack_hf2(c[mt][nt][2], c[mt][nt][3]);
            }
        }
    } else {
        __half* Oh = (z == 1) ? Kc : Vh;
        __half* Ol = (z == 1) ? (Kc + 64) : Vl;   // Kc lo at +64 within 128-row
        const int rstr = (z == 1) ? 128 : 64;
#pragma unroll
        for (int mt = 0; mt < 4; mt++) {
            int row = m0 + wm + mt * 16 + g;
#pragma unroll
            for (int nt = 0; nt < 8; nt++) {
                int col = n0 + wn + nt * 8 + tq * 2;
                int h_ = col >> 6, d_ = col & 63;
                {
                    int b_ = row >> 11, n_ = row & 2047;
                    size_t hb = ((size_t)(b_ * NH + h_)) * NN + n_;
                    uint32_t hi, lo;
                    split2h(c[mt][nt][0], c[mt][nt][1], hi, lo);
                    *(uint32_t*)&Oh[hb * rstr + d_] = hi;
                    *(uint32_t*)&Ol[hb * rstr + d_] = lo;
                }
                {
                    int row2 = row + 8;
                    int b_ = row2 >> 11, n_ = row2 & 2047;
                    size_t hb = ((size_t)(b_ * NH + h_)) * NN + n_;
                    uint32_t hi, lo;
                    split2h(c[mt][nt][2], c[mt][nt][3], hi, lo);
                    *(uint32_t*)&Oh[hb * rstr + d_] = hi;
                    *(uint32_t*)&Ol[hb * rstr + d_] = lo;
                }
            }
        }
    }
}

// ---------------------------------------------------------------------------
// HMMA fp16 flash attention: Qhi x [Khi|Klo]; Phi x (Vhi + Vlo).
// 2-stage cp.async pipeline, 2 CTAs/SM. Writes fp16 ctx-hi (final GEMM A op).
// ---------------------------------------------------------------------------
#define OFF_KC  0                   // [64][272B]
#define OFF_VH  17408               // [64][144B]
#define OFF_VL  26624               // [64][144B]
#define OFF_MSK 35840               // [128][64B]
#define BUFSZ   44032
#define A2_SMEM (2 * BUFSZ)         // 88064

__global__ void __launch_bounds__(256, 2) attn_hmma(
        const __half* __restrict__ Qh,
        const __half* __restrict__ Kc,
        const __half* __restrict__ Vh,
        const __half* __restrict__ Vl,
        const unsigned char* __restrict__ mask,
        __half* __restrict__ ctxh) {
    extern __shared__ char sm[];
    const uint32_t sb = cvta_s(sm);

    const int t = threadIdx.x;
    const int lane = t & 31, w = t >> 5;
    const int g = lane >> 2, q = lane & 3;
    const int bh = blockIdx.y;
    const int b = bh >> 4, h = bh & 15;
    const int bh2 = b * NH + h;
    const int m0 = blockIdx.x * 128;
    const int wm = w * 16;

    // ---- Phase 0: copy Qhi tile [128][144B] (overlays buffer 0), pull qf
    {
        const int row = t >> 1;
        const int cb = (t & 1) * 32;
        const uint4* qg = (const uint4*)(Qh + ((size_t)(b * MM + m0 + row)) * DMOD + h * DK + cb);
        char* qs = sm + row * 144 + cb * 2;
#pragma unroll
        for (int i = 0; i < 4; i++)
            *(uint4*)(qs + 16 * i) = qg[i];
    }
    __syncthreads();

    uint32_t qf[4][4];
    {
        const int mt_ = lane >> 3, r8_ = lane & 7;
#pragma unroll
        for (int kp = 0; kp < 4; kp++) {
            uint32_t ad = sb + (uint32_t)((wm + (mt_ & 1) * 8 + r8_) * 144
                                          + (kp * 16 + (mt_ >> 1) * 8) * 2);
            LDSM_X4(qf[kp][0], qf[kp][1], qf[kp][2], qf[kp][3], ad);
        }
    }
    __syncthreads();

    auto load_tile = [&](int itn, uint32_t bufb) {
        const int n0g = itn * 64;
        const uint32_t sdst = sb + bufb;
        const char* kgb = (const char*)(Kc + ((size_t)bh2 * NN + n0g) * 128);
#pragma unroll
        for (int i = 0; i < 4; i++) {
            int e = t + i * 256;
            int row = e >> 4, cc = e & 15;
            CP_ASYNC16(sdst + OFF_KC + row * 272 + cc * 16, kgb + row * 256 + cc * 16);
        }
        const char* vhb = (const char*)(Vh + ((size_t)bh2 * NN + n0g) * DK);
        const char* vlb = (const char*)(Vl + ((size_t)bh2 * NN + n0g) * DK);
#pragma unroll
        for (int i = 0; i < 2; i++) {
            int e = t + i * 256;
            int row = e >> 3, cc = e & 7;
            CP_ASYNC16(sdst + OFF_VH + row * 144 + cc * 16, vhb + row * 128 + cc * 16);
            CP_ASYNC16(sdst + OFF_VL + row * 144 + cc * 16, vlb + row * 128 + cc * 16);
        }
        const char* mb = (const char*)(mask + ((size_t)(b * MM + m0)) * NN + n0g);
#pragma unroll
        for (int i = 0; i < 2; i++) {
            int e = t + i * 256;
            int row = e >> 2, cc = e & 3;
            CP_ASYNC16(sdst + OFF_MSK + row * 64 + cc * 16, mb + (size_t)row * NN + cc * 16);
        }
    };

    float O[8][4];
#pragma unroll
    for (int i = 0; i < 8; i++)
#pragma unroll
        for (int j = 0; j < 4; j++) O[i][j] = 0.f;
    float mrow0 = -1e30f, mrow1 = -1e30f, lrow0 = 0.f, lrow1 = 0.f;

    const int mt = lane >> 3, r8 = lane & 7;

    load_tile(0, 0);
    CP_COMMIT();

    for (int it = 0; it < 32; it++) {
        const uint32_t bufb = (uint32_t)(it & 1) * BUFSZ;
        CP_WAIT0();
        __syncthreads();
        if (it < 31) {
            load_tile(it + 1, (uint32_t)((it + 1) & 1) * BUFSZ);
            CP_COMMIT();
        }

        // ---- S = Qhi @ [Khi|Klo]^T
        float S[8][4];
#pragma unroll
        for (int i = 0; i < 8; i++)
#pragma unroll
            for (int j = 0; j < 4; j++) S[i][j] = 0.f;

#pragma unroll
        for (int kp = 0; kp < 4; kp++) {
            const int qi = (kp & 1) * 2;
#pragma unroll
            for (int nt = 0; nt < 8; nt++) {
                uint32_t b0, b1, b2, b3;
                uint32_t ad = sb + bufb + OFF_KC + (uint32_t)((nt * 8 + r8) * 272
                                                             + (kp * 32 + mt * 8) * 2);
                LDSM_X4(b0, b1, b2, b3, ad);
                MMA_F16(S[nt][0], S[nt][1], S[nt][2], S[nt][3],
                        qf[qi][0], qf[qi][1], qf[qi][2], qf[qi][3], b0, b1);
                MMA_F16(S[nt][0], S[nt][1], S[nt][2], S[nt][3],
                        qf[qi + 1][0], qf[qi + 1][1], qf[qi + 1][2], qf[qi + 1][3], b2, b3);
            }
        }

        // ---- mask + scale (matches ref: (mask ? -1e9 : s) * 0.125)
        const char* mbuf = sm + bufb + OFF_MSK;
#pragma unroll
        for (int nt = 0; nt < 8; nt++) {
            unsigned short mA = *(const unsigned short*)(mbuf + (wm + g) * 64 + nt * 8 + 2 * q);
            unsigned short mB = *(const unsigned short*)(mbuf + (wm + g + 8) * 64 + nt * 8 + 2 * q);
            S[nt][0] = (mA & 0xff) ? -1.25e8f : S[nt][0] * 0.125f;
            S[nt][1] = (mA >> 8)   ? -1.25e8f : S[nt][1] * 0.125f;
            S[nt][2] = (mB & 0xff) ? -1.25e8f : S[nt][2] * 0.125f;
            S[nt][3] = (mB >> 8)   ? -1.25e8f : S[nt][3] * 0.125f;
        }

        // ---- online softmax
        float mx0 = -1e30f, mx1 = -1e30f;
#pragma unroll
        for (int nt = 0; nt < 8; nt++) {
            mx0 = fmaxf(mx0, fmaxf(S[nt][0], S[nt][1]));
            mx1 = fmaxf(mx1, fmaxf(S[nt][2], S[nt][3]));
        }
        mx0 = fmaxf(mx0, __shfl_xor_sync(0xffffffffu, mx0, 1));
        mx0 = fmaxf(mx0, __shfl_xor_sync(0xffffffffu, mx0, 2));
        mx1 = fmaxf(mx1, __shfl_xor_sync(0xffffffffu, mx1, 1));
        mx1 = fmaxf(mx1, __shfl_xor_sync(0xffffffffu, mx1, 2));
        const float nm0 = fmaxf(mrow0, mx0);
        const float nm1 = fmaxf(mrow1, mx1);
        const float c0 = __expf(mrow0 - nm0);
        const float c1 = __expf(mrow1 - nm1);
        mrow0 = nm0; mrow1 = nm1;

        float s0 = 0.f, s1 = 0.f;
        uint32_t pa[4][4];
#pragma unroll
        for (int nt = 0; nt < 8; nt++) {
            float p0 = __expf(S[nt][0] - nm0);
            float p1 = __expf(S[nt][1] - nm0);
            float p2 = __expf(S[nt][2] - nm1);
            float p3 = __expf(S[nt][3] - nm1);
            s0 += p0 + p1;
            s1 += p2 + p3;
            const int ks = nt >> 1;
            const int hv = (nt & 1) * 2;
            pa[ks][hv]     = pack_hf2(p0, p1);
            pa[ks][hv + 1] = pack_hf2(p2, p3);
        }
        s0 += __shfl_xor_sync(0xffffffffu, s0, 1);
        s0 += __shfl_xor_sync(0xffffffffu, s0, 2);
        s1 += __shfl_xor_sync(0xffffffffu, s1, 1);
        s1 += __shfl_xor_sync(0xffffffffu, s1, 2);
        lrow0 = lrow0 * c0 + s0;
        lrow1 = lrow1 * c1 + s1;

#pragma unroll
        for (int dt = 0; dt < 8; dt++) {
            O[dt][0] *= c0; O[dt][1] *= c0;
            O[dt][2] *= c1; O[dt][3] *= c1;
        }

        // ---- O += Phi @ (Vhi + Vlo): interleaved loads (short live ranges)
#pragma unroll
        for (int ks = 0; ks < 4; ks++) {
            const uint32_t vrow = (uint32_t)(ks * 16 + (mt & 1) * 8 + r8);
#pragma unroll
            for (int dp = 0; dp < 4; dp++) {
                const uint32_t vcol = (uint32_t)(dp * 16 + (mt >> 1) * 8);
                uint32_t v0, v1, v2, v3;
                LDSM_X4_T(v0, v1, v2, v3, sb + bufb + OFF_VH + vrow * 144 + vcol * 2);
                MMA_F16(O[2*dp][0], O[2*dp][1], O[2*dp][2], O[2*dp][3],
                        pa[ks][0], pa[ks][1], pa[ks][2], pa[ks][3], v0, v1);
                MMA_F16(O[2*dp+1][0], O[2*dp+1][1], O[2*dp+1][2], O[2*dp+1][3],
                        pa[ks][0], pa[ks][1], pa[ks][2], pa[ks][3], v2, v3);
                LDSM_X4_T(v0, v1, v2, v3, sb + bufb + OFF_VL + vrow * 144 + vcol * 2);
                MMA_F16(O[2*dp][0], O[2*dp][1], O[2*dp][2], O[2*dp][3],
                        pa[ks][0], pa[ks][1], pa[ks][2], pa[ks][3], v0, v1);
                MMA_F16(O[2*dp+1][0], O[2*dp+1][1], O[2*dp+1][2], O[2*dp+1][3],
                        pa[ks][0], pa[ks][1], pa[ks][2], pa[ks][3], v2, v3);
            }
        }
    }

    // ---- epilogue: write fp16 ctx-hi (A-operand of the output projection)
    const float inv0 = 1.0f / lrow0;
    const float inv1 = 1.0f / lrow1;
    const int row0 = m0 + wm + g;
#pragma unroll
    for (int dt = 0; dt < 8; dt++) {
        int col = h * DK + dt * 8 + 2 * q;
        *(uint32_t*)&ctxh[((size_t)(b * MM + row0)) * DMOD + col] =
            pack_hf2(O[dt][0] * inv0, O[dt][1] * inv0);
        *(uint32_t*)&ctxh[((size_t)(b * MM + row0 + 8)) * DMOD + col] =
            pack_hf2(O[dt][2] * inv1, O[dt][3] * inv1);
    }
}

// ---------------------------------------------------------------------------
extern "C" void kernel_launch(void* const* d_in, const int* in_sizes, int n_in,
                              void* d_out, int out_size) {
    const float* q  = (const float*)d_in[0];
    const float* k  = (const float*)d_in[1];
    const float* v  = (const float*)d_in[2];
    const void*  mask_raw = d_in[3];
    const float* Wq = (const float*)d_in[4];
    const float* Wk = (const float*)d_in[5];
    const float* Wv = (const float*)d_in[6];
    const float* Wo = (const float*)d_in[7];
    float* out = (float*)d_out;

    void *mask_, *A2_, *W2_, *Qh_, *Kc_, *Vh_, *Vl_;
    cudaGetSymbolAddress(&mask_, g_mask);
    cudaGetSymbolAddress(&A2_,  g_A2);
    cudaGetSymbolAddress(&W2_,  g_W2);
    cudaGetSymbolAddress(&Qh_,  g_Qh);
    cudaGetSymbolAddress(&Kc_,  g_Kc);
    cudaGetSymbolAddress(&Vh_,  g_Vh);
    cudaGetSymbolAddress(&Vl_,  g_Vl);
    unsigned char* mask = (unsigned char*)mask_;
    __half* A2 = (__half*)A2_;
    __half* W2 = (__half*)W2_;
    __half* Qh = (__half*)Qh_;
    __half* Kc = (__half*)Kc_;
    __half* Vh = (__half*)Vh_;
    __half* Vl = (__half*)Vl_;

    cudaFuncSetAttribute(attn_hmma,
                         cudaFuncAttributeMaxDynamicSharedMemorySize, A2_SMEM);
    cudaFuncSetAttribute(gemm_hmma,
                         cudaFuncAttributeMaxDynamicSharedMemorySize, G_SMEM);

    // Normalize mask dtype -> uint8
    detect_mask<<<1, 1024>>>((const unsigned int*)mask_raw);
    convert_mask<<<(unsigned)(((size_t)BB * MM * NN / 4 + 255) / 256), 256>>>(mask_raw);

    const unsigned actg = (unsigned)(((size_t)(BB * MM) * DMOD / 8 + 255) / 256);
    const unsigned wgtg = (unsigned)(((size_t)DMOD * DMOD / 8 + 255) / 256);

    // Stage the three input projections, run as one batched GEMM launch that
    // writes fp16 consumer formats directly (Qh, Kc, Vh/Vl).
    split_act<<<actg, 256>>>(q, A2);
    split_act<<<actg, 256>>>(k, A2 + AS2);
    split_act<<<actg, 256>>>(v, A2 + 2 * AS2);
    split_wgt<<<wgtg, 256>>>(Wq, W2);
    split_wgt<<<wgtg, 256>>>(Wk, W2 + WS2);
    split_wgt<<<wgtg, 256>>>(Wv, W2 + 2 * WS2);

    dim3 gridG3(DMOD / 128, (BB * MM) / 128, 3);        // (8, 32, 3)
    gemm_hmma<<<gridG3, 128, G_SMEM>>>((const uint4*)A2, (const uint4*)W2,
                                       out, Qh, Kc, Vh, Vl, 0);

    // Attention: writes fp16 ctx-hi directly into A2 region 0
    dim3 gridA(MM / 128, BB * NH);                      // (16, 32)
    attn_hmma<<<gridA, 256, A2_SMEM>>>(Qh, Kc, Vh, Vl, mask, A2);

    // out = ctx @ Wo^T (fp32 epilogue)
    split_wgt<<<wgtg, 256>>>(Wo, W2);
    dim3 gridG(DMOD / 128, (BB * MM) / 128, 1);
    gemm_hmma<<<gridG, 128, G_SMEM>>>((const uint4*)A2, (const uint4*)W2,
                                      out, Qh, Kc, Vh, Vl, 1);
}